// round 1
// baseline (speedup 1.0000x reference)
#include <cuda_runtime.h>
#include <math.h>

#define NN   100001
#define D    64
#define SB   1024
#define SS   50
#define DFF  256

// ---------------- scratch (no allocations allowed) ----------------
__device__ float g_x1[NN * D];
__device__ float g_x2[NN * D];
__device__ float g_xbuf[SB * SS * D];

// ---------------- smem layout for transformer kernel (floats) -----
#define OFF_XS   0        // 50*64 = 3200
#define OFF_WS   3200     // 64*64 = 4096 weight staging
#define OFF_Q    7296     // 3200
#define OFF_KT   10496    // 3200 (K transposed [64][50])
#define OFF_V    13696    // 3200
#define OFF_SC   16896    // 2*50*50 = 5000
#define OFF_CTX  21896    // 3200
#define OFF_H1   10496    // 50*256 = 12800 (reuses KT/V/SC/part of CTX, all dead)
#define OFF_KM   25096    // 50
#define SMEM_FLOATS 25152

__device__ __forceinline__ float wsum(float v) {
#pragma unroll
    for (int o = 16; o > 0; o >>= 1) v += __shfl_xor_sync(0xffffffffu, v, o);
    return v;
}
__device__ __forceinline__ float wmax(float v) {
#pragma unroll
    for (int o = 16; o > 0; o >>= 1) v = fmaxf(v, __shfl_xor_sync(0xffffffffu, v, o));
    return v;
}
__device__ __forceinline__ float gelu_f(float x) {
    float inner = 0.7978845608028654f * (x + 0.044715f * x * x * x);
    return 0.5f * x * (1.0f + tanhf(inner));
}

// ---------------- zero ----------------
__global__ void zero_kernel(float* __restrict__ p, int n) {
    int i = blockIdx.x * blockDim.x + threadIdx.x;
    int stride = gridDim.x * blockDim.x;
    for (; i < n; i += stride) p[i] = 0.0f;
}

// ---------------- GNN scatter: xout[dst] += xin[src] * w ----------
__global__ void __launch_bounds__(256) gnn_scatter(
    const float* __restrict__ xin, const int* __restrict__ ei,
    const float* __restrict__ ew, float* __restrict__ xout, int E)
{
    int warp = (blockIdx.x * blockDim.x + threadIdx.x) >> 5;
    if (warp >= E) return;
    int lane = threadIdx.x & 31;
    int src = ei[warp];
    int dst = ei[E + warp];
    float w = ew[warp];
    float v0 = xin[src * D + lane] * w;
    float v1 = xin[src * D + 32 + lane] * w;
    atomicAdd(&xout[dst * D + lane], v0);
    atomicAdd(&xout[dst * D + 32 + lane], v1);
}

// ---------------- fusion: gnn projection + alpha blend + pos ------
__global__ void __launch_bounds__(256) fuse_kernel(
    const int* __restrict__ seq, const int* __restrict__ lengths,
    const float* __restrict__ bert, const float* __restrict__ gnn_emb,
    const float* __restrict__ Wp, const float* __restrict__ bp,
    const float* __restrict__ pos)
{
    int row = blockIdx.x * 8 + (threadIdx.x >> 5);
    if (row >= SB * SS) return;
    int lane = threadIdx.x & 31;
    int b = row / SS, s = row - b * SS;
    int idx = seq[row];
    const float* gp  = gnn_emb + (size_t)idx * D;
    const float* x1p = g_x1 + (size_t)idx * D;
    const float* x2p = g_x2 + (size_t)idx * D;
    float a0 = (gp[lane]      + x1p[lane]      + x2p[lane])      * (1.0f / 3.0f);
    float a1 = (gp[lane + 32] + x1p[lane + 32] + x2p[lane + 32]) * (1.0f / 3.0f);
    float o0 = bp[lane], o1 = bp[lane + 32];
#pragma unroll
    for (int k = 0; k < 32; k++) {
        float ak = __shfl_sync(0xffffffffu, a0, k);
        o0 += ak * Wp[k * D + lane];
        o1 += ak * Wp[k * D + 32 + lane];
    }
#pragma unroll
    for (int k = 0; k < 32; k++) {
        float ak = __shfl_sync(0xffffffffu, a1, k);
        o0 += ak * Wp[(k + 32) * D + lane];
        o1 += ak * Wp[(k + 32) * D + 32 + lane];
    }
    int len = lengths[b];
    float alpha = (len <= 10) ? 0.3f : ((len >= 50) ? 0.7f : 0.5f);
    float beta = 1.0f - alpha;
    const float* brow = bert + (size_t)idx * D;
    g_xbuf[row * D + lane]      = alpha * brow[lane]      + beta * o0 + pos[s * D + lane];
    g_xbuf[row * D + 32 + lane] = alpha * brow[lane + 32] + beta * o1 + pos[s * D + 32 + lane];
}

// ---------------- 50x64 @ 64x64 matmul from smem ------------------
// thread map: lane = d (2 cols: lane, lane+32), warp w owns rows {w, w+8, ...}
template<int SLD, int DMODE, int DLD, bool GELU>
__device__ __forceinline__ void mm50(const float* __restrict__ src,
                                     const float* __restrict__ Ws,
                                     float* __restrict__ dst,
                                     const float* __restrict__ bias,
                                     int tid)
{
    int lane = tid & 31, w = tid >> 5;
    int nj = (w < 2) ? 7 : 6;
    float acc[7][2];
#pragma unroll
    for (int j = 0; j < 7; j++) { acc[j][0] = 0.0f; acc[j][1] = 0.0f; }
#pragma unroll 4
    for (int k = 0; k < 64; k++) {
        float w0 = Ws[k * 64 + lane];
        float w1 = Ws[k * 64 + 32 + lane];
#pragma unroll
        for (int j = 0; j < 7; j++) {
            if (j < nj) {
                float xv = src[(w + 8 * j) * SLD + k];
                acc[j][0] += xv * w0;
                acc[j][1] += xv * w1;
            }
        }
    }
#pragma unroll
    for (int j = 0; j < 7; j++) {
        if (j < nj) {
            int s = w + 8 * j;
            float o0 = acc[j][0], o1 = acc[j][1];
            if (bias) { o0 += bias[lane]; o1 += bias[32 + lane]; }
            if (GELU) { o0 = gelu_f(o0); o1 = gelu_f(o1); }
            if (DMODE == 0) { dst[s * DLD + lane] = o0; dst[s * DLD + 32 + lane] = o1; }
            else            { dst[lane * 50 + s] = o0; dst[(lane + 32) * 50 + s] = o1; }
        }
    }
}

__device__ __forceinline__ void stage64(float* __restrict__ ws,
                                        const float* __restrict__ W, int tid)
{
    for (int i = tid; i < 4096; i += 256) ws[i] = W[i];
}

// xs = LN(xs + y) row-wise, warp per row
__device__ __forceinline__ void ln_add(float* __restrict__ xs,
                                       const float* __restrict__ y,
                                       const float* __restrict__ g,
                                       const float* __restrict__ bta, int tid)
{
    int lane = tid & 31, w = tid >> 5;
    for (int r = w; r < 50; r += 8) {
        float v0 = xs[r * 64 + lane]      + y[r * 64 + lane];
        float v1 = xs[r * 64 + 32 + lane] + y[r * 64 + 32 + lane];
        float mean = wsum(v0 + v1) * (1.0f / 64.0f);
        float d0 = v0 - mean, d1 = v1 - mean;
        float var = wsum(d0 * d0 + d1 * d1) * (1.0f / 64.0f);
        float inv = 1.0f / sqrtf(var + 1e-5f);
        xs[r * 64 + lane]      = d0 * inv * g[lane]      + bta[lane];
        xs[r * 64 + 32 + lane] = d1 * inv * g[32 + lane] + bta[32 + lane];
    }
}

// ---------------- one transformer block, CTA per batch row --------
__global__ void __launch_bounds__(256) xformer_kernel(
    const int* __restrict__ seq,
    const float* __restrict__ wq, const float* __restrict__ wk,
    const float* __restrict__ wv, const float* __restrict__ wo,
    const float* __restrict__ w1, const float* __restrict__ b1,
    const float* __restrict__ w2, const float* __restrict__ b2,
    const float* __restrict__ ln1g, const float* __restrict__ ln1b,
    const float* __restrict__ ln2g, const float* __restrict__ ln2b)
{
    extern __shared__ float sm[];
    int tid = threadIdx.x;
    int b = blockIdx.x;
    float* xg  = g_xbuf + (size_t)b * SS * D;
    float* xs  = sm + OFF_XS;
    float* ws  = sm + OFF_WS;
    float* q   = sm + OFF_Q;
    float* kT  = sm + OFF_KT;
    float* v   = sm + OFF_V;
    float* sc  = sm + OFF_SC;
    float* ctx = sm + OFF_CTX;
    float* y   = q;            // reuse
    float* h1  = sm + OFF_H1;  // reuse
    float* km  = sm + OFF_KM;

    for (int i = tid; i < 3200; i += 256) xs[i] = xg[i];
    if (tid < 50) km[tid] = (seq[b * SS + tid] != 0) ? 0.0f : -1e9f;
    __syncthreads();

    // Q, K^T, V
    stage64(ws, wq, tid); __syncthreads();
    mm50<64, 0, 64, false>(xs, ws, q, nullptr, tid); __syncthreads();
    stage64(ws, wk, tid); __syncthreads();
    mm50<64, 1, 0, false>(xs, ws, kT, nullptr, tid); __syncthreads();
    stage64(ws, wv, tid); __syncthreads();
    mm50<64, 0, 64, false>(xs, ws, v, nullptr, tid); __syncthreads();

    // scores + softmax (warp per (h,qs) row)
    {
        int lane = tid & 31, w = tid >> 5;
        const float scale = 0.17677669529663687f; // 1/sqrt(32)
        bool has1 = (lane + 32) < 50;
        for (int r = w; r < 100; r += 8) {
            int h = (r >= 50) ? 1 : 0;
            int qs = r - h * 50;
            const float* qrow = q + qs * 64 + h * 32;
            const float* kcol = kT + h * 32 * 50;
            float acc0 = 0.0f, acc1 = 0.0f;
#pragma unroll
            for (int c = 0; c < 32; c++) {
                float qc = qrow[c];
                acc0 += qc * kcol[c * 50 + lane];
                float k1 = has1 ? kcol[c * 50 + lane + 32] : 0.0f;
                acc1 += qc * k1;
            }
            float s0 = (km[lane] == 0.0f) ? acc0 * scale : -1e9f;
            float s1 = -3.0e38f;
            if (has1) s1 = (km[lane + 32] == 0.0f) ? acc1 * scale : -1e9f;
            float m = wmax(fmaxf(s0, s1));
            float e0 = expf(s0 - m);
            float e1 = has1 ? expf(s1 - m) : 0.0f;
            float inv = 1.0f / wsum(e0 + e1);
            float* srow = sc + h * 2500 + qs * 50;
            srow[lane] = e0 * inv;
            if (has1) srow[lane + 32] = e1 * inv;
        }
    }
    __syncthreads();

    // ctx = attn @ V
    {
        int d = tid & 63, g = tid >> 6;
        int h = d >> 5;
        for (int qs = g; qs < 50; qs += 4) {
            const float* srow = sc + h * 2500 + qs * 50;
            float acc = 0.0f;
#pragma unroll 5
            for (int ks = 0; ks < 50; ks++) acc += srow[ks] * v[ks * 64 + d];
            ctx[qs * 64 + d] = acc;
        }
    }
    __syncthreads();

    // y = ctx @ wo ; xs = LN1(xs + y)
    stage64(ws, wo, tid); __syncthreads();
    mm50<64, 0, 64, false>(ctx, ws, y, nullptr, tid); __syncthreads();
    ln_add(xs, y, ln1g, ln1b, tid); __syncthreads();

    // FFN1: h1 = gelu(xs @ w1 + b1), 4 column chunks of 64
    for (int c = 0; c < 4; c++) {
        for (int i = tid; i < 4096; i += 256)
            ws[i] = w1[(i >> 6) * 256 + c * 64 + (i & 63)];
        __syncthreads();
        mm50<64, 0, 256, true>(xs, ws, h1 + c * 64, b1 + c * 64, tid);
        __syncthreads();
    }

    // FFN2: y = h1 @ w2 + b2, accumulate over 4 k-chunks
    {
        int lane = tid & 31, w = tid >> 5;
        int nj = (w < 2) ? 7 : 6;
        float acc[7][2];
#pragma unroll
        for (int j = 0; j < 7; j++) { acc[j][0] = 0.0f; acc[j][1] = 0.0f; }
        for (int c = 0; c < 4; c++) {
            for (int i = tid; i < 4096; i += 256) ws[i] = w2[c * 4096 + i];
            __syncthreads();
#pragma unroll 4
            for (int k = 0; k < 64; k++) {
                float w0  = ws[k * 64 + lane];
                float w1v = ws[k * 64 + 32 + lane];
#pragma unroll
                for (int j = 0; j < 7; j++) {
                    if (j < nj) {
                        float xv = h1[(w + 8 * j) * 256 + c * 64 + k];
                        acc[j][0] += xv * w0;
                        acc[j][1] += xv * w1v;
                    }
                }
            }
            __syncthreads();
        }
#pragma unroll
        for (int j = 0; j < 7; j++) {
            if (j < nj) {
                int s = w + 8 * j;
                y[s * 64 + lane]      = acc[j][0] + b2[lane];
                y[s * 64 + 32 + lane] = acc[j][1] + b2[32 + lane];
            }
        }
    }
    __syncthreads();

    // xs = LN2(xs + y), write back
    ln_add(xs, y, ln2g, ln2b, tid); __syncthreads();
    for (int i = tid; i < 3200; i += 256) xg[i] = xs[i];
}

// ---------------- final LN + gather -------------------------------
__global__ void __launch_bounds__(256) final_kernel(
    const int* __restrict__ lengths, const float* __restrict__ g,
    const float* __restrict__ bt, float* __restrict__ out)
{
    int b = blockIdx.x * 8 + (threadIdx.x >> 5);
    if (b >= SB) return;
    int lane = threadIdx.x & 31;
    int r = lengths[b] - 1;
    const float* row = g_xbuf + ((size_t)b * SS + r) * D;
    float v0 = row[lane], v1 = row[lane + 32];
    float mean = wsum(v0 + v1) * (1.0f / 64.0f);
    float d0 = v0 - mean, d1 = v1 - mean;
    float var = wsum(d0 * d0 + d1 * d1) * (1.0f / 64.0f);
    float inv = 1.0f / sqrtf(var + 1e-5f);
    out[b * D + lane]      = d0 * inv * g[lane]      + bt[lane];
    out[b * D + 32 + lane] = d1 * inv * g[lane + 32] + bt[lane + 32];
}

// ---------------- launch -------------------------------------------
extern "C" void kernel_launch(void* const* d_in, const int* in_sizes, int n_in,
                              void* d_out, int out_size)
{
    const int*   seq  = (const int*)d_in[0];
    const int*   lens = (const int*)d_in[1];
    const int*   ei   = (const int*)d_in[2];
    const float* ew   = (const float*)d_in[3];
    const float* bert = (const float*)d_in[4];
    const float* gnn  = (const float*)d_in[5];
    const float* Wp   = (const float*)d_in[6];
    const float* bp   = (const float*)d_in[7];
    const float* pos  = (const float*)d_in[8];
    const float* wq   = (const float*)d_in[9];
    const float* wk   = (const float*)d_in[10];
    const float* wv   = (const float*)d_in[11];
    const float* wo   = (const float*)d_in[12];
    const float* w1   = (const float*)d_in[13];
    const float* b1   = (const float*)d_in[14];
    const float* w2   = (const float*)d_in[15];
    const float* b2   = (const float*)d_in[16];
    const float* ln1g = (const float*)d_in[17];
    const float* ln1b = (const float*)d_in[18];
    const float* ln2g = (const float*)d_in[19];
    const float* ln2b = (const float*)d_in[20];
    const float* lnfg = (const float*)d_in[21];
    const float* lnfb = (const float*)d_in[22];
    float* out = (float*)d_out;
    int E = in_sizes[3];

    size_t smem = SMEM_FLOATS * sizeof(float);
    cudaFuncSetAttribute(xformer_kernel,
                         cudaFuncAttributeMaxDynamicSharedMemorySize, (int)smem);

    float *x1p = nullptr, *x2p = nullptr;
    cudaGetSymbolAddress((void**)&x1p, g_x1);
    cudaGetSymbolAddress((void**)&x2p, g_x2);

    zero_kernel<<<2048, 256>>>(x1p, NN * D);
    zero_kernel<<<2048, 256>>>(x2p, NN * D);

    int sblocks = (E + 7) / 8;  // 8 warps per block, warp per edge
    gnn_scatter<<<sblocks, 256>>>(gnn, ei, ew, x1p, E);
    gnn_scatter<<<sblocks, 256>>>(x1p, ei, ew, x2p, E);

    fuse_kernel<<<(SB * SS + 7) / 8, 256>>>(seq, lens, bert, gnn, Wp, bp, pos);

    for (int i = 0; i < 2; i++) {
        xformer_kernel<<<SB, 256, smem>>>(seq,
            wq + i * 4096, wk + i * 4096, wv + i * 4096, wo + i * 4096,
            w1 + i * 64 * 256, b1 + i * 256, w2 + i * 256 * 64, b2 + i * 64,
            ln1g + i * 64, ln1b + i * 64, ln2g + i * 64, ln2b + i * 64);
    }

    final_kernel<<<SB / 8, 256>>>(lens, lnfg, lnfb, out);
}

// round 2
// speedup vs baseline: 1.8073x; 1.8073x over previous
#include <cuda_runtime.h>
#include <cuda_fp16.h>
#include <math.h>

#define NN   100001
#define D    64
#define SB   1024
#define SS   50
#define DFF  256

// ---------------- scratch (no allocations allowed) ----------------
__device__ float g_x1[NN * D];
__device__ float g_x2[NN * D];
__device__ float g_xbuf[SB * SS * D];
// fp16 weight copies (converted once per launch by cvt_kernel)
__device__ __half g_wqh[2 * 4096];
__device__ __half g_wkh[2 * 4096];
__device__ __half g_wvh[2 * 4096];
__device__ __half g_woh[2 * 4096];
__device__ __half g_w1h[2 * 16384];
__device__ __half g_w2h[2 * 16384];

// ---------------- smem byte offsets for xformer ----------------
// persistent: Ah (fp16 A operand [64][72]), Wh (fp16 B stage [64][72]), xs
#define OFF_AH   0        // half[64*72]   9216B
#define OFF_WH   9216     // half[64*72]   9216B
#define OFF_XS   18432    // f32 [3200]    12800B
// attention phase:
#define OFF_Q    31232    // f32 [50][66]  13200B
#define OFF_KT   44432    // f32 [64][52]  13312B
#define OFF_V    57744    // f32 [50][66]  13200B
#define OFF_SC   70944    // f32 [2][50][52] 20800B  (dead after ctx)
#define OFF_Y    70944    // f32 [50][66]  13200B (O out; overlays SC)
#define OFF_KM   91744    // f32 [64]      256B
// FFN overlay (q/kT/v/sc dead):
#define OFF_W1H  31232    // half[64][264] 33792B
#define OFF_H1H  65024    // half[64][264] 33792B -> 98816
#define OFF_W2H  31232    // half[128][72] 18432B (W1h dead)
#define OFF_Y2   49664    // f32 [50][66]  13200B
#define SMEM_BYTES 98816

__device__ __forceinline__ float wsum(float v) {
#pragma unroll
    for (int o = 16; o > 0; o >>= 1) v += __shfl_xor_sync(0xffffffffu, v, o);
    return v;
}
__device__ __forceinline__ float wmax(float v) {
#pragma unroll
    for (int o = 16; o > 0; o >>= 1) v = fmaxf(v, __shfl_xor_sync(0xffffffffu, v, o));
    return v;
}
__device__ __forceinline__ float gelu_f(float x) {
    float inner = 0.7978845608028654f * (x + 0.044715f * x * x * x);
    return 0.5f * x * (1.0f + tanhf(inner));
}

// ---------------- mma helpers ----------------
__device__ __forceinline__ void ldsm_x4(unsigned &r0, unsigned &r1, unsigned &r2, unsigned &r3, unsigned addr) {
    asm volatile("ldmatrix.sync.aligned.m8n8.x4.shared.b16 {%0,%1,%2,%3}, [%4];"
                 : "=r"(r0), "=r"(r1), "=r"(r2), "=r"(r3) : "r"(addr));
}
__device__ __forceinline__ void ldsm_x4_t(unsigned &r0, unsigned &r1, unsigned &r2, unsigned &r3, unsigned addr) {
    asm volatile("ldmatrix.sync.aligned.m8n8.x4.trans.shared.b16 {%0,%1,%2,%3}, [%4];"
                 : "=r"(r0), "=r"(r1), "=r"(r2), "=r"(r3) : "r"(addr));
}
__device__ __forceinline__ void mma16816(float c[4], unsigned a0, unsigned a1, unsigned a2, unsigned a3,
                                         unsigned b0, unsigned b1) {
    asm volatile("mma.sync.aligned.m16n8k16.row.col.f32.f16.f16.f32 "
                 "{%0,%1,%2,%3}, {%4,%5,%6,%7}, {%8,%9}, {%0,%1,%2,%3};"
                 : "+f"(c[0]), "+f"(c[1]), "+f"(c[2]), "+f"(c[3])
                 : "r"(a0), "r"(a1), "r"(a2), "r"(a3), "r"(b0), "r"(b1));
}

// warp computes 16x32 tile: m0=(w&3)*16, n0=(w>>2)*32 (plus caller offset)
// A: smem half, lda halves, starting k column k0 (halves). B: smem half, ldb halves, col n0.
__device__ __forceinline__ void mma_block(const __half* Ah, int lda, int k0,
                                          const __half* Bh, int ldb, int n0,
                                          int m0, int KT, float acc[4][4]) {
    int lane = threadIdx.x & 31;
    unsigned abase = (unsigned)__cvta_generic_to_shared(Ah) +
                     (unsigned)(((m0 + (lane & 15)) * lda + k0 + ((lane >> 4) * 8)) * 2);
    unsigned bbase = (unsigned)__cvta_generic_to_shared(Bh);
    int brow = lane & 15;
    int bcol8 = (lane >> 4) * 8;
    for (int kt = 0; kt < KT; kt++) {
        unsigned a0, a1, a2, a3;
        ldsm_x4(a0, a1, a2, a3, abase + kt * 32);
#pragma unroll
        for (int ns = 0; ns < 2; ns++) {
            unsigned baddr = bbase + (unsigned)(((kt * 16 + brow) * ldb + n0 + ns * 16 + bcol8) * 2);
            unsigned b0, b1, b2, b3;
            ldsm_x4_t(b0, b1, b2, b3, baddr);
            mma16816(acc[ns * 2 + 0], a0, a1, a2, a3, b0, b1);
            mma16816(acc[ns * 2 + 1], a0, a1, a2, a3, b2, b3);
        }
    }
}

// ---------------- misc kernels ----------------
__global__ void zero_kernel(float4* __restrict__ p, int n4) {
    int i = blockIdx.x * blockDim.x + threadIdx.x;
    int stride = gridDim.x * blockDim.x;
    float4 z = make_float4(0.f, 0.f, 0.f, 0.f);
    for (; i < n4; i += stride) p[i] = z;
}

__global__ void cvt_kernel(const float* __restrict__ s, __half* __restrict__ d, int n) {
    int i = blockIdx.x * blockDim.x + threadIdx.x;
    int st = gridDim.x * blockDim.x;
    for (; i < n; i += st) d[i] = __float2half_rn(s[i]);
}

// GNN scatter: 16 lanes per edge, float4 vector reductions
__global__ void __launch_bounds__(256) gnn_scatter(
    const float* __restrict__ xin, const int* __restrict__ ei,
    const float* __restrict__ ew, float* __restrict__ xout, int E)
{
    int t = blockIdx.x * blockDim.x + threadIdx.x;
    int edge = t >> 4;
    if (edge >= E) return;
    int comp = (t & 15) * 4;
    int src = __ldg(ei + edge);
    int dst = __ldg(ei + E + edge);
    float w = __ldg(ew + edge);
    float4 s4 = *(const float4*)(xin + (size_t)src * D + comp);
    float* dp = xout + (size_t)dst * D + comp;
    asm volatile("red.global.add.v4.f32 [%0], {%1,%2,%3,%4};"
                 :: "l"(dp), "f"(s4.x * w), "f"(s4.y * w), "f"(s4.z * w), "f"(s4.w * w)
                 : "memory");
}

// fusion: gnn projection + alpha blend + pos
__global__ void __launch_bounds__(256) fuse_kernel(
    const int* __restrict__ seq, const int* __restrict__ lengths,
    const float* __restrict__ bert, const float* __restrict__ gnn_emb,
    const float* __restrict__ Wp, const float* __restrict__ bp,
    const float* __restrict__ pos)
{
    int row = blockIdx.x * 8 + (threadIdx.x >> 5);
    if (row >= SB * SS) return;
    int lane = threadIdx.x & 31;
    int b = row / SS, s = row - b * SS;
    int idx = seq[row];
    const float* gp  = gnn_emb + (size_t)idx * D;
    const float* x1p = g_x1 + (size_t)idx * D;
    const float* x2p = g_x2 + (size_t)idx * D;
    float a0 = (gp[lane]      + x1p[lane]      + x2p[lane])      * (1.0f / 3.0f);
    float a1 = (gp[lane + 32] + x1p[lane + 32] + x2p[lane + 32]) * (1.0f / 3.0f);
    float o0 = bp[lane], o1 = bp[lane + 32];
#pragma unroll
    for (int k = 0; k < 32; k++) {
        float ak = __shfl_sync(0xffffffffu, a0, k);
        o0 += ak * Wp[k * D + lane];
        o1 += ak * Wp[k * D + 32 + lane];
    }
#pragma unroll
    for (int k = 0; k < 32; k++) {
        float ak = __shfl_sync(0xffffffffu, a1, k);
        o0 += ak * Wp[(k + 32) * D + lane];
        o1 += ak * Wp[(k + 32) * D + 32 + lane];
    }
    int len = lengths[b];
    float alpha = (len <= 10) ? 0.3f : ((len >= 50) ? 0.7f : 0.5f);
    float beta = 1.0f - alpha;
    const float* brow = bert + (size_t)idx * D;
    g_xbuf[row * D + lane]      = alpha * brow[lane]      + beta * o0 + pos[s * D + lane];
    g_xbuf[row * D + 32 + lane] = alpha * brow[lane + 32] + beta * o1 + pos[s * D + 32 + lane];
}

// ---------------- transformer helpers ----------------
__device__ __forceinline__ void build_Ah(__half* Ah, const float* xs, int tid) {
    for (int i = tid; i < 64 * 32; i += 256) {
        int row = i >> 5, c2 = i & 31;
        __half2 hv;
        if (row < 50) {
            float2 xv = *(const float2*)(xs + row * 64 + c2 * 2);
            hv = __floats2half2_rn(xv.x, xv.y);
        } else {
            hv = __floats2half2_rn(0.f, 0.f);
        }
        *(__half2*)(Ah + row * 72 + c2 * 2) = hv;
    }
}

__device__ __forceinline__ void stage_w64(__half* Wh, const __half* src, int tid) {
    // 64x64 halves -> [64][72]
    for (int i = tid; i < 512; i += 256) {
        uint4 u = ((const uint4*)src)[i];
        int row = i >> 3, col = (i & 7) * 8;
        *(uint4*)(Wh + row * 72 + col) = u;
    }
}

__device__ __forceinline__ void epi_store66(float* dst, float acc[4][4], int m0, int n0, int lane) {
    int r = m0 + (lane >> 2);
    int cb = (lane & 3) * 2;
#pragma unroll
    for (int t = 0; t < 4; t++) {
        int c = n0 + t * 8 + cb;
        if (r < 50)     *(float2*)(dst + r * 66 + c)       = make_float2(acc[t][0], acc[t][1]);
        if (r + 8 < 50) *(float2*)(dst + (r + 8) * 66 + c) = make_float2(acc[t][2], acc[t][3]);
    }
}

// xs = LN(xs + y) row-wise, warp per row; y has ld=66
__device__ __forceinline__ void ln_add(float* __restrict__ xs,
                                       const float* __restrict__ y,
                                       const float* __restrict__ g,
                                       const float* __restrict__ bta, int tid)
{
    int lane = tid & 31, w = tid >> 5;
    for (int r = w; r < 50; r += 8) {
        float v0 = xs[r * 64 + lane]      + y[r * 66 + lane];
        float v1 = xs[r * 64 + 32 + lane] + y[r * 66 + 32 + lane];
        float mean = wsum(v0 + v1) * (1.0f / 64.0f);
        float d0 = v0 - mean, d1 = v1 - mean;
        float var = wsum(d0 * d0 + d1 * d1) * (1.0f / 64.0f);
        float inv = 1.0f / sqrtf(var + 1e-5f);
        xs[r * 64 + lane]      = d0 * inv * g[lane]      + bta[lane];
        xs[r * 64 + 32 + lane] = d1 * inv * g[32 + lane] + bta[32 + lane];
    }
}

// ---------------- one transformer block, CTA per batch row --------
__global__ void __launch_bounds__(256) xformer_kernel(
    const int* __restrict__ seq,
    const __half* __restrict__ wqh, const __half* __restrict__ wkh,
    const __half* __restrict__ wvh, const __half* __restrict__ woh,
    const __half* __restrict__ w1h, const float* __restrict__ b1,
    const __half* __restrict__ w2h, const float* __restrict__ b2,
    const float* __restrict__ ln1g, const float* __restrict__ ln1b,
    const float* __restrict__ ln2g, const float* __restrict__ ln2b)
{
    extern __shared__ char smraw[];
    int tid = threadIdx.x;
    int lane = tid & 31, w = tid >> 5;
    int b = blockIdx.x;
    float* xg = g_xbuf + (size_t)b * SS * D;

    __half* Ah  = (__half*)(smraw + OFF_AH);
    __half* Wh  = (__half*)(smraw + OFF_WH);
    float*  xs  = (float*)(smraw + OFF_XS);
    float*  q   = (float*)(smraw + OFF_Q);
    float*  kT  = (float*)(smraw + OFF_KT);
    float*  v   = (float*)(smraw + OFF_V);
    float*  sc  = (float*)(smraw + OFF_SC);
    float*  y   = (float*)(smraw + OFF_Y);
    float*  km  = (float*)(smraw + OFF_KM);
    __half* W1h = (__half*)(smraw + OFF_W1H);
    __half* H1h = (__half*)(smraw + OFF_H1H);
    __half* W2h = (__half*)(smraw + OFF_W2H);
    float*  y2  = (float*)(smraw + OFF_Y2);

    int m0 = (w & 3) * 16;
    int n0 = (w >> 2) * 32;

    // load xs, mask, build fp16 A, stage Wq
    for (int i = tid; i < 3200; i += 256) xs[i] = xg[i];
    if (tid < 50) km[tid] = (seq[b * SS + tid] != 0) ? 0.0f : -1e9f;
    __syncthreads();
    build_Ah(Ah, xs, tid);
    stage_w64(Wh, wqh, tid);
    __syncthreads();

    // Q
    {
        float acc[4][4] = {};
        mma_block(Ah, 72, 0, Wh, 72, n0, m0, 4, acc);
        epi_store66(q, acc, m0, n0, lane);
    }
    __syncthreads();
    stage_w64(Wh, wkh, tid);
    __syncthreads();
    // K -> kT [d][s] ld 52
    {
        float acc[4][4] = {};
        mma_block(Ah, 72, 0, Wh, 72, n0, m0, 4, acc);
        int r = m0 + (lane >> 2);
        int cb = (lane & 3) * 2;
#pragma unroll
        for (int t = 0; t < 4; t++) {
            int c = n0 + t * 8 + cb;
            if (r < 50)     { kT[c * 52 + r] = acc[t][0];     kT[(c + 1) * 52 + r] = acc[t][1]; }
            if (r + 8 < 50) { kT[c * 52 + r + 8] = acc[t][2]; kT[(c + 1) * 52 + r + 8] = acc[t][3]; }
        }
    }
    __syncthreads();
    stage_w64(Wh, wvh, tid);
    __syncthreads();
    // V
    {
        float acc[4][4] = {};
        mma_block(Ah, 72, 0, Wh, 72, n0, m0, 4, acc);
        epi_store66(v, acc, m0, n0, lane);
    }
    __syncthreads();

    // scores + softmax (warp per (h,qs) row)
    {
        const float scale = 0.17677669529663687f; // 1/sqrt(32)
        bool has1 = (lane + 32) < 50;
        for (int r = w; r < 100; r += 8) {
            int h = (r >= 50) ? 1 : 0;
            int qs = r - h * 50;
            const float* qrow = q + qs * 66 + h * 32;
            const float* kcol = kT + (h * 32) * 52;
            float acc0 = 0.0f, acc1 = 0.0f;
#pragma unroll
            for (int c = 0; c < 32; c++) {
                float qc = qrow[c];
                acc0 += qc * kcol[c * 52 + lane];
                float k1 = has1 ? kcol[c * 52 + lane + 32] : 0.0f;
                acc1 += qc * k1;
            }
            float s0 = (km[lane] == 0.0f) ? acc0 * scale : -1e9f;
            float s1 = -3.0e38f;
            if (has1) s1 = (km[lane + 32] == 0.0f) ? acc1 * scale : -1e9f;
            float m = wmax(fmaxf(s0, s1));
            float e0 = expf(s0 - m);
            float e1 = has1 ? expf(s1 - m) : 0.0f;
            float inv = 1.0f / wsum(e0 + e1);
            float* srow = sc + h * 2600 + qs * 52;
            srow[lane] = e0 * inv;
            if (has1) srow[lane + 32] = e1 * inv;
        }
    }
    __syncthreads();

    // ctx = attn @ V  -> write fp16 directly into Ah (rows>=50 stay zero)
    {
        int d = tid & 63, gq = tid >> 6;
        int h = d >> 5;
        for (int qs = gq; qs < 50; qs += 4) {
            const float* srow = sc + h * 2600 + qs * 52;
            float acc = 0.0f;
#pragma unroll 5
            for (int ks = 0; ks < 50; ks++) acc += srow[ks] * v[ks * 66 + d];
            Ah[qs * 72 + d] = __float2half_rn(acc);
        }
    }
    __syncthreads();
    stage_w64(Wh, woh, tid);
    __syncthreads();
    // O = ctx @ Wo -> y
    {
        float acc[4][4] = {};
        mma_block(Ah, 72, 0, Wh, 72, n0, m0, 4, acc);
        epi_store66(y, acc, m0, n0, lane);
    }
    __syncthreads();
    ln_add(xs, y, ln1g, ln1b, tid);
    __syncthreads();

    // rebuild Ah from LN1'd xs, stage W1 [64][256] -> [64][264]
    build_Ah(Ah, xs, tid);
    for (int i = tid; i < 2048; i += 256) {
        uint4 u = ((const uint4*)w1h)[i];
        int row = i >> 5, col = (i & 31) * 8;
        *(uint4*)(W1h + row * 264 + col) = u;
    }
    __syncthreads();

    // FFN1: H1h = fp16(gelu(Ah @ W1 + b1)), 4 column chunks of 64
    for (int nc = 0; nc < 4; nc++) {
        float acc[4][4] = {};
        mma_block(Ah, 72, 0, W1h, 264, nc * 64 + n0, m0, 4, acc);
        int r = m0 + (lane >> 2);
        int cb = (lane & 3) * 2;
#pragma unroll
        for (int t = 0; t < 4; t++) {
            int cg = nc * 64 + n0 + t * 8 + cb;
            float bb0 = b1[cg], bb1 = b1[cg + 1];
            *(__half2*)(H1h + r * 264 + cg) =
                __floats2half2_rn(gelu_f(acc[t][0] + bb0), gelu_f(acc[t][1] + bb1));
            *(__half2*)(H1h + (r + 8) * 264 + cg) =
                __floats2half2_rn(gelu_f(acc[t][2] + bb0), gelu_f(acc[t][3] + bb1));
        }
    }
    __syncthreads();

    // FFN2: y2 = H1h @ W2 + b2, K=256 in 2 staged chunks of 128
    {
        float acc[4][4] = {};
        for (int ch = 0; ch < 2; ch++) {
            for (int i = tid; i < 1024; i += 256) {
                uint4 u = ((const uint4*)w2h)[ch * 1024 + i];
                int row = i >> 3, col = (i & 7) * 8;
                *(uint4*)(W2h + row * 72 + col) = u;
            }
            __syncthreads();
            mma_block(H1h, 264, ch * 128, W2h, 72, n0, m0, 8, acc);
            __syncthreads();
        }
        int r = m0 + (lane >> 2);
        int cb = (lane & 3) * 2;
#pragma unroll
        for (int t = 0; t < 4; t++) {
            int c = n0 + t * 8 + cb;
            float bb0 = b2[c], bb1 = b2[c + 1];
            if (r < 50)     *(float2*)(y2 + r * 66 + c)       = make_float2(acc[t][0] + bb0, acc[t][1] + bb1);
            if (r + 8 < 50) *(float2*)(y2 + (r + 8) * 66 + c) = make_float2(acc[t][2] + bb0, acc[t][3] + bb1);
        }
    }
    __syncthreads();
    ln_add(xs, y2, ln2g, ln2b, tid);
    __syncthreads();
    for (int i = tid; i < 3200; i += 256) xg[i] = xs[i];
}

// ---------------- final LN + gather -------------------------------
__global__ void __launch_bounds__(256) final_kernel(
    const int* __restrict__ lengths, const float* __restrict__ g,
    const float* __restrict__ bt, float* __restrict__ out)
{
    int b = blockIdx.x * 8 + (threadIdx.x >> 5);
    if (b >= SB) return;
    int lane = threadIdx.x & 31;
    int r = lengths[b] - 1;
    const float* row = g_xbuf + ((size_t)b * SS + r) * D;
    float v0 = row[lane], v1 = row[lane + 32];
    float mean = wsum(v0 + v1) * (1.0f / 64.0f);
    float d0 = v0 - mean, d1 = v1 - mean;
    float var = wsum(d0 * d0 + d1 * d1) * (1.0f / 64.0f);
    float inv = 1.0f / sqrtf(var + 1e-5f);
    out[b * D + lane]      = d0 * inv * g[lane]      + bt[lane];
    out[b * D + 32 + lane] = d1 * inv * g[lane + 32] + bt[lane + 32];
}

// ---------------- launch -------------------------------------------
extern "C" void kernel_launch(void* const* d_in, const int* in_sizes, int n_in,
                              void* d_out, int out_size)
{
    const int*   seq  = (const int*)d_in[0];
    const int*   lens = (const int*)d_in[1];
    const int*   ei   = (const int*)d_in[2];
    const float* ew   = (const float*)d_in[3];
    const float* bert = (const float*)d_in[4];
    const float* gnn  = (const float*)d_in[5];
    const float* Wp   = (const float*)d_in[6];
    const float* bp   = (const float*)d_in[7];
    const float* pos  = (const float*)d_in[8];
    const float* wq   = (const float*)d_in[9];
    const float* wk   = (const float*)d_in[10];
    const float* wv   = (const float*)d_in[11];
    const float* wo   = (const float*)d_in[12];
    const float* w1   = (const float*)d_in[13];
    const float* b1   = (const float*)d_in[14];
    const float* w2   = (const float*)d_in[15];
    const float* b2   = (const float*)d_in[16];
    const float* ln1g = (const float*)d_in[17];
    const float* ln1b = (const float*)d_in[18];
    const float* ln2g = (const float*)d_in[19];
    const float* ln2b = (const float*)d_in[20];
    const float* lnfg = (const float*)d_in[21];
    const float* lnfb = (const float*)d_in[22];
    float* out = (float*)d_out;
    int E = in_sizes[3];

    cudaFuncSetAttribute(xformer_kernel,
                         cudaFuncAttributeMaxDynamicSharedMemorySize, SMEM_BYTES);

    float *x1p = nullptr, *x2p = nullptr;
    __half *wqh, *wkh, *wvh, *woh, *w1hp, *w2hp;
    cudaGetSymbolAddress((void**)&x1p, g_x1);
    cudaGetSymbolAddress((void**)&x2p, g_x2);
    cudaGetSymbolAddress((void**)&wqh, g_wqh);
    cudaGetSymbolAddress((void**)&wkh, g_wkh);
    cudaGetSymbolAddress((void**)&wvh, g_wvh);
    cudaGetSymbolAddress((void**)&woh, g_woh);
    cudaGetSymbolAddress((void**)&w1hp, g_w1h);
    cudaGetSymbolAddress((void**)&w2hp, g_w2h);

    zero_kernel<<<1024, 256>>>((float4*)x1p, NN * D / 4);
    zero_kernel<<<1024, 256>>>((float4*)x2p, NN * D / 4);

    cvt_kernel<<<32, 256>>>(wq, wqh, 2 * 4096);
    cvt_kernel<<<32, 256>>>(wk, wkh, 2 * 4096);
    cvt_kernel<<<32, 256>>>(wv, wvh, 2 * 4096);
    cvt_kernel<<<32, 256>>>(wo, woh, 2 * 4096);
    cvt_kernel<<<64, 256>>>(w1, w1hp, 2 * 16384);
    cvt_kernel<<<64, 256>>>(w2, w2hp, 2 * 16384);

    int sblocks = (E * 16 + 255) / 256;  // 16 lanes per edge
    gnn_scatter<<<sblocks, 256>>>(gnn, ei, ew, x1p, E);
    gnn_scatter<<<sblocks, 256>>>(x1p, ei, ew, x2p, E);

    fuse_kernel<<<(SB * SS + 7) / 8, 256>>>(seq, lens, bert, gnn, Wp, bp, pos);

    for (int i = 0; i < 2; i++) {
        xformer_kernel<<<SB, 256, SMEM_BYTES>>>(seq,
            wqh + i * 4096, wkh + i * 4096, wvh + i * 4096, woh + i * 4096,
            w1hp + i * 16384, b1 + i * 256, w2hp + i * 16384, b2 + i * 64,
            ln1g + i * 64, ln1b + i * 64, ln2g + i * 64, ln2b + i * 64);
    }

    final_kernel<<<SB / 8, 256>>>(lens, lnfg, lnfb, out);
}

// round 7
// speedup vs baseline: 2.2896x; 1.2669x over previous
#include <cuda_runtime.h>
#include <cuda_fp16.h>
#include <math.h>

#define NN   100001
#define D    64
#define SB   1024
#define SS   50
#define DFF  256

// ---------------- scratch (no allocations allowed) ----------------
__device__ float g_x1[NN * D];
__device__ float g_x2[NN * D];
__device__ float g_xbuf[SB * SS * D];
// fp16 packed weights (written once per launch by prep_kernel)
__device__ __align__(16) __half g_wqkvh[2 * 64 * 192];
__device__ __align__(16) __half g_woh[2 * 4096];
__device__ __align__(16) __half g_w1h[2 * 16384];
__device__ __align__(16) __half g_w2h[2 * 16384];

// ---------------- smem byte offsets for xformer ----------------
#define OFF_AH   0        // half[64][72]      9216
#define OFF_WH   9216     // stage, max 33792  -> 43008
#define OFF_XS   43008    // f32[3200]         -> 55808
#define OFF_QH   55808    // half[64][72]      -> 65024
#define OFF_KH   65024    // half[64][72]      -> 74240
#define OFF_PH   55808    // half[2][64][72]   (overlays QH+KH, dead)
#define OFF_VH   74240    // half[64][72]      -> 83456
#define OFF_SS   83456    // f32[2][64][52]    -> 110080
#define OFF_Y    83456    // f32[50][66]       (overlays VH/SS, dead)
#define OFF_H1H  55808    // half[64][264]     -> 89600 (FFN phase)
#define OFF_Y2   89600    // f32[50][66]       -> 102800
#define OFF_KM   110080   // f32[64]           -> 110336
#define SMEM_BYTES 110336

__device__ __forceinline__ float wsum(float v) {
#pragma unroll
    for (int o = 16; o > 0; o >>= 1) v += __shfl_xor_sync(0xffffffffu, v, o);
    return v;
}
__device__ __forceinline__ float wmax(float v) {
#pragma unroll
    for (int o = 16; o > 0; o >>= 1) v = fmaxf(v, __shfl_xor_sync(0xffffffffu, v, o));
    return v;
}
__device__ __forceinline__ float gelu_f(float x) {
    float inner = 0.7978845608028654f * (x + 0.044715f * x * x * x);
    return 0.5f * x * (1.0f + tanhf(inner));
}

// ---------------- mma helpers ----------------
__device__ __forceinline__ void ldsm_x4(unsigned &r0, unsigned &r1, unsigned &r2, unsigned &r3, unsigned addr) {
    asm volatile("ldmatrix.sync.aligned.m8n8.x4.shared.b16 {%0,%1,%2,%3}, [%4];"
                 : "=r"(r0), "=r"(r1), "=r"(r2), "=r"(r3) : "r"(addr));
}
__device__ __forceinline__ void ldsm_x4_t(unsigned &r0, unsigned &r1, unsigned &r2, unsigned &r3, unsigned addr) {
    asm volatile("ldmatrix.sync.aligned.m8n8.x4.trans.shared.b16 {%0,%1,%2,%3}, [%4];"
                 : "=r"(r0), "=r"(r1), "=r"(r2), "=r"(r3) : "r"(addr));
}
__device__ __forceinline__ void mma16816(float c[4], unsigned a0, unsigned a1, unsigned a2, unsigned a3,
                                         unsigned b0, unsigned b1) {
    asm volatile("mma.sync.aligned.m16n8k16.row.col.f32.f16.f16.f32 "
                 "{%0,%1,%2,%3}, {%4,%5,%6,%7}, {%8,%9}, {%0,%1,%2,%3};"
                 : "+f"(c[0]), "+f"(c[1]), "+f"(c[2]), "+f"(c[3])
                 : "r"(a0), "r"(a1), "r"(a2), "r"(a3), "r"(b0), "r"(b1));
}

// warp computes 16x32 tile. A row-major [m][k] read starting at column k0;
// B stored [k][n] row-major in a LOCAL buffer (rows 0..16*KT-1), trans ldmatrix.
// NOTE: k0 applies ONLY to the A side; B is freshly staged per K-chunk.
__device__ __forceinline__ void mma_block(const __half* Ah, int lda, int k0,
                                          const __half* Bh, int ldb, int n0,
                                          int m0, int KT, float acc[4][4]) {
    int lane = threadIdx.x & 31;
    unsigned abase = (unsigned)__cvta_generic_to_shared(Ah) +
                     (unsigned)(((m0 + (lane & 15)) * lda + k0 + ((lane >> 4) * 8)) * 2);
    unsigned bbase = (unsigned)__cvta_generic_to_shared(Bh);
    int brow = lane & 15;
    int bcol8 = (lane >> 4) * 8;
    for (int kt = 0; kt < KT; kt++) {
        unsigned a0, a1, a2, a3;
        ldsm_x4(a0, a1, a2, a3, abase + kt * 32);
#pragma unroll
        for (int ns = 0; ns < 2; ns++) {
            unsigned baddr = bbase + (unsigned)(((kt * 16 + brow) * ldb + n0 + ns * 16 + bcol8) * 2);
            unsigned b0, b1, b2, b3;
            ldsm_x4_t(b0, b1, b2, b3, baddr);
            mma16816(acc[ns * 2 + 0], a0, a1, a2, a3, b0, b1);
            mma16816(acc[ns * 2 + 1], a0, a1, a2, a3, b2, b3);
        }
    }
}

// scores: A = Qh [m][72] at k-cols h*32..; B = Kh [n][72] row-major (non-trans ldmatrix)
__device__ __forceinline__ void score_mma(float acc[4][4], const __half* Qh, const __half* Kh,
                                          int h, int m0, int n0, int lane) {
    unsigned abase = (unsigned)__cvta_generic_to_shared(Qh) +
                     (unsigned)(((m0 + (lane & 15)) * 72 + h * 32 + ((lane >> 4) * 8)) * 2);
    unsigned kb = (unsigned)__cvta_generic_to_shared(Kh);
    int nbase = n0 + (lane & 7) + ((lane >= 16) ? 8 : 0);
    int koff = ((lane & 15) >= 8) ? 8 : 0;
    for (int kt = 0; kt < 2; kt++) {
        unsigned a0, a1, a2, a3;
        ldsm_x4(a0, a1, a2, a3, abase + kt * 32);
#pragma unroll
        for (int ns = 0; ns < 2; ns++) {
            unsigned baddr = kb + (unsigned)(((nbase + ns * 16) * 72 + h * 32 + kt * 16 + koff) * 2);
            unsigned b0, b1, b2, b3;
            ldsm_x4(b0, b1, b2, b3, baddr);
            mma16816(acc[ns * 2 + 0], a0, a1, a2, a3, b0, b1);
            mma16816(acc[ns * 2 + 1], a0, a1, a2, a3, b2, b3);
        }
    }
}

// ---------------- prep: zero scratch + convert/pack weights -------
__global__ void prep_kernel(const float* __restrict__ wq, const float* __restrict__ wk,
                            const float* __restrict__ wv, const float* __restrict__ wo,
                            const float* __restrict__ w1, const float* __restrict__ w2)
{
    int i = blockIdx.x * blockDim.x + threadIdx.x;
    int st = gridDim.x * blockDim.x;
    float4 z = make_float4(0.f, 0.f, 0.f, 0.f);
    int n4 = NN * D / 4;
    for (int j = i; j < n4; j += st) { ((float4*)g_x1)[j] = z; ((float4*)g_x2)[j] = z; }
    for (int j = i; j < 2 * 64 * 192; j += st) {
        int blk = j / (64 * 192), rem = j % (64 * 192);
        int k = rem / 192, n = rem % 192;
        const float* src = (n < 64) ? wq : (n < 128) ? wk : wv;
        g_wqkvh[j] = __float2half_rn(src[blk * 4096 + k * 64 + (n & 63)]);
    }
    for (int j = i; j < 2 * 4096; j += st)  g_woh[j] = __float2half_rn(wo[j]);
    for (int j = i; j < 2 * 16384; j += st) g_w1h[j] = __float2half_rn(w1[j]);
    for (int j = i; j < 2 * 16384; j += st) g_w2h[j] = __float2half_rn(w2[j]);
}

// ---------------- GNN scatter: 16 lanes per edge, v4 red ----------
__global__ void __launch_bounds__(256) gnn_scatter(
    const float* __restrict__ xin, const int* __restrict__ ei,
    const float* __restrict__ ew, float* __restrict__ xout, int E)
{
    int t = blockIdx.x * blockDim.x + threadIdx.x;
    int edge = t >> 4;
    if (edge >= E) return;
    int comp = (t & 15) * 4;
    int src = __ldg(ei + edge);
    int dst = __ldg(ei + E + edge);
    float w = __ldg(ew + edge);
    float4 s4 = *(const float4*)(xin + (size_t)src * D + comp);
    float* dp = xout + (size_t)dst * D + comp;
    asm volatile("red.global.add.v4.f32 [%0], {%1,%2,%3,%4};"
                 :: "l"(dp), "f"(s4.x * w), "f"(s4.y * w), "f"(s4.z * w), "f"(s4.w * w)
                 : "memory");
}

// ---------------- fusion: gnn projection + alpha blend + pos ------
__global__ void __launch_bounds__(256) fuse_kernel(
    const int* __restrict__ seq, const int* __restrict__ lengths,
    const float* __restrict__ bert, const float* __restrict__ gnn_emb,
    const float* __restrict__ Wp, const float* __restrict__ bp,
    const float* __restrict__ pos)
{
    int row = blockIdx.x * 8 + (threadIdx.x >> 5);
    if (row >= SB * SS) return;
    int lane = threadIdx.x & 31;
    int b = row / SS, s = row - b * SS;
    int idx = seq[row];
    const float* gp  = gnn_emb + (size_t)idx * D;
    const float* x1p = g_x1 + (size_t)idx * D;
    const float* x2p = g_x2 + (size_t)idx * D;
    float a0 = (gp[lane]      + x1p[lane]      + x2p[lane])      * (1.0f / 3.0f);
    float a1 = (gp[lane + 32] + x1p[lane + 32] + x2p[lane + 32]) * (1.0f / 3.0f);
    float o0 = bp[lane], o1 = bp[lane + 32];
#pragma unroll
    for (int k = 0; k < 32; k++) {
        float ak = __shfl_sync(0xffffffffu, a0, k);
        o0 += ak * Wp[k * D + lane];
        o1 += ak * Wp[k * D + 32 + lane];
    }
#pragma unroll
    for (int k = 0; k < 32; k++) {
        float ak = __shfl_sync(0xffffffffu, a1, k);
        o0 += ak * Wp[(k + 32) * D + lane];
        o1 += ak * Wp[(k + 32) * D + 32 + lane];
    }
    int len = lengths[b];
    float alpha = (len <= 10) ? 0.3f : ((len >= 50) ? 0.7f : 0.5f);
    float beta = 1.0f - alpha;
    const float* brow = bert + (size_t)idx * D;
    g_xbuf[row * D + lane]      = alpha * brow[lane]      + beta * o0 + pos[s * D + lane];
    g_xbuf[row * D + 32 + lane] = alpha * brow[lane + 32] + beta * o1 + pos[s * D + 32 + lane];
}

// ---------------- transformer helpers ----------------
__device__ __forceinline__ void build_Ah(__half* Ah, const float* xs, int tid) {
    for (int i = tid; i < 64 * 32; i += 256) {
        int row = i >> 5, c2 = i & 31;
        __half2 hv;
        if (row < 50) {
            float2 xv = *(const float2*)(xs + row * 64 + c2 * 2);
            hv = __floats2half2_rn(xv.x, xv.y);
        } else {
            hv = __floats2half2_rn(0.f, 0.f);
        }
        *(__half2*)(Ah + row * 72 + c2 * 2) = hv;
    }
}

// fp16 epilogue into [64][72] buffer, all rows
__device__ __forceinline__ void epi_h16(__half* dst, float acc[4][4], int m0, int n0, int lane) {
    int r = m0 + (lane >> 2);
    int cb = (lane & 3) * 2;
#pragma unroll
    for (int t = 0; t < 4; t++) {
        int c = n0 + t * 8 + cb;
        *(__half2*)(dst + r * 72 + c)       = __floats2half2_rn(acc[t][0], acc[t][1]);
        *(__half2*)(dst + (r + 8) * 72 + c) = __floats2half2_rn(acc[t][2], acc[t][3]);
    }
}

__device__ __forceinline__ void epi_store66(float* dst, float acc[4][4], int m0, int n0, int lane) {
    int r = m0 + (lane >> 2);
    int cb = (lane & 3) * 2;
#pragma unroll
    for (int t = 0; t < 4; t++) {
        int c = n0 + t * 8 + cb;
        if (r < 50)     *(float2*)(dst + r * 66 + c)       = make_float2(acc[t][0], acc[t][1]);
        if (r + 8 < 50) *(float2*)(dst + (r + 8) * 66 + c) = make_float2(acc[t][2], acc[t][3]);
    }
}

__device__ __forceinline__ void ln_add(float* __restrict__ xs,
                                       const float* __restrict__ y,
                                       const float* __restrict__ g,
                                       const float* __restrict__ bta, int tid)
{
    int lane = tid & 31, w = tid >> 5;
    for (int r = w; r < 50; r += 8) {
        float v0 = xs[r * 64 + lane]      + y[r * 66 + lane];
        float v1 = xs[r * 64 + 32 + lane] + y[r * 66 + 32 + lane];
        float mean = wsum(v0 + v1) * (1.0f / 64.0f);
        float d0 = v0 - mean, d1 = v1 - mean;
        float var = wsum(d0 * d0 + d1 * d1) * (1.0f / 64.0f);
        float inv = 1.0f / sqrtf(var + 1e-5f);
        xs[r * 64 + lane]      = d0 * inv * g[lane]      + bta[lane];
        xs[r * 64 + 32 + lane] = d1 * inv * g[32 + lane] + bta[32 + lane];
    }
}

// ---------------- one transformer block, CTA per batch row --------
__global__ void __launch_bounds__(256) xformer_kernel(
    const int* __restrict__ seq,
    const __half* __restrict__ wqkvh, const __half* __restrict__ woh,
    const __half* __restrict__ w1h, const float* __restrict__ b1,
    const __half* __restrict__ w2h, const float* __restrict__ b2,
    const float* __restrict__ ln1g, const float* __restrict__ ln1b,
    const float* __restrict__ ln2g, const float* __restrict__ ln2b)
{
    extern __shared__ char smraw[];
    int tid = threadIdx.x;
    int lane = tid & 31, w = tid >> 5;
    int b = blockIdx.x;
    float* xg = g_xbuf + (size_t)b * SS * D;

    __half* Ah  = (__half*)(smraw + OFF_AH);
    __half* Wh  = (__half*)(smraw + OFF_WH);
    float*  xs  = (float*)(smraw + OFF_XS);
    __half* Qh  = (__half*)(smraw + OFF_QH);
    __half* Kh  = (__half*)(smraw + OFF_KH);
    __half* Ph  = (__half*)(smraw + OFF_PH);
    __half* Vh  = (__half*)(smraw + OFF_VH);
    float*  Ssm = (float*)(smraw + OFF_SS);
    float*  y   = (float*)(smraw + OFF_Y);
    __half* H1h = (__half*)(smraw + OFF_H1H);
    float*  y2  = (float*)(smraw + OFF_Y2);
    float*  km  = (float*)(smraw + OFF_KM);

    int m0 = (w & 3) * 16;
    int n0 = (w >> 2) * 32;

    // load xs, key-mask flags, build fp16 A, stage packed WQKV [64][200]
    for (int i = tid; i < 3200; i += 256) xs[i] = xg[i];
    if (tid < 64) km[tid] = (tid < 50) ? ((seq[b * SS + tid] != 0) ? 0.f : 1.f) : 2.f;
    __syncthreads();
    build_Ah(Ah, xs, tid);
    // 64 rows x 192 halves = 24 uint4 per row (uint4 = 8 halves)
    for (int i = tid; i < 1536; i += 256) {
        uint4 u = ((const uint4*)wqkvh)[i];
        int row = i / 24, c = (i % 24) * 8;
        *(uint4*)(Wh + row * 200 + c) = u;
    }
    __syncthreads();

    // QKV in one pass, N=192
#pragma unroll
    for (int ng = 0; ng < 3; ng++) {
        float acc[4][4] = {};
        mma_block(Ah, 72, 0, Wh, 200, ng * 64 + n0, m0, 4, acc);
        __half* dst = (ng == 0) ? Qh : (ng == 1) ? Kh : Vh;
        epi_h16(dst, acc, m0, n0, lane);
    }
    __syncthreads();

    // scores: S[h] = Q_h @ K_h^T (fp16 MMA), store fp32 raw dots
#pragma unroll
    for (int h = 0; h < 2; h++) {
        float acc[4][4] = {};
        score_mma(acc, Qh, Kh, h, m0, n0, lane);
        int r = m0 + (lane >> 2);
        int cb = (lane & 3) * 2;
        float* S = Ssm + h * 3328;
#pragma unroll
        for (int t = 0; t < 4; t++) {
            int c = n0 + t * 8 + cb;
            if (r < 50) {
                if (c < 50)     S[r * 52 + c]     = acc[t][0];
                if (c + 1 < 50) S[r * 52 + c + 1] = acc[t][1];
            }
            if (r + 8 < 50) {
                if (c < 50)     S[(r + 8) * 52 + c]     = acc[t][2];
                if (c + 1 < 50) S[(r + 8) * 52 + c + 1] = acc[t][3];
            }
        }
    }
    __syncthreads();

    // softmax -> Ph fp16 (pad cols & rows zeroed)
    {
        const float scale = 0.17677669529663687f; // 1/sqrt(32)
        for (int idx = w; idx < 128; idx += 8) {
            int h = idx >> 6, r = idx & 63;
            __half* prow = Ph + h * 4608 + r * 72;
            if (r >= 50) {
                *(__half2*)(prow + lane * 2) = __floats2half2_rn(0.f, 0.f);
            } else {
                const float* S = Ssm + h * 3328 + r * 52;
                float f0 = km[lane], f1 = km[lane + 32];
                float raw0 = S[lane];
                float raw1 = S[(lane + 32 < 50) ? lane + 32 : 0];
                float s0 = (f0 == 0.f) ? raw0 * scale : -1e9f;
                float s1 = (f1 == 0.f) ? raw1 * scale : ((f1 == 1.f) ? -1e9f : -INFINITY);
                float m = wmax(fmaxf(s0, s1));
                float e0 = expf(s0 - m);
                float e1 = expf(s1 - m);
                float inv = 1.0f / wsum(e0 + e1);
                prow[lane]      = __float2half_rn(e0 * inv);
                prow[lane + 32] = __float2half_rn(e1 * inv);
            }
        }
    }
    __syncthreads();

    // ctx = P @ V per head (fp16 MMA) -> Ah fp16
    {
        int h = w >> 2, mm = (w & 3) * 16;
        float acc[4][4] = {};
        mma_block(Ph + h * 4608, 72, 0, Vh, 72, h * 32, mm, 4, acc);
        int r = mm + (lane >> 2);
        int cb = (lane & 3) * 2;
#pragma unroll
        for (int t = 0; t < 4; t++) {
            int c = h * 32 + t * 8 + cb;
            *(__half2*)(Ah + r * 72 + c)       = __floats2half2_rn(acc[t][0], acc[t][1]);
            *(__half2*)(Ah + (r + 8) * 72 + c) = __floats2half2_rn(acc[t][2], acc[t][3]);
        }
    }
    __syncthreads();

    // O = ctx @ Wo -> y ; LN1
    for (int i = tid; i < 512; i += 256) {
        uint4 u = ((const uint4*)woh)[i];
        int row = i >> 3, c = (i & 7) * 8;
        *(uint4*)(Wh + row * 72 + c) = u;
    }
    __syncthreads();
    {
        float acc[4][4] = {};
        mma_block(Ah, 72, 0, Wh, 72, n0, m0, 4, acc);
        epi_store66(y, acc, m0, n0, lane);
    }
    __syncthreads();
    ln_add(xs, y, ln1g, ln1b, tid);
    __syncthreads();

    // FFN1
    build_Ah(Ah, xs, tid);
    // 64 rows x 256 halves = 32 uint4 per row
    for (int i = tid; i < 2048; i += 256) {
        uint4 u = ((const uint4*)w1h)[i];
        int row = i >> 5, c = (i & 31) * 8;
        *(uint4*)(Wh + row * 264 + c) = u;
    }
    __syncthreads();
#pragma unroll
    for (int ng = 0; ng < 4; ng++) {
        float acc[4][4] = {};
        mma_block(Ah, 72, 0, Wh, 264, ng * 64 + n0, m0, 4, acc);
        int r = m0 + (lane >> 2);
        int cb = (lane & 3) * 2;
#pragma unroll
        for (int t = 0; t < 4; t++) {
            int c = ng * 64 + n0 + t * 8 + cb;
            float bb0 = b1[c], bb1 = b1[c + 1];
            *(__half2*)(H1h + r * 264 + c) =
                __floats2half2_rn(gelu_f(acc[t][0] + bb0), gelu_f(acc[t][1] + bb1));
            *(__half2*)(H1h + (r + 8) * 264 + c) =
                __floats2half2_rn(gelu_f(acc[t][2] + bb0), gelu_f(acc[t][3] + bb1));
        }
    }
    __syncthreads();

    // FFN2: K=256 in 2 staged chunks of [128][72] (B rows are chunk-local)
    {
        float acc[4][4] = {};
        for (int ch = 0; ch < 2; ch++) {
            for (int i = tid; i < 1024; i += 256) {
                uint4 u = ((const uint4*)w2h)[ch * 1024 + i];
                int row = i >> 3, c = (i & 7) * 8;
                *(uint4*)(Wh + row * 72 + c) = u;
            }
            __syncthreads();
            mma_block(H1h, 264, ch * 128, Wh, 72, n0, m0, 8, acc);
            __syncthreads();
        }
        int r = m0 + (lane >> 2);
        int cb = (lane & 3) * 2;
#pragma unroll
        for (int t = 0; t < 4; t++) {
            int c = n0 + t * 8 + cb;
            float bb0 = b2[c], bb1 = b2[c + 1];
            if (r < 50)     *(float2*)(y2 + r * 66 + c)       = make_float2(acc[t][0] + bb0, acc[t][1] + bb1);
            if (r + 8 < 50) *(float2*)(y2 + (r + 8) * 66 + c) = make_float2(acc[t][2] + bb0, acc[t][3] + bb1);
        }
    }
    __syncthreads();
    ln_add(xs, y2, ln2g, ln2b, tid);
    __syncthreads();
    for (int i = tid; i < 3200; i += 256) xg[i] = xs[i];
}

// ---------------- final LN + gather -------------------------------
__global__ void __launch_bounds__(256) final_kernel(
    const int* __restrict__ lengths, const float* __restrict__ g,
    const float* __restrict__ bt, float* __restrict__ out)
{
    int b = blockIdx.x * 8 + (threadIdx.x >> 5);
    if (b >= SB) return;
    int lane = threadIdx.x & 31;
    int r = lengths[b] - 1;
    const float* row = g_xbuf + ((size_t)b * SS + r) * D;
    float v0 = row[lane], v1 = row[lane + 32];
    float mean = wsum(v0 + v1) * (1.0f / 64.0f);
    float d0 = v0 - mean, d1 = v1 - mean;
    float var = wsum(d0 * d0 + d1 * d1) * (1.0f / 64.0f);
    float inv = 1.0f / sqrtf(var + 1e-5f);
    out[b * D + lane]      = d0 * inv * g[lane]      + bt[lane];
    out[b * D + 32 + lane] = d1 * inv * g[lane + 32] + bt[lane + 32];
}

// ---------------- launch -------------------------------------------
extern "C" void kernel_launch(void* const* d_in, const int* in_sizes, int n_in,
                              void* d_out, int out_size)
{
    const int*   seq  = (const int*)d_in[0];
    const int*   lens = (const int*)d_in[1];
    const int*   ei   = (const int*)d_in[2];
    const float* ew   = (const float*)d_in[3];
    const float* bert = (const float*)d_in[4];
    const float* gnn  = (const float*)d_in[5];
    const float* Wp   = (const float*)d_in[6];
    const float* bp   = (const float*)d_in[7];
    const float* pos  = (const float*)d_in[8];
    const float* wq   = (const float*)d_in[9];
    const float* wk   = (const float*)d_in[10];
    const float* wv   = (const float*)d_in[11];
    const float* wo   = (const float*)d_in[12];
    const float* w1   = (const float*)d_in[13];
    const float* b1   = (const float*)d_in[14];
    const float* w2   = (const float*)d_in[15];
    const float* b2   = (const float*)d_in[16];
    const float* ln1g = (const float*)d_in[17];
    const float* ln1b = (const float*)d_in[18];
    const float* ln2g = (const float*)d_in[19];
    const float* ln2b = (const float*)d_in[20];
    const float* lnfg = (const float*)d_in[21];
    const float* lnfb = (const float*)d_in[22];
    float* out = (float*)d_out;
    int E = in_sizes[3];

    cudaFuncSetAttribute(xformer_kernel,
                         cudaFuncAttributeMaxDynamicSharedMemorySize, SMEM_BYTES);

    float *x1p = nullptr, *x2p = nullptr;
    __half *wqkvh, *woh, *w1hp, *w2hp;
    cudaGetSymbolAddress((void**)&x1p, g_x1);
    cudaGetSymbolAddress((void**)&x2p, g_x2);
    cudaGetSymbolAddress((void**)&wqkvh, g_wqkvh);
    cudaGetSymbolAddress((void**)&woh, g_woh);
    cudaGetSymbolAddress((void**)&w1hp, g_w1h);
    cudaGetSymbolAddress((void**)&w2hp, g_w2h);

    prep_kernel<<<2048, 256>>>(wq, wk, wv, wo, w1, w2);

    int sblocks = (E * 16 + 255) / 256;  // 16 lanes per edge
    gnn_scatter<<<sblocks, 256>>>(gnn, ei, ew, x1p, E);
    gnn_scatter<<<sblocks, 256>>>(x1p, ei, ew, x2p, E);

    fuse_kernel<<<(SB * SS + 7) / 8, 256>>>(seq, lens, bert, gnn, Wp, bp, pos);

    for (int i = 0; i < 2; i++) {
        xformer_kernel<<<SB, 256, SMEM_BYTES>>>(seq,
            wqkvh + i * 12288, woh + i * 4096,
            w1hp + i * 16384, b1 + i * 256, w2hp + i * 16384, b2 + i * 64,
            ln1g + i * 64, ln1b + i * 64, ln2g + i * 64, ln2b + i * 64);
    }

    final_kernel<<<SB / 8, 256>>>(lens, lnfg, lnfb, out);
}

// round 8
// speedup vs baseline: 2.4537x; 1.0717x over previous
#include <cuda_runtime.h>
#include <cuda_fp16.h>
#include <math.h>

#define NN   100001
#define D    64
#define SB   1024
#define SQ   50
#define DFF  256

// ---------------- scratch (no allocations allowed) ----------------
__device__ float g_x1[NN * D];
__device__ float g_x2[NN * D];
__device__ float g_proj[NN * D];
__device__ float g_xbuf[SB * SQ * D];
// fp16 packed weights (written once per launch by prep_kernel)
__device__ __align__(16) __half g_wqkvh[2 * 64 * 192];
__device__ __align__(16) __half g_woh[2 * 4096];
__device__ __align__(16) __half g_w1h[2 * 16384];
__device__ __align__(16) __half g_w2h[2 * 16384];

// ---------------- smem byte offsets for xformer (total 75520) -----
#define SO_XS   0        // f32[3200]          -> 12800
#define SO_AH   12800    // half[64][72]       -> 22016
#define SO_KM   22016    // f32[64]            -> 22272
#define SO_QH   22272    // half[64][72]       -> 31488
#define SO_KH   31488    // half[64][72]       -> 40704
#define SO_PH   22272    // half[2][64][72]    (overlays QH+KH, dead)
#define SO_VH   40704    // half[64][72]       -> 49920
#define SO_WST  49920    // half[64][200]      -> 75520 (WQKV stage)
#define SO_SS   49920    // f32[2][50][52]     -> 70720 (overlay WST, dead)
#define SO_Y    49920    // f32[50][66]        -> 63120 (overlay SS, dead)
#define SO_WOST 63120    // half[64][72]       -> 72336
#define SO_W1C  22272    // half[64][136]      -> 39680 (FFN, PH dead)
#define SO_H1C  39680    // half[64][136]      -> 57088
#define SO_W2C  57088    // half[128][72]      -> 75520
#define SO_Y2   22272    // f32[50][66]        (after W1C dead)
#define SMEM_BYTES 75520

__device__ __forceinline__ float wsum(float v) {
#pragma unroll
    for (int o = 16; o > 0; o >>= 1) v += __shfl_xor_sync(0xffffffffu, v, o);
    return v;
}
__device__ __forceinline__ float wmax(float v) {
#pragma unroll
    for (int o = 16; o > 0; o >>= 1) v = fmaxf(v, __shfl_xor_sync(0xffffffffu, v, o));
    return v;
}
__device__ __forceinline__ float gelu_f(float x) {
    float inner = 0.7978845608028654f * (x + 0.044715f * x * x * x);
    return 0.5f * x * (1.0f + tanhf(inner));
}

// ---------------- mma helpers ----------------
__device__ __forceinline__ void ldsm_x4(unsigned &r0, unsigned &r1, unsigned &r2, unsigned &r3, unsigned addr) {
    asm volatile("ldmatrix.sync.aligned.m8n8.x4.shared.b16 {%0,%1,%2,%3}, [%4];"
                 : "=r"(r0), "=r"(r1), "=r"(r2), "=r"(r3) : "r"(addr));
}
__device__ __forceinline__ void ldsm_x4_t(unsigned &r0, unsigned &r1, unsigned &r2, unsigned &r3, unsigned addr) {
    asm volatile("ldmatrix.sync.aligned.m8n8.x4.trans.shared.b16 {%0,%1,%2,%3}, [%4];"
                 : "=r"(r0), "=r"(r1), "=r"(r2), "=r"(r3) : "r"(addr));
}
__device__ __forceinline__ void mma16816(float c[4], unsigned a0, unsigned a1, unsigned a2, unsigned a3,
                                         unsigned b0, unsigned b1) {
    asm volatile("mma.sync.aligned.m16n8k16.row.col.f32.f16.f16.f32 "
                 "{%0,%1,%2,%3}, {%4,%5,%6,%7}, {%8,%9}, {%0,%1,%2,%3};"
                 : "+f"(c[0]), "+f"(c[1]), "+f"(c[2]), "+f"(c[3])
                 : "r"(a0), "r"(a1), "r"(a2), "r"(a3), "r"(b0), "r"(b1));
}

// warp computes 16x32 tile. A row-major [m][k] read starting at column k0;
// B stored [k][n] row-major in a LOCAL buffer (rows 0..16*KT-1), trans ldmatrix.
// k0 applies ONLY to the A side.
__device__ __forceinline__ void mma_block(const __half* Ah, int lda, int k0,
                                          const __half* Bh, int ldb, int n0,
                                          int m0, int KT, float acc[4][4]) {
    int lane = threadIdx.x & 31;
    unsigned abase = (unsigned)__cvta_generic_to_shared(Ah) +
                     (unsigned)(((m0 + (lane & 15)) * lda + k0 + ((lane >> 4) * 8)) * 2);
    unsigned bbase = (unsigned)__cvta_generic_to_shared(Bh);
    int brow = lane & 15;
    int bcol8 = (lane >> 4) * 8;
    for (int kt = 0; kt < KT; kt++) {
        unsigned a0, a1, a2, a3;
        ldsm_x4(a0, a1, a2, a3, abase + kt * 32);
#pragma unroll
        for (int ns = 0; ns < 2; ns++) {
            unsigned baddr = bbase + (unsigned)(((kt * 16 + brow) * ldb + n0 + ns * 16 + bcol8) * 2);
            unsigned b0, b1, b2, b3;
            ldsm_x4_t(b0, b1, b2, b3, baddr);
            mma16816(acc[ns * 2 + 0], a0, a1, a2, a3, b0, b1);
            mma16816(acc[ns * 2 + 1], a0, a1, a2, a3, b2, b3);
        }
    }
}

// scores: A = Qh [m][72] at k-cols h*32..; B = Kh [n][72] row-major (non-trans ldmatrix)
__device__ __forceinline__ void score_mma(float acc[4][4], const __half* Qh, const __half* Kh,
                                          int h, int m0, int n0, int lane) {
    unsigned abase = (unsigned)__cvta_generic_to_shared(Qh) +
                     (unsigned)(((m0 + (lane & 15)) * 72 + h * 32 + ((lane >> 4) * 8)) * 2);
    unsigned kb = (unsigned)__cvta_generic_to_shared(Kh);
    int nbase = n0 + (lane & 7) + ((lane >= 16) ? 8 : 0);
    int koff = ((lane & 15) >= 8) ? 8 : 0;
    for (int kt = 0; kt < 2; kt++) {
        unsigned a0, a1, a2, a3;
        ldsm_x4(a0, a1, a2, a3, abase + kt * 32);
#pragma unroll
        for (int ns = 0; ns < 2; ns++) {
            unsigned baddr = kb + (unsigned)(((nbase + ns * 16) * 72 + h * 32 + kt * 16 + koff) * 2);
            unsigned b0, b1, b2, b3;
            ldsm_x4(b0, b1, b2, b3, baddr);
            mma16816(acc[ns * 2 + 0], a0, a1, a2, a3, b0, b1);
            mma16816(acc[ns * 2 + 1], a0, a1, a2, a3, b2, b3);
        }
    }
}

// ---------------- prep: zero scratch + convert/pack weights -------
__global__ void prep_kernel(const float* __restrict__ wq, const float* __restrict__ wk,
                            const float* __restrict__ wv, const float* __restrict__ wo,
                            const float* __restrict__ w1, const float* __restrict__ w2)
{
    int i = blockIdx.x * blockDim.x + threadIdx.x;
    int st = gridDim.x * blockDim.x;
    float4 z = make_float4(0.f, 0.f, 0.f, 0.f);
    int n4 = NN * D / 4;
    for (int j = i; j < n4; j += st) { ((float4*)g_x1)[j] = z; ((float4*)g_x2)[j] = z; }
    for (int j = i; j < 2 * 64 * 192; j += st) {
        int blk = j / (64 * 192), rem = j % (64 * 192);
        int k = rem / 192, n = rem % 192;
        const float* src = (n < 64) ? wq : (n < 128) ? wk : wv;
        g_wqkvh[j] = __float2half_rn(src[blk * 4096 + k * 64 + (n & 63)]);
    }
    for (int j = i; j < 2 * 4096; j += st)  g_woh[j] = __float2half_rn(wo[j]);
    for (int j = i; j < 2 * 16384; j += st) g_w1h[j] = __float2half_rn(w1[j]);
    for (int j = i; j < 2 * 16384; j += st) g_w2h[j] = __float2half_rn(w2[j]);
}

// ---------------- GNN scatter: 16 lanes per edge, v4 red ----------
__global__ void __launch_bounds__(256) gnn_scatter(
    const float* __restrict__ xin, const int* __restrict__ ei,
    const float* __restrict__ ew, float* __restrict__ xout, int E)
{
    int t = blockIdx.x * blockDim.x + threadIdx.x;
    int edge = t >> 4;
    if (edge >= E) return;
    int comp = (t & 15) * 4;
    int src = __ldg(ei + edge);
    int dst = __ldg(ei + E + edge);
    float w = __ldg(ew + edge);
    float4 s4 = *(const float4*)(xin + (size_t)src * D + comp);
    float* dp = xout + (size_t)dst * D + comp;
    asm volatile("red.global.add.v4.f32 [%0], {%1,%2,%3,%4};"
                 :: "l"(dp), "f"(s4.x * w), "f"(s4.y * w), "f"(s4.z * w), "f"(s4.w * w)
                 : "memory");
}

// ---------------- proj: g_proj = ((gnn+x1+x2)/3) @ Wp + bp, all N --
__global__ void __launch_bounds__(256) proj_kernel(
    const float* __restrict__ gnn_emb, const float* __restrict__ Wp,
    const float* __restrict__ bp)
{
    __shared__ float Wps[4096];
    __shared__ float bps[64];
    int tid = threadIdx.x;
    for (int i = tid; i < 4096; i += 256) Wps[i] = Wp[i];
    if (tid < 64) bps[tid] = bp[tid];
    __syncthreads();
    int lane = tid & 31, w = tid >> 5;
    int base = blockIdx.x * 32 + w * 4;
    float alo[4], ahi[4], ac0[4], ac1[4];
#pragma unroll
    for (int j = 0; j < 4; j++) {
        int row = base + j;
        ac0[j] = 0.f; ac1[j] = 0.f;
        if (row < NN) {
            size_t o = (size_t)row * D;
            alo[j] = (gnn_emb[o + lane]      + g_x1[o + lane]      + g_x2[o + lane])      * (1.0f / 3.0f);
            ahi[j] = (gnn_emb[o + 32 + lane] + g_x1[o + 32 + lane] + g_x2[o + 32 + lane]) * (1.0f / 3.0f);
        } else { alo[j] = 0.f; ahi[j] = 0.f; }
    }
#pragma unroll
    for (int k = 0; k < 64; k++) {
        float w0 = Wps[k * 64 + lane];
        float w1 = Wps[k * 64 + 32 + lane];
#pragma unroll
        for (int j = 0; j < 4; j++) {
            float ak = __shfl_sync(0xffffffffu, (k < 32) ? alo[j] : ahi[j], k & 31);
            ac0[j] += ak * w0;
            ac1[j] += ak * w1;
        }
    }
#pragma unroll
    for (int j = 0; j < 4; j++) {
        int row = base + j;
        if (row < NN) {
            size_t o = (size_t)row * D;
            g_proj[o + lane]      = ac0[j] + bps[lane];
            g_proj[o + 32 + lane] = ac1[j] + bps[32 + lane];
        }
    }
}

// ---------------- fuse2: gather bert/proj, blend, add pos ---------
__global__ void __launch_bounds__(256) fuse2_kernel(
    const int* __restrict__ seq, const int* __restrict__ lengths,
    const float* __restrict__ bert, const float* __restrict__ pos)
{
    int row = blockIdx.x * 8 + (threadIdx.x >> 5);
    if (row >= SB * SQ) return;
    int lane = threadIdx.x & 31;
    int b = row / SQ, s = row - b * SQ;
    int idx = seq[row];
    int len = lengths[b];
    float alpha = (len <= 10) ? 0.3f : ((len >= 50) ? 0.7f : 0.5f);
    float beta = 1.0f - alpha;
    size_t o = (size_t)idx * D;
    g_xbuf[row * D + lane]      = alpha * bert[o + lane]      + beta * g_proj[o + lane]      + pos[s * D + lane];
    g_xbuf[row * D + 32 + lane] = alpha * bert[o + 32 + lane] + beta * g_proj[o + 32 + lane] + pos[s * D + 32 + lane];
}

// ---------------- transformer helpers ----------------
__device__ __forceinline__ void build_Ah(__half* Ah, const float* xs, int tid) {
    for (int i = tid; i < 64 * 32; i += 256) {
        int row = i >> 5, c2 = i & 31;
        __half2 hv;
        if (row < 50) {
            float2 xv = *(const float2*)(xs + row * 64 + c2 * 2);
            hv = __floats2half2_rn(xv.x, xv.y);
        } else {
            hv = __floats2half2_rn(0.f, 0.f);
        }
        *(__half2*)(Ah + row * 72 + c2 * 2) = hv;
    }
}

__device__ __forceinline__ void epi_h16(__half* dst, float acc[4][4], int m0, int n0, int lane) {
    int r = m0 + (lane >> 2);
    int cb = (lane & 3) * 2;
#pragma unroll
    for (int t = 0; t < 4; t++) {
        int c = n0 + t * 8 + cb;
        *(__half2*)(dst + r * 72 + c)       = __floats2half2_rn(acc[t][0], acc[t][1]);
        *(__half2*)(dst + (r + 8) * 72 + c) = __floats2half2_rn(acc[t][2], acc[t][3]);
    }
}

__device__ __forceinline__ void epi_store66(float* dst, float acc[4][4], int m0, int n0, int lane) {
    int r = m0 + (lane >> 2);
    int cb = (lane & 3) * 2;
#pragma unroll
    for (int t = 0; t < 4; t++) {
        int c = n0 + t * 8 + cb;
        if (r < 50)     *(float2*)(dst + r * 66 + c)       = make_float2(acc[t][0], acc[t][1]);
        if (r + 8 < 50) *(float2*)(dst + (r + 8) * 66 + c) = make_float2(acc[t][2], acc[t][3]);
    }
}

__device__ __forceinline__ void ln_add(float* __restrict__ xs,
                                       const float* __restrict__ y,
                                       const float* __restrict__ g,
                                       const float* __restrict__ bta, int tid)
{
    int lane = tid & 31, w = tid >> 5;
    for (int r = w; r < 50; r += 8) {
        float v0 = xs[r * 64 + lane]      + y[r * 66 + lane];
        float v1 = xs[r * 64 + 32 + lane] + y[r * 66 + 32 + lane];
        float mean = wsum(v0 + v1) * (1.0f / 64.0f);
        float d0 = v0 - mean, d1 = v1 - mean;
        float var = wsum(d0 * d0 + d1 * d1) * (1.0f / 64.0f);
        float inv = 1.0f / sqrtf(var + 1e-5f);
        xs[r * 64 + lane]      = d0 * inv * g[lane]      + bta[lane];
        xs[r * 64 + 32 + lane] = d1 * inv * g[32 + lane] + bta[32 + lane];
    }
}

// -------- both transformer blocks, CTA per batch row, occ-3 smem --
__global__ void __launch_bounds__(256) xformer_kernel(
    const int* __restrict__ seq,
    const __half* __restrict__ wqkvh_all, const __half* __restrict__ woh_all,
    const __half* __restrict__ w1h_all, const float* __restrict__ b1_all,
    const __half* __restrict__ w2h_all, const float* __restrict__ b2_all,
    const float* __restrict__ ln1g_all, const float* __restrict__ ln1b_all,
    const float* __restrict__ ln2g_all, const float* __restrict__ ln2b_all)
{
    extern __shared__ char smraw[];
    int tid = threadIdx.x;
    int lane = tid & 31, w = tid >> 5;
    int b = blockIdx.x;
    float* xg = g_xbuf + (size_t)b * SQ * D;

    float*  xs  = (float*)(smraw + SO_XS);
    __half* Ah  = (__half*)(smraw + SO_AH);
    float*  km  = (float*)(smraw + SO_KM);
    __half* Qh  = (__half*)(smraw + SO_QH);
    __half* Kh  = (__half*)(smraw + SO_KH);
    __half* Ph  = (__half*)(smraw + SO_PH);
    __half* Vh  = (__half*)(smraw + SO_VH);
    __half* Wst = (__half*)(smraw + SO_WST);
    float*  Ssm = (float*)(smraw + SO_SS);
    float*  y   = (float*)(smraw + SO_Y);
    __half* Wos = (__half*)(smraw + SO_WOST);
    __half* W1c = (__half*)(smraw + SO_W1C);
    __half* H1c = (__half*)(smraw + SO_H1C);
    __half* W2c = (__half*)(smraw + SO_W2C);
    float*  y2  = (float*)(smraw + SO_Y2);

    int m0 = (w & 3) * 16;
    int n0 = (w >> 2) * 32;

    for (int i = tid; i < 3200; i += 256) xs[i] = xg[i];
    if (tid < 64) km[tid] = (tid < 50) ? ((seq[b * SQ + tid] != 0) ? 0.f : 1.f) : 2.f;
    __syncthreads();

    for (int blk = 0; blk < 2; blk++) {
        const __half* wqkvh = wqkvh_all + blk * 12288;
        const __half* woh   = woh_all   + blk * 4096;
        const __half* w1h   = w1h_all   + blk * 16384;
        const float*  b1    = b1_all    + blk * 256;
        const __half* w2h   = w2h_all   + blk * 16384;
        const float*  b2    = b2_all    + blk * 64;
        const float*  ln1g  = ln1g_all  + blk * 64;
        const float*  ln1b  = ln1b_all  + blk * 64;
        const float*  ln2g  = ln2g_all  + blk * 64;
        const float*  ln2b  = ln2b_all  + blk * 64;

        // build fp16 A, stage packed WQKV [64][200]
        build_Ah(Ah, xs, tid);
        for (int i = tid; i < 1536; i += 256) {
            uint4 u = ((const uint4*)wqkvh)[i];
            int row = i / 24, c = (i % 24) * 8;
            *(uint4*)(Wst + row * 200 + c) = u;
        }
        __syncthreads();

        // QKV in one pass, N=192
#pragma unroll
        for (int ng = 0; ng < 3; ng++) {
            float acc[4][4] = {};
            mma_block(Ah, 72, 0, Wst, 200, ng * 64 + n0, m0, 4, acc);
            __half* dst = (ng == 0) ? Qh : (ng == 1) ? Kh : Vh;
            epi_h16(dst, acc, m0, n0, lane);
        }
        __syncthreads();

        // scores -> SS (overlays Wst, now dead)
#pragma unroll
        for (int h = 0; h < 2; h++) {
            float acc[4][4] = {};
            score_mma(acc, Qh, Kh, h, m0, n0, lane);
            int r = m0 + (lane >> 2);
            int cb = (lane & 3) * 2;
            float* S = Ssm + h * 2600;
#pragma unroll
            for (int t = 0; t < 4; t++) {
                int c = n0 + t * 8 + cb;
                if (r < 50) {
                    if (c < 50)     S[r * 52 + c]     = acc[t][0];
                    if (c + 1 < 50) S[r * 52 + c + 1] = acc[t][1];
                }
                if (r + 8 < 50) {
                    if (c < 50)     S[(r + 8) * 52 + c]     = acc[t][2];
                    if (c + 1 < 50) S[(r + 8) * 52 + c + 1] = acc[t][3];
                }
            }
        }
        __syncthreads();

        // softmax -> Ph fp16 (overlays QH/KH, now dead)
        {
            const float scale = 0.17677669529663687f; // 1/sqrt(32)
            for (int idx = w; idx < 128; idx += 8) {
                int h = idx >> 6, r = idx & 63;
                __half* prow = Ph + h * 4608 + r * 72;
                if (r >= 50) {
                    *(__half2*)(prow + lane * 2) = __floats2half2_rn(0.f, 0.f);
                } else {
                    const float* S = Ssm + h * 2600 + r * 52;
                    float f0 = km[lane], f1 = km[lane + 32];
                    float raw0 = S[lane];
                    float raw1 = S[(lane + 32 < 50) ? lane + 32 : 0];
                    float s0 = (f0 == 0.f) ? raw0 * scale : -1e9f;
                    float s1 = (f1 == 0.f) ? raw1 * scale : ((f1 == 1.f) ? -1e9f : -INFINITY);
                    float m = wmax(fmaxf(s0, s1));
                    float e0 = expf(s0 - m);
                    float e1 = expf(s1 - m);
                    float inv = 1.0f / wsum(e0 + e1);
                    prow[lane]      = __float2half_rn(e0 * inv);
                    prow[lane + 32] = __float2half_rn(e1 * inv);
                }
            }
        }
        __syncthreads();

        // ctx = P @ V per head -> Ah; concurrently stage Wo (SS dead)
        {
            int h = w >> 2, mm = (w & 3) * 16;
            float acc[4][4] = {};
            mma_block(Ph + h * 4608, 72, 0, Vh, 72, h * 32, mm, 4, acc);
            int r = mm + (lane >> 2);
            int cb = (lane & 3) * 2;
#pragma unroll
            for (int t = 0; t < 4; t++) {
                int c = h * 32 + t * 8 + cb;
                *(__half2*)(Ah + r * 72 + c)       = __floats2half2_rn(acc[t][0], acc[t][1]);
                *(__half2*)(Ah + (r + 8) * 72 + c) = __floats2half2_rn(acc[t][2], acc[t][3]);
            }
        }
        for (int i = tid; i < 512; i += 256) {
            uint4 u = ((const uint4*)woh)[i];
            int row = i >> 3, c = (i & 7) * 8;
            *(uint4*)(Wos + row * 72 + c) = u;
        }
        __syncthreads();

        // O = ctx @ Wo -> y ; LN1
        {
            float acc[4][4] = {};
            mma_block(Ah, 72, 0, Wos, 72, n0, m0, 4, acc);
            epi_store66(y, acc, m0, n0, lane);
        }
        __syncthreads();
        ln_add(xs, y, ln1g, ln1b, tid);
        __syncthreads();

        // FFN: two chunks of 128 (N for FFN1, K for FFN2)
        build_Ah(Ah, xs, tid);
        {
            float acc[4][4] = {};
            for (int ch = 0; ch < 2; ch++) {
                // stage W1 chunk [64][136] and W2 chunk [128][72]
                for (int i = tid; i < 1024; i += 256) {
                    int row = i >> 4, j = i & 15;
                    uint4 u = ((const uint4*)w1h)[row * 32 + ch * 16 + j];
                    *(uint4*)(W1c + row * 136 + j * 8) = u;
                }
                for (int i = tid; i < 1024; i += 256) {
                    uint4 u = ((const uint4*)w2h)[ch * 1024 + i];
                    int row = i >> 3, c = (i & 7) * 8;
                    *(uint4*)(W2c + row * 72 + c) = u;
                }
                __syncthreads();
                // FFN1: H1c = fp16(gelu(Ah @ W1c + b1)), N=128 per chunk
#pragma unroll
                for (int ng = 0; ng < 2; ng++) {
                    float a1[4][4] = {};
                    mma_block(Ah, 72, 0, W1c, 136, ng * 64 + n0, m0, 4, a1);
                    int r = m0 + (lane >> 2);
                    int cb = (lane & 3) * 2;
#pragma unroll
                    for (int t = 0; t < 4; t++) {
                        int cl = ng * 64 + n0 + t * 8 + cb;
                        int cg = ch * 128 + cl;
                        float bb0 = b1[cg], bb1 = b1[cg + 1];
                        *(__half2*)(H1c + r * 136 + cl) =
                            __floats2half2_rn(gelu_f(a1[t][0] + bb0), gelu_f(a1[t][1] + bb1));
                        *(__half2*)(H1c + (r + 8) * 136 + cl) =
                            __floats2half2_rn(gelu_f(a1[t][2] + bb0), gelu_f(a1[t][3] + bb1));
                    }
                }
                __syncthreads();
                // FFN2 accumulate: K=128 chunk (chunk-local A and B)
                mma_block(H1c, 136, 0, W2c, 72, n0, m0, 8, acc);
                __syncthreads();
            }
            // y2 epilogue (W1c region dead)
            int r = m0 + (lane >> 2);
            int cb = (lane & 3) * 2;
#pragma unroll
            for (int t = 0; t < 4; t++) {
                int c = n0 + t * 8 + cb;
                float bb0 = b2[c], bb1 = b2[c + 1];
                if (r < 50)     *(float2*)(y2 + r * 66 + c)       = make_float2(acc[t][0] + bb0, acc[t][1] + bb1);
                if (r + 8 < 50) *(float2*)(y2 + (r + 8) * 66 + c) = make_float2(acc[t][2] + bb0, acc[t][3] + bb1);
            }
        }
        __syncthreads();
        ln_add(xs, y2, ln2g, ln2b, tid);
        __syncthreads();
    }

    for (int i = tid; i < 3200; i += 256) xg[i] = xs[i];
}

// ---------------- final LN + gather -------------------------------
__global__ void __launch_bounds__(256) final_kernel(
    const int* __restrict__ lengths, const float* __restrict__ g,
    const float* __restrict__ bt, float* __restrict__ out)
{
    int b = blockIdx.x * 8 + (threadIdx.x >> 5);
    if (b >= SB) return;
    int lane = threadIdx.x & 31;
    int r = lengths[b] - 1;
    const float* row = g_xbuf + ((size_t)b * SQ + r) * D;
    float v0 = row[lane], v1 = row[lane + 32];
    float mean = wsum(v0 + v1) * (1.0f / 64.0f);
    float d0 = v0 - mean, d1 = v1 - mean;
    float var = wsum(d0 * d0 + d1 * d1) * (1.0f / 64.0f);
    float inv = 1.0f / sqrtf(var + 1e-5f);
    out[b * D + lane]      = d0 * inv * g[lane]      + bt[lane];
    out[b * D + 32 + lane] = d1 * inv * g[lane + 32] + bt[lane + 32];
}

// ---------------- launch -------------------------------------------
extern "C" void kernel_launch(void* const* d_in, const int* in_sizes, int n_in,
                              void* d_out, int out_size)
{
    const int*   seq  = (const int*)d_in[0];
    const int*   lens = (const int*)d_in[1];
    const int*   ei   = (const int*)d_in[2];
    const float* ew   = (const float*)d_in[3];
    const float* bert = (const float*)d_in[4];
    const float* gnn  = (const float*)d_in[5];
    const float* Wp   = (const float*)d_in[6];
    const float* bp   = (const float*)d_in[7];
    const float* pos  = (const float*)d_in[8];
    const float* wq   = (const float*)d_in[9];
    const float* wk   = (const float*)d_in[10];
    const float* wv   = (const float*)d_in[11];
    const float* wo   = (const float*)d_in[12];
    const float* w1   = (const float*)d_in[13];
    const float* b1   = (const float*)d_in[14];
    const float* w2   = (const float*)d_in[15];
    const float* b2   = (const float*)d_in[16];
    const float* ln1g = (const float*)d_in[17];
    const float* ln1b = (const float*)d_in[18];
    const float* ln2g = (const float*)d_in[19];
    const float* ln2b = (const float*)d_in[20];
    const float* lnfg = (const float*)d_in[21];
    const float* lnfb = (const float*)d_in[22];
    float* out = (float*)d_out;
    int E = in_sizes[3];

    cudaFuncSetAttribute(xformer_kernel,
                         cudaFuncAttributeMaxDynamicSharedMemorySize, SMEM_BYTES);

    float *x1p = nullptr, *x2p = nullptr;
    __half *wqkvh, *woh, *w1hp, *w2hp;
    cudaGetSymbolAddress((void**)&x1p, g_x1);
    cudaGetSymbolAddress((void**)&x2p, g_x2);
    cudaGetSymbolAddress((void**)&wqkvh, g_wqkvh);
    cudaGetSymbolAddress((void**)&woh, g_woh);
    cudaGetSymbolAddress((void**)&w1hp, g_w1h);
    cudaGetSymbolAddress((void**)&w2hp, g_w2h);

    prep_kernel<<<2048, 256>>>(wq, wk, wv, wo, w1, w2);

    int sblocks = (E * 16 + 255) / 256;  // 16 lanes per edge
    gnn_scatter<<<sblocks, 256>>>(gnn, ei, ew, x1p, E);
    gnn_scatter<<<sblocks, 256>>>(x1p, ei, ew, x2p, E);

    proj_kernel<<<(NN + 31) / 32, 256>>>(gnn, Wp, bp);
    fuse2_kernel<<<(SB * SQ + 7) / 8, 256>>>(seq, lens, bert, pos);

    xformer_kernel<<<SB, 256, SMEM_BYTES>>>(seq,
        wqkvh, woh, w1hp, b1, w2hp, b2, ln1g, ln1b, ln2g, ln2b);

    final_kernel<<<SB / 8, 256>>>(lens, lnfg, lnfb, out);
}

// round 9
// speedup vs baseline: 2.9098x; 1.1859x over previous
#include <cuda_runtime.h>
#include <cuda_fp16.h>
#include <math.h>

#define NN   100001
#define D    64
#define SB   1024
#define SQ   50
#define DFF  256
#define EMAX 1048576

// ---------------- scratch (no allocations allowed) ----------------
__device__ float g_x1[NN * D];
__device__ float g_x2[NN * D];
__device__ float g_proj[NN * D];
__device__ float g_xbuf[SB * SQ * D];
// CSR build scratch
__device__ int   g_cnt[NN];
__device__ int   g_scanned[NN];
__device__ int   g_bsum[128];
__device__ int   g_boff[128];
__device__ int   g_rowptr[NN];
__device__ int   g_cursor[NN];
__device__ int   g_csrc[EMAX];
__device__ float g_cw[EMAX];
// fp16 packed weights (written once per launch by prep_kernel)
__device__ __align__(16) __half g_wph[4096];
__device__ __align__(16) __half g_wqkvh[2 * 64 * 192];
__device__ __align__(16) __half g_woh[2 * 4096];
__device__ __align__(16) __half g_w1h[2 * 16384];
__device__ __align__(16) __half g_w2h[2 * 16384];

// ---------------- smem byte offsets for xformer (total 75520) -----
#define SO_XS   0        // f32[3200]          -> 12800
#define SO_AH   12800    // half[64][72]       -> 22016
#define SO_KM   22016    // f32[64]            -> 22272
#define SO_QH   22272    // half[64][72]       -> 31488
#define SO_KH   31488    // half[64][72]       -> 40704
#define SO_PH   22272    // half[2][64][72]    (overlays QH+KH, dead)
#define SO_VH   40704    // half[64][72]       -> 49920
#define SO_WST  49920    // half[64][200]      -> 75520 (WQKV stage)
#define SO_SS   49920    // f32[2][50][52]     -> 70720 (overlay WST, dead)
#define SO_Y    49920    // f32[50][66]        -> 63120 (overlay SS, dead)
#define SO_WOST 63120    // half[64][72]       -> 72336
#define SO_W1C  22272    // half[64][136]      -> 39680 (FFN, PH dead)
#define SO_H1C  39680    // half[64][136]      -> 57088
#define SO_W2C  57088    // half[128][72]      -> 75520
#define SO_Y2   22272    // f32[50][66]        (after W1C dead)
#define SMEM_BYTES 75520

__device__ __forceinline__ float wsum(float v) {
#pragma unroll
    for (int o = 16; o > 0; o >>= 1) v += __shfl_xor_sync(0xffffffffu, v, o);
    return v;
}
__device__ __forceinline__ float wmax(float v) {
#pragma unroll
    for (int o = 16; o > 0; o >>= 1) v = fmaxf(v, __shfl_xor_sync(0xffffffffu, v, o));
    return v;
}
__device__ __forceinline__ float gelu_f(float x) {
    float inner = 0.7978845608028654f * (x + 0.044715f * x * x * x);
    return 0.5f * x * (1.0f + tanhf(inner));
}

// ---------------- mma helpers ----------------
__device__ __forceinline__ void ldsm_x4(unsigned &r0, unsigned &r1, unsigned &r2, unsigned &r3, unsigned addr) {
    asm volatile("ldmatrix.sync.aligned.m8n8.x4.shared.b16 {%0,%1,%2,%3}, [%4];"
                 : "=r"(r0), "=r"(r1), "=r"(r2), "=r"(r3) : "r"(addr));
}
__device__ __forceinline__ void ldsm_x4_t(unsigned &r0, unsigned &r1, unsigned &r2, unsigned &r3, unsigned addr) {
    asm volatile("ldmatrix.sync.aligned.m8n8.x4.trans.shared.b16 {%0,%1,%2,%3}, [%4];"
                 : "=r"(r0), "=r"(r1), "=r"(r2), "=r"(r3) : "r"(addr));
}
__device__ __forceinline__ void mma16816(float c[4], unsigned a0, unsigned a1, unsigned a2, unsigned a3,
                                         unsigned b0, unsigned b1) {
    asm volatile("mma.sync.aligned.m16n8k16.row.col.f32.f16.f16.f32 "
                 "{%0,%1,%2,%3}, {%4,%5,%6,%7}, {%8,%9}, {%0,%1,%2,%3};"
                 : "+f"(c[0]), "+f"(c[1]), "+f"(c[2]), "+f"(c[3])
                 : "r"(a0), "r"(a1), "r"(a2), "r"(a3), "r"(b0), "r"(b1));
}

// warp computes 16x32 tile. A row-major [m][k] read starting at column k0;
// B stored [k][n] row-major in a LOCAL buffer (rows 0..16*KT-1), trans ldmatrix.
// k0 applies ONLY to the A side.
__device__ __forceinline__ void mma_block(const __half* Ah, int lda, int k0,
                                          const __half* Bh, int ldb, int n0,
                                          int m0, int KT, float acc[4][4]) {
    int lane = threadIdx.x & 31;
    unsigned abase = (unsigned)__cvta_generic_to_shared(Ah) +
                     (unsigned)(((m0 + (lane & 15)) * lda + k0 + ((lane >> 4) * 8)) * 2);
    unsigned bbase = (unsigned)__cvta_generic_to_shared(Bh);
    int brow = lane & 15;
    int bcol8 = (lane >> 4) * 8;
    for (int kt = 0; kt < KT; kt++) {
        unsigned a0, a1, a2, a3;
        ldsm_x4(a0, a1, a2, a3, abase + kt * 32);
#pragma unroll
        for (int ns = 0; ns < 2; ns++) {
            unsigned baddr = bbase + (unsigned)(((kt * 16 + brow) * ldb + n0 + ns * 16 + bcol8) * 2);
            unsigned b0, b1, b2, b3;
            ldsm_x4_t(b0, b1, b2, b3, baddr);
            mma16816(acc[ns * 2 + 0], a0, a1, a2, a3, b0, b1);
            mma16816(acc[ns * 2 + 1], a0, a1, a2, a3, b2, b3);
        }
    }
}

// scores: A = Qh [m][72] at k-cols h*32..; B = Kh [n][72] row-major (non-trans ldmatrix)
__device__ __forceinline__ void score_mma(float acc[4][4], const __half* Qh, const __half* Kh,
                                          int h, int m0, int n0, int lane) {
    unsigned abase = (unsigned)__cvta_generic_to_shared(Qh) +
                     (unsigned)(((m0 + (lane & 15)) * 72 + h * 32 + ((lane >> 4) * 8)) * 2);
    unsigned kb = (unsigned)__cvta_generic_to_shared(Kh);
    int nbase = n0 + (lane & 7) + ((lane >= 16) ? 8 : 0);
    int koff = ((lane & 15) >= 8) ? 8 : 0;
    for (int kt = 0; kt < 2; kt++) {
        unsigned a0, a1, a2, a3;
        ldsm_x4(a0, a1, a2, a3, abase + kt * 32);
#pragma unroll
        for (int ns = 0; ns < 2; ns++) {
            unsigned baddr = kb + (unsigned)(((nbase + ns * 16) * 72 + h * 32 + kt * 16 + koff) * 2);
            unsigned b0, b1, b2, b3;
            ldsm_x4(b0, b1, b2, b3, baddr);
            mma16816(acc[ns * 2 + 0], a0, a1, a2, a3, b0, b1);
            mma16816(acc[ns * 2 + 1], a0, a1, a2, a3, b2, b3);
        }
    }
}

// ---------------- prep: zero counts + convert/pack weights --------
__global__ void prep_kernel(const float* __restrict__ wp,
                            const float* __restrict__ wq, const float* __restrict__ wk,
                            const float* __restrict__ wv, const float* __restrict__ wo,
                            const float* __restrict__ w1, const float* __restrict__ w2)
{
    int i = blockIdx.x * blockDim.x + threadIdx.x;
    int st = gridDim.x * blockDim.x;
    for (int j = i; j < NN; j += st) g_cnt[j] = 0;
    for (int j = i; j < 4096; j += st) g_wph[j] = __float2half_rn(wp[j]);
    for (int j = i; j < 2 * 64 * 192; j += st) {
        int blk = j / (64 * 192), rem = j % (64 * 192);
        int k = rem / 192, n = rem % 192;
        const float* src = (n < 64) ? wq : (n < 128) ? wk : wv;
        g_wqkvh[j] = __float2half_rn(src[blk * 4096 + k * 64 + (n & 63)]);
    }
    for (int j = i; j < 2 * 4096; j += st)  g_woh[j] = __float2half_rn(wo[j]);
    for (int j = i; j < 2 * 16384; j += st) g_w1h[j] = __float2half_rn(w1[j]);
    for (int j = i; j < 2 * 16384; j += st) g_w2h[j] = __float2half_rn(w2[j]);
}

// ---------------- CSR build ----------------
__global__ void hist_kernel(const int* __restrict__ ei, int E) {
    int t = blockIdx.x * blockDim.x + threadIdx.x;
    if (t < E) atomicAdd(&g_cnt[ei[E + t]], 1);
}

// block=256 threads, 1024 elems/block: exclusive scan within block + block sums
__global__ void scan1_kernel() {
    __shared__ int wsums[8];
    int tid = threadIdx.x;
    int base = blockIdx.x * 1024 + tid * 4;
    int c[4]; int s = 0;
#pragma unroll
    for (int j = 0; j < 4; j++) {
        int idx = base + j;
        c[j] = (idx < NN) ? g_cnt[idx] : 0;
        s += c[j];
    }
    int lane = tid & 31, wid = tid >> 5;
    int v = s;
#pragma unroll
    for (int o = 1; o < 32; o <<= 1) { int u = __shfl_up_sync(0xffffffffu, v, o); if (lane >= o) v += u; }
    if (lane == 31) wsums[wid] = v;
    __syncthreads();
    if (wid == 0) {
        int wv = (lane < 8) ? wsums[lane] : 0;
#pragma unroll
        for (int o = 1; o < 8; o <<= 1) { int u = __shfl_up_sync(0xffffffffu, wv, o); if (lane >= o) wv += u; }
        if (lane < 8) wsums[lane] = wv;
    }
    __syncthreads();
    int excl = v - s + ((wid > 0) ? wsums[wid - 1] : 0);
    int run = excl;
#pragma unroll
    for (int j = 0; j < 4; j++) {
        int idx = base + j;
        if (idx < NN) g_scanned[idx] = run;
        run += c[j];
    }
    if (tid == 255) g_bsum[blockIdx.x] = run;
}

// single block scans the (<=128) block sums exclusively
__global__ void scan2_kernel(int nblk) {
    __shared__ int ws[4];
    int tid = threadIdx.x;
    int orig = (tid < nblk) ? g_bsum[tid] : 0;
    int v = orig;
    int lane = tid & 31, wid = tid >> 5;
#pragma unroll
    for (int o = 1; o < 32; o <<= 1) { int u = __shfl_up_sync(0xffffffffu, v, o); if (lane >= o) v += u; }
    if (lane == 31) ws[wid] = v;
    __syncthreads();
    int add = 0;
    for (int k = 0; k < wid; k++) add += ws[k];
    if (tid < nblk) g_boff[tid] = v + add - orig;
}

__global__ void scan3_kernel() {
    int idx = blockIdx.x * blockDim.x + threadIdx.x;
    if (idx < NN) {
        int v = g_scanned[idx] + g_boff[idx >> 10];
        g_rowptr[idx] = v;
        g_cursor[idx] = v;
    }
}

__global__ void reorder_kernel(const int* __restrict__ ei, const float* __restrict__ ew, int E) {
    int t = blockIdx.x * blockDim.x + threadIdx.x;
    if (t >= E) return;
    int src = ei[t];
    int dst = ei[E + t];
    int pos = atomicAdd(&g_cursor[dst], 1);
    g_csrc[pos] = src;
    g_cw[pos] = ew[t];
}

// ---------------- aggregation: xout[n] = sum_j w_j * xin[src_j] ---
__global__ void __launch_bounds__(256) agg_kernel(
    const float* __restrict__ xin, float* __restrict__ xout)
{
    int node = blockIdx.x * 8 + (threadIdx.x >> 5);
    if (node >= NN) return;
    int lane = threadIdx.x & 31;
    int beg = g_rowptr[node];
    int cnt = g_cnt[node];
    float a0 = 0.f, a1 = 0.f;
    for (int j = 0; j < cnt; j++) {
        int src = g_csrc[beg + j];
        float w = g_cw[beg + j];
        const float* xr = xin + (size_t)src * D;
        a0 += w * xr[lane];
        a1 += w * xr[32 + lane];
    }
    xout[(size_t)node * D + lane]      = a0;
    xout[(size_t)node * D + 32 + lane] = a1;
}

// ---------------- proj (MMA): g_proj = ((gnn+x1+x2)/3) @ Wp + bp --
__global__ void __launch_bounds__(256) proj_kernel(
    const float* __restrict__ gnn_emb, const float* __restrict__ bp)
{
    __shared__ __align__(16) __half Ah[64 * 72];
    __shared__ __align__(16) __half Wps[64 * 72];
    int tid = threadIdx.x;
    int lane = tid & 31, w = tid >> 5;
    int rbase = blockIdx.x * 64;

    for (int i = tid; i < 512; i += 256) {
        uint4 u = ((const uint4*)g_wph)[i];
        int row = i >> 3, c = (i & 7) * 8;
        *(uint4*)(Wps + row * 72 + c) = u;
    }
    for (int i = tid; i < 2048; i += 256) {
        int row = i >> 5, c2 = i & 31;
        int g = rbase + row;
        __half2 hv;
        if (g < NN) {
            size_t o = (size_t)g * D + c2 * 2;
            float2 ga = *(const float2*)(gnn_emb + o);
            float2 xa = *(const float2*)(g_x1 + o);
            float2 xb = *(const float2*)(g_x2 + o);
            hv = __floats2half2_rn((ga.x + xa.x + xb.x) * (1.0f / 3.0f),
                                   (ga.y + xa.y + xb.y) * (1.0f / 3.0f));
        } else {
            hv = __floats2half2_rn(0.f, 0.f);
        }
        *(__half2*)(Ah + row * 72 + c2 * 2) = hv;
    }
    __syncthreads();

    int m0 = (w & 3) * 16;
    int n0 = (w >> 2) * 32;
    float acc[4][4] = {};
    mma_block(Ah, 72, 0, Wps, 72, n0, m0, 4, acc);
    int r = m0 + (lane >> 2);
    int cb = (lane & 3) * 2;
#pragma unroll
    for (int t = 0; t < 4; t++) {
        int c = n0 + t * 8 + cb;
        float bb0 = bp[c], bb1 = bp[c + 1];
        int g0 = rbase + r, g1 = rbase + r + 8;
        if (g0 < NN) *(float2*)(g_proj + (size_t)g0 * D + c) = make_float2(acc[t][0] + bb0, acc[t][1] + bb1);
        if (g1 < NN) *(float2*)(g_proj + (size_t)g1 * D + c) = make_float2(acc[t][2] + bb0, acc[t][3] + bb1);
    }
}

// ---------------- fuse2: gather bert/proj, blend, add pos ---------
__global__ void __launch_bounds__(256) fuse2_kernel(
    const int* __restrict__ seq, const int* __restrict__ lengths,
    const float* __restrict__ bert, const float* __restrict__ pos)
{
    int row = blockIdx.x * 8 + (threadIdx.x >> 5);
    if (row >= SB * SQ) return;
    int lane = threadIdx.x & 31;
    int b = row / SQ, s = row - b * SQ;
    int idx = seq[row];
    int len = lengths[b];
    float alpha = (len <= 10) ? 0.3f : ((len >= 50) ? 0.7f : 0.5f);
    float beta = 1.0f - alpha;
    size_t o = (size_t)idx * D;
    g_xbuf[row * D + lane]      = alpha * bert[o + lane]      + beta * g_proj[o + lane]      + pos[s * D + lane];
    g_xbuf[row * D + 32 + lane] = alpha * bert[o + 32 + lane] + beta * g_proj[o + 32 + lane] + pos[s * D + 32 + lane];
}

// ---------------- transformer helpers ----------------
__device__ __forceinline__ void build_Ah(__half* Ah, const float* xs, int tid) {
    for (int i = tid; i < 64 * 32; i += 256) {
        int row = i >> 5, c2 = i & 31;
        __half2 hv;
        if (row < 50) {
            float2 xv = *(const float2*)(xs + row * 64 + c2 * 2);
            hv = __floats2half2_rn(xv.x, xv.y);
        } else {
            hv = __floats2half2_rn(0.f, 0.f);
        }
        *(__half2*)(Ah + row * 72 + c2 * 2) = hv;
    }
}

__device__ __forceinline__ void epi_h16(__half* dst, float acc[4][4], int m0, int n0, int lane) {
    int r = m0 + (lane >> 2);
    int cb = (lane & 3) * 2;
#pragma unroll
    for (int t = 0; t < 4; t++) {
        int c = n0 + t * 8 + cb;
        *(__half2*)(dst + r * 72 + c)       = __floats2half2_rn(acc[t][0], acc[t][1]);
        *(__half2*)(dst + (r + 8) * 72 + c) = __floats2half2_rn(acc[t][2], acc[t][3]);
    }
}

__device__ __forceinline__ void epi_store66(float* dst, float acc[4][4], int m0, int n0, int lane) {
    int r = m0 + (lane >> 2);
    int cb = (lane & 3) * 2;
#pragma unroll
    for (int t = 0; t < 4; t++) {
        int c = n0 + t * 8 + cb;
        if (r < 50)     *(float2*)(dst + r * 66 + c)       = make_float2(acc[t][0], acc[t][1]);
        if (r + 8 < 50) *(float2*)(dst + (r + 8) * 66 + c) = make_float2(acc[t][2], acc[t][3]);
    }
}

__device__ __forceinline__ void ln_add(float* __restrict__ xs,
                                       const float* __restrict__ y,
                                       const float* __restrict__ g,
                                       const float* __restrict__ bta, int tid)
{
    int lane = tid & 31, w = tid >> 5;
    for (int r = w; r < 50; r += 8) {
        float v0 = xs[r * 64 + lane]      + y[r * 66 + lane];
        float v1 = xs[r * 64 + 32 + lane] + y[r * 66 + 32 + lane];
        float mean = wsum(v0 + v1) * (1.0f / 64.0f);
        float d0 = v0 - mean, d1 = v1 - mean;
        float var = wsum(d0 * d0 + d1 * d1) * (1.0f / 64.0f);
        float inv = 1.0f / sqrtf(var + 1e-5f);
        xs[r * 64 + lane]      = d0 * inv * g[lane]      + bta[lane];
        xs[r * 64 + 32 + lane] = d1 * inv * g[32 + lane] + bta[32 + lane];
    }
}

// -------- both transformer blocks, CTA per batch row --------------
__global__ void __launch_bounds__(256) xformer_kernel(
    const int* __restrict__ seq,
    const __half* __restrict__ wqkvh_all, const __half* __restrict__ woh_all,
    const __half* __restrict__ w1h_all, const float* __restrict__ b1_all,
    const __half* __restrict__ w2h_all, const float* __restrict__ b2_all,
    const float* __restrict__ ln1g_all, const float* __restrict__ ln1b_all,
    const float* __restrict__ ln2g_all, const float* __restrict__ ln2b_all)
{
    extern __shared__ char smraw[];
    int tid = threadIdx.x;
    int lane = tid & 31, w = tid >> 5;
    int b = blockIdx.x;
    float* xg = g_xbuf + (size_t)b * SQ * D;

    float*  xs  = (float*)(smraw + SO_XS);
    __half* Ah  = (__half*)(smraw + SO_AH);
    float*  km  = (float*)(smraw + SO_KM);
    __half* Qh  = (__half*)(smraw + SO_QH);
    __half* Kh  = (__half*)(smraw + SO_KH);
    __half* Ph  = (__half*)(smraw + SO_PH);
    __half* Vh  = (__half*)(smraw + SO_VH);
    __half* Wst = (__half*)(smraw + SO_WST);
    float*  Ssm = (float*)(smraw + SO_SS);
    float*  y   = (float*)(smraw + SO_Y);
    __half* Wos = (__half*)(smraw + SO_WOST);
    __half* W1c = (__half*)(smraw + SO_W1C);
    __half* H1c = (__half*)(smraw + SO_H1C);
    __half* W2c = (__half*)(smraw + SO_W2C);
    float*  y2  = (float*)(smraw + SO_Y2);

    int m0 = (w & 3) * 16;
    int n0 = (w >> 2) * 32;

    for (int i = tid; i < 3200; i += 256) xs[i] = xg[i];
    if (tid < 64) km[tid] = (tid < 50) ? ((seq[b * SQ + tid] != 0) ? 0.f : 1.f) : 2.f;
    __syncthreads();

    for (int blk = 0; blk < 2; blk++) {
        const __half* wqkvh = wqkvh_all + blk * 12288;
        const __half* woh   = woh_all   + blk * 4096;
        const __half* w1h   = w1h_all   + blk * 16384;
        const float*  b1    = b1_all    + blk * 256;
        const __half* w2h   = w2h_all   + blk * 16384;
        const float*  b2    = b2_all    + blk * 64;
        const float*  ln1g  = ln1g_all  + blk * 64;
        const float*  ln1b  = ln1b_all  + blk * 64;
        const float*  ln2g  = ln2g_all  + blk * 64;
        const float*  ln2b  = ln2b_all  + blk * 64;

        build_Ah(Ah, xs, tid);
        for (int i = tid; i < 1536; i += 256) {
            uint4 u = ((const uint4*)wqkvh)[i];
            int row = i / 24, c = (i % 24) * 8;
            *(uint4*)(Wst + row * 200 + c) = u;
        }
        __syncthreads();

#pragma unroll
        for (int ng = 0; ng < 3; ng++) {
            float acc[4][4] = {};
            mma_block(Ah, 72, 0, Wst, 200, ng * 64 + n0, m0, 4, acc);
            __half* dst = (ng == 0) ? Qh : (ng == 1) ? Kh : Vh;
            epi_h16(dst, acc, m0, n0, lane);
        }
        __syncthreads();

#pragma unroll
        for (int h = 0; h < 2; h++) {
            float acc[4][4] = {};
            score_mma(acc, Qh, Kh, h, m0, n0, lane);
            int r = m0 + (lane >> 2);
            int cb = (lane & 3) * 2;
            float* S = Ssm + h * 2600;
#pragma unroll
            for (int t = 0; t < 4; t++) {
                int c = n0 + t * 8 + cb;
                if (r < 50) {
                    if (c < 50)     S[r * 52 + c]     = acc[t][0];
                    if (c + 1 < 50) S[r * 52 + c + 1] = acc[t][1];
                }
                if (r + 8 < 50) {
                    if (c < 50)     S[(r + 8) * 52 + c]     = acc[t][2];
                    if (c + 1 < 50) S[(r + 8) * 52 + c + 1] = acc[t][3];
                }
            }
        }
        __syncthreads();

        {
            const float scale = 0.17677669529663687f; // 1/sqrt(32)
            for (int idx = w; idx < 128; idx += 8) {
                int h = idx >> 6, r = idx & 63;
                __half* prow = Ph + h * 4608 + r * 72;
                if (r >= 50) {
                    *(__half2*)(prow + lane * 2) = __floats2half2_rn(0.f, 0.f);
                } else {
                    const float* S = Ssm + h * 2600 + r * 52;
                    float f0 = km[lane], f1 = km[lane + 32];
                    float raw0 = S[lane];
                    float raw1 = S[(lane + 32 < 50) ? lane + 32 : 0];
                    float s0 = (f0 == 0.f) ? raw0 * scale : -1e9f;
                    float s1 = (f1 == 0.f) ? raw1 * scale : ((f1 == 1.f) ? -1e9f : -INFINITY);
                    float m = wmax(fmaxf(s0, s1));
                    float e0 = expf(s0 - m);
                    float e1 = expf(s1 - m);
                    float inv = 1.0f / wsum(e0 + e1);
                    prow[lane]      = __float2half_rn(e0 * inv);
                    prow[lane + 32] = __float2half_rn(e1 * inv);
                }
            }
        }
        __syncthreads();

        {
            int h = w >> 2, mm = (w & 3) * 16;
            float acc[4][4] = {};
            mma_block(Ph + h * 4608, 72, 0, Vh, 72, h * 32, mm, 4, acc);
            int r = mm + (lane >> 2);
            int cb = (lane & 3) * 2;
#pragma unroll
            for (int t = 0; t < 4; t++) {
                int c = h * 32 + t * 8 + cb;
                *(__half2*)(Ah + r * 72 + c)       = __floats2half2_rn(acc[t][0], acc[t][1]);
                *(__half2*)(Ah + (r + 8) * 72 + c) = __floats2half2_rn(acc[t][2], acc[t][3]);
            }
        }
        for (int i = tid; i < 512; i += 256) {
            uint4 u = ((const uint4*)woh)[i];
            int row = i >> 3, c = (i & 7) * 8;
            *(uint4*)(Wos + row * 72 + c) = u;
        }
        __syncthreads();

        {
            float acc[4][4] = {};
            mma_block(Ah, 72, 0, Wos, 72, n0, m0, 4, acc);
            epi_store66(y, acc, m0, n0, lane);
        }
        __syncthreads();
        ln_add(xs, y, ln1g, ln1b, tid);
        __syncthreads();

        build_Ah(Ah, xs, tid);
        {
            float acc[4][4] = {};
            for (int ch = 0; ch < 2; ch++) {
                for (int i = tid; i < 1024; i += 256) {
                    int row = i >> 4, j = i & 15;
                    uint4 u = ((const uint4*)w1h)[row * 32 + ch * 16 + j];
                    *(uint4*)(W1c + row * 136 + j * 8) = u;
                }
                for (int i = tid; i < 1024; i += 256) {
                    uint4 u = ((const uint4*)w2h)[ch * 1024 + i];
                    int row = i >> 3, c = (i & 7) * 8;
                    *(uint4*)(W2c + row * 72 + c) = u;
                }
                __syncthreads();
#pragma unroll
                for (int ng = 0; ng < 2; ng++) {
                    float a1[4][4] = {};
                    mma_block(Ah, 72, 0, W1c, 136, ng * 64 + n0, m0, 4, a1);
                    int r = m0 + (lane >> 2);
                    int cb = (lane & 3) * 2;
#pragma unroll
                    for (int t = 0; t < 4; t++) {
                        int cl = ng * 64 + n0 + t * 8 + cb;
                        int cg = ch * 128 + cl;
                        float bb0 = b1[cg], bb1 = b1[cg + 1];
                        *(__half2*)(H1c + r * 136 + cl) =
                            __floats2half2_rn(gelu_f(a1[t][0] + bb0), gelu_f(a1[t][1] + bb1));
                        *(__half2*)(H1c + (r + 8) * 136 + cl) =
                            __floats2half2_rn(gelu_f(a1[t][2] + bb0), gelu_f(a1[t][3] + bb1));
                    }
                }
                __syncthreads();
                mma_block(H1c, 136, 0, W2c, 72, n0, m0, 8, acc);
                __syncthreads();
            }
            int r = m0 + (lane >> 2);
            int cb = (lane & 3) * 2;
#pragma unroll
            for (int t = 0; t < 4; t++) {
                int c = n0 + t * 8 + cb;
                float bb0 = b2[c], bb1 = b2[c + 1];
                if (r < 50)     *(float2*)(y2 + r * 66 + c)       = make_float2(acc[t][0] + bb0, acc[t][1] + bb1);
                if (r + 8 < 50) *(float2*)(y2 + (r + 8) * 66 + c) = make_float2(acc[t][2] + bb0, acc[t][3] + bb1);
            }
        }
        __syncthreads();
        ln_add(xs, y2, ln2g, ln2b, tid);
        __syncthreads();
    }

    for (int i = tid; i < 3200; i += 256) xg[i] = xs[i];
}

// ---------------- final LN + gather -------------------------------
__global__ void __launch_bounds__(256) final_kernel(
    const int* __restrict__ lengths, const float* __restrict__ g,
    const float* __restrict__ bt, float* __restrict__ out)
{
    int b = blockIdx.x * 8 + (threadIdx.x >> 5);
    if (b >= SB) return;
    int lane = threadIdx.x & 31;
    int r = lengths[b] - 1;
    const float* row = g_xbuf + ((size_t)b * SQ + r) * D;
    float v0 = row[lane], v1 = row[lane + 32];
    float mean = wsum(v0 + v1) * (1.0f / 64.0f);
    float d0 = v0 - mean, d1 = v1 - mean;
    float var = wsum(d0 * d0 + d1 * d1) * (1.0f / 64.0f);
    float inv = 1.0f / sqrtf(var + 1e-5f);
    out[b * D + lane]      = d0 * inv * g[lane]      + bt[lane];
    out[b * D + 32 + lane] = d1 * inv * g[lane + 32] + bt[lane + 32];
}

// ---------------- launch -------------------------------------------
extern "C" void kernel_launch(void* const* d_in, const int* in_sizes, int n_in,
                              void* d_out, int out_size)
{
    const int*   seq  = (const int*)d_in[0];
    const int*   lens = (const int*)d_in[1];
    const int*   ei   = (const int*)d_in[2];
    const float* ew   = (const float*)d_in[3];
    const float* bert = (const float*)d_in[4];
    const float* gnn  = (const float*)d_in[5];
    const float* Wp   = (const float*)d_in[6];
    const float* bp   = (const float*)d_in[7];
    const float* pos  = (const float*)d_in[8];
    const float* wq   = (const float*)d_in[9];
    const float* wk   = (const float*)d_in[10];
    const float* wv   = (const float*)d_in[11];
    const float* wo   = (const float*)d_in[12];
    const float* w1   = (const float*)d_in[13];
    const float* b1   = (const float*)d_in[14];
    const float* w2   = (const float*)d_in[15];
    const float* b2   = (const float*)d_in[16];
    const float* ln1g = (const float*)d_in[17];
    const float* ln1b = (const float*)d_in[18];
    const float* ln2g = (const float*)d_in[19];
    const float* ln2b = (const float*)d_in[20];
    const float* lnfg = (const float*)d_in[21];
    const float* lnfb = (const float*)d_in[22];
    float* out = (float*)d_out;
    int E = in_sizes[3];

    cudaFuncSetAttribute(xformer_kernel,
                         cudaFuncAttributeMaxDynamicSharedMemorySize, SMEM_BYTES);

    float *x1p = nullptr, *x2p = nullptr;
    __half *wqkvh, *woh, *w1hp, *w2hp;
    cudaGetSymbolAddress((void**)&x1p, g_x1);
    cudaGetSymbolAddress((void**)&x2p, g_x2);
    cudaGetSymbolAddress((void**)&wqkvh, g_wqkvh);
    cudaGetSymbolAddress((void**)&woh, g_woh);
    cudaGetSymbolAddress((void**)&w1hp, g_w1h);
    cudaGetSymbolAddress((void**)&w2hp, g_w2h);

    prep_kernel<<<1024, 256>>>(Wp, wq, wk, wv, wo, w1, w2);

    // CSR build
    hist_kernel<<<(E + 255) / 256, 256>>>(ei, E);
    scan1_kernel<<<(NN + 1023) / 1024, 256>>>();
    scan2_kernel<<<1, 128>>>((NN + 1023) / 1024);
    scan3_kernel<<<(NN + 255) / 256, 256>>>();
    reorder_kernel<<<(E + 255) / 256, 256>>>(ei, ew, E);

    // two GNN layers via gather-aggregate
    agg_kernel<<<(NN + 7) / 8, 256>>>(gnn, x1p);
    agg_kernel<<<(NN + 7) / 8, 256>>>(x1p, x2p);

    proj_kernel<<<(NN + 63) / 64, 256>>>(gnn, bp);
    fuse2_kernel<<<(SB * SQ + 7) / 8, 256>>>(seq, lens, bert, pos);

    xformer_kernel<<<SB, 256, SMEM_BYTES>>>(seq,
        wqkvh, woh, w1hp, b1, w2hp, b2, ln1g, ln1b, ln2g, ln2b);

    final_kernel<<<SB / 8, 256>>>(lens, lnfg, lnfb, out);
}

// round 12
// speedup vs baseline: 3.1966x; 1.0986x over previous
#include <cuda_runtime.h>
#include <cuda_fp16.h>
#include <math.h>

#define NN   100001
#define D    64
#define SB   1024
#define SQ   50
#define DFF  256
#define EMAX 1048576

// ---------------- scratch (no allocations allowed) ----------------
__device__ __align__(8) __half2 g_gnnh[NN * 32];
__device__ __align__(8) __half2 g_x1h[NN * 32];
__device__ __align__(8) __half2 g_x2h[NN * 32];
// CSR build scratch
__device__ int   g_cnt[NN];
__device__ int   g_scanned[NN];
__device__ int   g_bsum[128];
__device__ int   g_rowptr[NN];
__device__ int   g_cursor[NN];
__device__ int   g_csrc[EMAX];
__device__ float g_cw[EMAX];
// fp16 packed weights (written once per launch by prep_kernel)
__device__ __align__(16) __half g_wph[4096];
__device__ __align__(16) __half g_wqkvh[2 * 64 * 192];
__device__ __align__(16) __half g_woh[2 * 4096];
__device__ __align__(16) __half g_w1h[2 * 16384];
__device__ __align__(16) __half g_w2h[2 * 16384];

// ---------------- smem byte offsets for xformer -------------------
#define SO_XS   0        // f32[3200]          -> 12800
#define SO_AH   12800    // half[64][72]       -> 22016
#define SO_KM   22016    // f32[64]            -> 22272
#define SO_QH   22272    // half[64][72]       -> 31488
#define SO_KH   31488    // half[64][72]       -> 40704
#define SO_PH   22272    // half[2][64][72]    (overlays QH+KH, dead)
#define SO_VH   40704    // half[64][72]       -> 49920
#define SO_WST  49920    // half[64][200]      -> 75520 (WQKV stage)
#define SO_SS   49920    // f32[2][50][52]     -> 70720 (overlay WST, dead)
#define SO_Y    49920    // f32[50][66]        -> 63120 (overlay SS, dead)
#define SO_WOST 63120    // half[64][72]       -> 72336
#define SO_W1C  22272    // half[64][136]      -> 39680 (FFN, PH dead)
#define SO_H1C  39680    // half[64][136]      -> 57088
#define SO_W2C  57088    // half[128][72]      -> 75520
#define SO_Y2   22272    // f32[50][66]        (after W1C dead)
#define SO_SEQ  75520    // int[64]            -> 75776
#define SMEM_BYTES 75776

__device__ __forceinline__ float wsum(float v) {
#pragma unroll
    for (int o = 16; o > 0; o >>= 1) v += __shfl_xor_sync(0xffffffffu, v, o);
    return v;
}
__device__ __forceinline__ int wsumi(int v) {
#pragma unroll
    for (int o = 16; o > 0; o >>= 1) v += __shfl_xor_sync(0xffffffffu, v, o);
    return v;
}
__device__ __forceinline__ float wmax(float v) {
#pragma unroll
    for (int o = 16; o > 0; o >>= 1) v = fmaxf(v, __shfl_xor_sync(0xffffffffu, v, o));
    return v;
}
__device__ __forceinline__ float gelu_f(float x) {
    float inner = 0.7978845608028654f * (x + 0.044715f * x * x * x);
    return 0.5f * x * (1.0f + tanhf(inner));
}

// ---------------- mma helpers ----------------
__device__ __forceinline__ void ldsm_x4(unsigned &r0, unsigned &r1, unsigned &r2, unsigned &r3, unsigned addr) {
    asm volatile("ldmatrix.sync.aligned.m8n8.x4.shared.b16 {%0,%1,%2,%3}, [%4];"
                 : "=r"(r0), "=r"(r1), "=r"(r2), "=r"(r3) : "r"(addr));
}
__device__ __forceinline__ void ldsm_x4_t(unsigned &r0, unsigned &r1, unsigned &r2, unsigned &r3, unsigned addr) {
    asm volatile("ldmatrix.sync.aligned.m8n8.x4.trans.shared.b16 {%0,%1,%2,%3}, [%4];"
                 : "=r"(r0), "=r"(r1), "=r"(r2), "=r"(r3) : "r"(addr));
}
__device__ __forceinline__ void mma16816(float c[4], unsigned a0, unsigned a1, unsigned a2, unsigned a3,
                                         unsigned b0, unsigned b1) {
    asm volatile("mma.sync.aligned.m16n8k16.row.col.f32.f16.f16.f32 "
                 "{%0,%1,%2,%3}, {%4,%5,%6,%7}, {%8,%9}, {%0,%1,%2,%3};"
                 : "+f"(c[0]), "+f"(c[1]), "+f"(c[2]), "+f"(c[3])
                 : "r"(a0), "r"(a1), "r"(a2), "r"(a3), "r"(b0), "r"(b1));
}

// warp computes 16x32 tile. A row-major [m][k] read starting at column k0;
// B stored [k][n] row-major in a LOCAL buffer (rows 0..16*KT-1), trans ldmatrix.
// k0 applies ONLY to the A side.
__device__ __forceinline__ void mma_block(const __half* Ah, int lda, int k0,
                                          const __half* Bh, int ldb, int n0,
                                          int m0, int KT, float acc[4][4]) {
    int lane = threadIdx.x & 31;
    unsigned abase = (unsigned)__cvta_generic_to_shared(Ah) +
                     (unsigned)(((m0 + (lane & 15)) * lda + k0 + ((lane >> 4) * 8)) * 2);
    unsigned bbase = (unsigned)__cvta_generic_to_shared(Bh);
    int brow = lane & 15;
    int bcol8 = (lane >> 4) * 8;
    for (int kt = 0; kt < KT; kt++) {
        unsigned a0, a1, a2, a3;
        ldsm_x4(a0, a1, a2, a3, abase + kt * 32);
#pragma unroll
        for (int ns = 0; ns < 2; ns++) {
            unsigned baddr = bbase + (unsigned)(((kt * 16 + brow) * ldb + n0 + ns * 16 + bcol8) * 2);
            unsigned b0, b1, b2, b3;
            ldsm_x4_t(b0, b1, b2, b3, baddr);
            mma16816(acc[ns * 2 + 0], a0, a1, a2, a3, b0, b1);
            mma16816(acc[ns * 2 + 1], a0, a1, a2, a3, b2, b3);
        }
    }
}

// scores: A = Qh [m][72] at k-cols h*32..; B = Kh [n][72] row-major (non-trans ldmatrix)
__device__ __forceinline__ void score_mma(float acc[4][4], const __half* Qh, const __half* Kh,
                                          int h, int m0, int n0, int lane) {
    unsigned abase = (unsigned)__cvta_generic_to_shared(Qh) +
                     (unsigned)(((m0 + (lane & 15)) * 72 + h * 32 + ((lane >> 4) * 8)) * 2);
    unsigned kb = (unsigned)__cvta_generic_to_shared(Kh);
    int nbase = n0 + (lane & 7) + ((lane >= 16) ? 8 : 0);
    int koff = ((lane & 15) >= 8) ? 8 : 0;
    for (int kt = 0; kt < 2; kt++) {
        unsigned a0, a1, a2, a3;
        ldsm_x4(a0, a1, a2, a3, abase + kt * 32);
#pragma unroll
        for (int ns = 0; ns < 2; ns++) {
            unsigned baddr = kb + (unsigned)(((nbase + ns * 16) * 72 + h * 32 + kt * 16 + koff) * 2);
            unsigned b0, b1, b2, b3;
            ldsm_x4(b0, b1, b2, b3, baddr);
            mma16816(acc[ns * 2 + 0], a0, a1, a2, a3, b0, b1);
            mma16816(acc[ns * 2 + 1], a0, a1, a2, a3, b2, b3);
        }
    }
}

// ---------------- prep: zero counts + convert/pack weights + gnn --
__global__ void prep_kernel(const float* __restrict__ gnn, const float* __restrict__ wp,
                            const float* __restrict__ wq, const float* __restrict__ wk,
                            const float* __restrict__ wv, const float* __restrict__ wo,
                            const float* __restrict__ w1, const float* __restrict__ w2)
{
    int i = blockIdx.x * blockDim.x + threadIdx.x;
    int st = gridDim.x * blockDim.x;
    for (int j = i; j < NN; j += st) g_cnt[j] = 0;
    for (int j = i; j < NN * 32; j += st) {
        float2 v = ((const float2*)gnn)[j];
        g_gnnh[j] = __floats2half2_rn(v.x, v.y);
    }
    for (int j = i; j < 4096; j += st) g_wph[j] = __float2half_rn(wp[j]);
    for (int j = i; j < 2 * 64 * 192; j += st) {
        int blk = j / (64 * 192), rem = j % (64 * 192);
        int k = rem / 192, n = rem % 192;
        const float* src = (n < 64) ? wq : (n < 128) ? wk : wv;
        g_wqkvh[j] = __float2half_rn(src[blk * 4096 + k * 64 + (n & 63)]);
    }
    for (int j = i; j < 2 * 4096; j += st)  g_woh[j] = __float2half_rn(wo[j]);
    for (int j = i; j < 2 * 16384; j += st) g_w1h[j] = __float2half_rn(w1[j]);
    for (int j = i; j < 2 * 16384; j += st) g_w2h[j] = __float2half_rn(w2[j]);
}

// ---------------- CSR build ----------------
__global__ void hist_kernel(const int* __restrict__ ei, int E) {
    int t = blockIdx.x * blockDim.x + threadIdx.x;
    if (t < E) atomicAdd(&g_cnt[ei[E + t]], 1);
}

// block=256 threads, 1024 elems/block: exclusive scan within block + block sums
__global__ void scan1_kernel() {
    __shared__ int wsums[8];
    int tid = threadIdx.x;
    int base = blockIdx.x * 1024 + tid * 4;
    int c[4]; int s = 0;
#pragma unroll
    for (int j = 0; j < 4; j++) {
        int idx = base + j;
        c[j] = (idx < NN) ? g_cnt[idx] : 0;
        s += c[j];
    }
    int lane = tid & 31, wid = tid >> 5;
    int v = s;
#pragma unroll
    for (int o = 1; o < 32; o <<= 1) { int u = __shfl_up_sync(0xffffffffu, v, o); if (lane >= o) v += u; }
    if (lane == 31) wsums[wid] = v;
    __syncthreads();
    if (wid == 0) {
        int wv = (lane < 8) ? wsums[lane] : 0;
#pragma unroll
        for (int o = 1; o < 8; o <<= 1) { int u = __shfl_up_sync(0xffffffffu, wv, o); if (lane >= o) wv += u; }
        if (lane < 8) wsums[lane] = wv;
    }
    __syncthreads();
    int excl = v - s + ((wid > 0) ? wsums[wid - 1] : 0);
    int run = excl;
#pragma unroll
    for (int j = 0; j < 4; j++) {
        int idx = base + j;
        if (idx < NN) g_scanned[idx] = run;
        run += c[j];
    }
    if (tid == 255) g_bsum[blockIdx.x] = run;
}

// scan3 with inlined block-sum prefix (each block sums bsum[0..bucket))
__global__ void scan3_kernel() {
    __shared__ int boff_s;
    int tid = threadIdx.x;
    int bucket = blockIdx.x >> 2;   // 256-thread block lies inside one 1024-bucket
    if (tid < 32) {
        int s = 0;
        for (int k = tid; k < bucket; k += 32) s += g_bsum[k];
        s = wsumi(s);
        if (tid == 0) boff_s = s;
    }
    __syncthreads();
    int idx = blockIdx.x * 256 + tid;
    if (idx < NN) {
        int v = g_scanned[idx] + boff_s;
        g_rowptr[idx] = v;
        g_cursor[idx] = v;
    }
}

__global__ void reorder_kernel(const int* __restrict__ ei, const float* __restrict__ ew, int E) {
    int t = blockIdx.x * blockDim.x + threadIdx.x;
    if (t >= E) return;
    int src = ei[t];
    int dst = ei[E + t];
    int pos = atomicAdd(&g_cursor[dst], 1);
    g_csrc[pos] = src;
    g_cw[pos] = ew[t];
}

// ---------------- aggregation (half2 in, half2 out) ---------------
__global__ void __launch_bounds__(256) agg_kernel(
    const __half2* __restrict__ xin, __half2* __restrict__ xout)
{
    int node = blockIdx.x * 8 + (threadIdx.x >> 5);
    if (node >= NN) return;
    int lane = threadIdx.x & 31;
    int beg = g_rowptr[node];
    int cnt = g_cnt[node];
    float a0 = 0.f, a1 = 0.f;
    for (int j = 0; j < cnt; j++) {
        int src = g_csrc[beg + j];
        float w = g_cw[beg + j];
        float2 f = __half22float2(xin[(size_t)src * 32 + lane]);
        a0 += w * f.x;
        a1 += w * f.y;
    }
    xout[(size_t)node * 32 + lane] = __floats2half2_rn(a0, a1);
}

// ---------------- transformer helpers ----------------
__device__ __forceinline__ void build_Ah(__half* Ah, const float* xs, int tid) {
    for (int i = tid; i < 64 * 32; i += 256) {
        int row = i >> 5, c2 = i & 31;
        __half2 hv;
        if (row < 50) {
            float2 xv = *(const float2*)(xs + row * 64 + c2 * 2);
            hv = __floats2half2_rn(xv.x, xv.y);
        } else {
            hv = __floats2half2_rn(0.f, 0.f);
        }
        *(__half2*)(Ah + row * 72 + c2 * 2) = hv;
    }
}

__device__ __forceinline__ void epi_h16(__half* dst, float acc[4][4], int m0, int n0, int lane) {
    int r = m0 + (lane >> 2);
    int cb = (lane & 3) * 2;
#pragma unroll
    for (int t = 0; t < 4; t++) {
        int c = n0 + t * 8 + cb;
        *(__half2*)(dst + r * 72 + c)       = __floats2half2_rn(acc[t][0], acc[t][1]);
        *(__half2*)(dst + (r + 8) * 72 + c) = __floats2half2_rn(acc[t][2], acc[t][3]);
    }
}

__device__ __forceinline__ void epi_store66(float* dst, float acc[4][4], int m0, int n0, int lane) {
    int r = m0 + (lane >> 2);
    int cb = (lane & 3) * 2;
#pragma unroll
    for (int t = 0; t < 4; t++) {
        int c = n0 + t * 8 + cb;
        if (r < 50)     *(float2*)(dst + r * 66 + c)       = make_float2(acc[t][0], acc[t][1]);
        if (r + 8 < 50) *(float2*)(dst + (r + 8) * 66 + c) = make_float2(acc[t][2], acc[t][3]);
    }
}

__device__ __forceinline__ void ln_add(float* __restrict__ xs,
                                       const float* __restrict__ y,
                                       const float* __restrict__ g,
                                       const float* __restrict__ bta, int tid)
{
    int lane = tid & 31, w = tid >> 5;
    for (int r = w; r < 50; r += 8) {
        float v0 = xs[r * 64 + lane]      + y[r * 66 + lane];
        float v1 = xs[r * 64 + 32 + lane] + y[r * 66 + 32 + lane];
        float mean = wsum(v0 + v1) * (1.0f / 64.0f);
        float d0 = v0 - mean, d1 = v1 - mean;
        float var = wsum(d0 * d0 + d1 * d1) * (1.0f / 64.0f);
        float inv = 1.0f / sqrtf(var + 1e-5f);
        xs[r * 64 + lane]      = d0 * inv * g[lane]      + bta[lane];
        xs[r * 64 + 32 + lane] = d1 * inv * g[32 + lane] + bta[32 + lane];
    }
}

// -------- fused: proj + blend + 2 transformer blocks + final LN ---
__global__ void __launch_bounds__(256) xformer_kernel(
    const int* __restrict__ seq, const int* __restrict__ lens,
    const float* __restrict__ bert, const float* __restrict__ pos,
    const float* __restrict__ bp,
    const __half* __restrict__ wph,
    const __half* __restrict__ wqkvh_all, const __half* __restrict__ woh_all,
    const __half* __restrict__ w1h_all, const float* __restrict__ b1_all,
    const __half* __restrict__ w2h_all, const float* __restrict__ b2_all,
    const float* __restrict__ ln1g_all, const float* __restrict__ ln1b_all,
    const float* __restrict__ ln2g_all, const float* __restrict__ ln2b_all,
    const float* __restrict__ lnfg, const float* __restrict__ lnfb,
    float* __restrict__ out)
{
    extern __shared__ char smraw[];
    int tid = threadIdx.x;
    int lane = tid & 31, w = tid >> 5;
    int b = blockIdx.x;

    float*  xs  = (float*)(smraw + SO_XS);
    __half* Ah  = (__half*)(smraw + SO_AH);
    float*  km  = (float*)(smraw + SO_KM);
    __half* Qh  = (__half*)(smraw + SO_QH);
    __half* Kh  = (__half*)(smraw + SO_KH);
    __half* Ph  = (__half*)(smraw + SO_PH);
    __half* Vh  = (__half*)(smraw + SO_VH);
    __half* Wst = (__half*)(smraw + SO_WST);
    float*  Ssm = (float*)(smraw + SO_SS);
    float*  y   = (float*)(smraw + SO_Y);
    __half* Wos = (__half*)(smraw + SO_WOST);
    __half* W1c = (__half*)(smraw + SO_W1C);
    __half* H1c = (__half*)(smraw + SO_H1C);
    __half* W2c = (__half*)(smraw + SO_W2C);
    float*  y2  = (float*)(smraw + SO_Y2);
    int*    seqs = (int*)(smraw + SO_SEQ);

    int m0 = (w & 3) * 16;
    int n0 = (w >> 2) * 32;

    // ---- prologue: seq/mask, proj of this CTA's 50 nodes, blend ----
    if (tid < 64) {
        int sv = (tid < 50) ? seq[b * SQ + tid] : 0;
        seqs[tid] = sv;
        km[tid] = (tid < 50) ? ((sv != 0) ? 0.f : 1.f) : 2.f;
    }
    __syncthreads();
    // stage Wp -> Wos; build blend A -> Ah
    for (int i = tid; i < 512; i += 256) {
        uint4 u = ((const uint4*)wph)[i];
        int row = i >> 3, c = (i & 7) * 8;
        *(uint4*)(Wos + row * 72 + c) = u;
    }
    for (int i = tid; i < 2048; i += 256) {
        int row = i >> 5, c2 = i & 31;
        __half2 hv = __floats2half2_rn(0.f, 0.f);
        if (row < 50) {
            int idx = seqs[row];
            float2 gv = __half22float2(g_gnnh[(size_t)idx * 32 + c2]);
            float2 xa = __half22float2(g_x1h[(size_t)idx * 32 + c2]);
            float2 xb = __half22float2(g_x2h[(size_t)idx * 32 + c2]);
            hv = __floats2half2_rn((gv.x + xa.x + xb.x) * (1.0f / 3.0f),
                                   (gv.y + xa.y + xb.y) * (1.0f / 3.0f));
        }
        *(__half2*)(Ah + row * 72 + c2 * 2) = hv;
    }
    __syncthreads();
    // proj mma -> y [50][66] (y region disjoint from Wos)
    {
        float acc[4][4] = {};
        mma_block(Ah, 72, 0, Wos, 72, n0, m0, 4, acc);
        int r = m0 + (lane >> 2);
        int cb = (lane & 3) * 2;
#pragma unroll
        for (int t = 0; t < 4; t++) {
            int c = n0 + t * 8 + cb;
            float bb0 = bp[c], bb1 = bp[c + 1];
            if (r < 50)     *(float2*)(y + r * 66 + c)       = make_float2(acc[t][0] + bb0, acc[t][1] + bb1);
            if (r + 8 < 50) *(float2*)(y + (r + 8) * 66 + c) = make_float2(acc[t][2] + bb0, acc[t][3] + bb1);
        }
    }
    __syncthreads();
    // xs = alpha*bert + beta*proj + pos
    {
        int len = lens[b];
        float alpha = (len <= 10) ? 0.3f : ((len >= 50) ? 0.7f : 0.5f);
        float beta = 1.0f - alpha;
        for (int i = tid; i < 3200; i += 256) {
            int row = i >> 6, c = i & 63;
            int idx = seqs[row];
            xs[i] = alpha * bert[(size_t)idx * D + c] + beta * y[row * 66 + c] + pos[i];
        }
    }
    __syncthreads();

    // ---- two transformer blocks ----
    for (int blk = 0; blk < 2; blk++) {
        const __half* wqkvh = wqkvh_all + blk * 12288;
        const __half* woh   = woh_all   + blk * 4096;
        const __half* w1h   = w1h_all   + blk * 16384;
        const float*  b1    = b1_all    + blk * 256;
        const __half* w2h   = w2h_all   + blk * 16384;
        const float*  b2    = b2_all    + blk * 64;
        const float*  ln1g  = ln1g_all  + blk * 64;
        const float*  ln1b  = ln1b_all  + blk * 64;
        const float*  ln2g  = ln2g_all  + blk * 64;
        const float*  ln2b  = ln2b_all  + blk * 64;

        build_Ah(Ah, xs, tid);
        for (int i = tid; i < 1536; i += 256) {
            uint4 u = ((const uint4*)wqkvh)[i];
            int row = i / 24, c = (i % 24) * 8;
            *(uint4*)(Wst + row * 200 + c) = u;
        }
        __syncthreads();

#pragma unroll
        for (int ng = 0; ng < 3; ng++) {
            float acc[4][4] = {};
            mma_block(Ah, 72, 0, Wst, 200, ng * 64 + n0, m0, 4, acc);
            __half* dst = (ng == 0) ? Qh : (ng == 1) ? Kh : Vh;
            epi_h16(dst, acc, m0, n0, lane);
        }
        __syncthreads();

#pragma unroll
        for (int h = 0; h < 2; h++) {
            float acc[4][4] = {};
            score_mma(acc, Qh, Kh, h, m0, n0, lane);
            int r = m0 + (lane >> 2);
            int cb = (lane & 3) * 2;
            float* S = Ssm + h * 2600;
#pragma unroll
            for (int t = 0; t < 4; t++) {
                int c = n0 + t * 8 + cb;
                if (r < 50) {
                    if (c < 50)     S[r * 52 + c]     = acc[t][0];
                    if (c + 1 < 50) S[r * 52 + c + 1] = acc[t][1];
                }
                if (r + 8 < 50) {
                    if (c < 50)     S[(r + 8) * 52 + c]     = acc[t][2];
                    if (c + 1 < 50) S[(r + 8) * 52 + c + 1] = acc[t][3];
                }
            }
        }
        __syncthreads();

        {
            const float scale = 0.17677669529663687f; // 1/sqrt(32)
            for (int idx = w; idx < 128; idx += 8) {
                int h = idx >> 6, r = idx & 63;
                __half* prow = Ph + h * 4608 + r * 72;
                if (r >= 50) {
                    *(__half2*)(prow + lane * 2) = __floats2half2_rn(0.f, 0.f);
                } else {
                    const float* S = Ssm + h * 2600 + r * 52;
                    float f0 = km[lane], f1 = km[lane + 32];
                    float raw0 = S[lane];
                    float raw1 = S[(lane + 32 < 50) ? lane + 32 : 0];
                    float s0 = (f0 == 0.f) ? raw0 * scale : -1e9f;
                    float s1 = (f1 == 0.f) ? raw1 * scale : ((f1 == 1.f) ? -1e9f : -INFINITY);
                    float m = wmax(fmaxf(s0, s1));
                    float e0 = expf(s0 - m);
                    float e1 = expf(s1 - m);
                    float inv = 1.0f / wsum(e0 + e1);
                    prow[lane]      = __float2half_rn(e0 * inv);
                    prow[lane + 32] = __float2half_rn(e1 * inv);
                }
            }
        }
        __syncthreads();

        {
            int h = w >> 2, mm = (w & 3) * 16;
            float acc[4][4] = {};
            mma_block(Ph + h * 4608, 72, 0, Vh, 72, h * 32, mm, 4, acc);
            int r = mm + (lane >> 2);
            int cb = (lane & 3) * 2;
#pragma unroll
            for (int t = 0; t < 4; t++) {
                int c = h * 32 + t * 8 + cb;
                *(__half2*)(Ah + r * 72 + c)       = __floats2half2_rn(acc[t][0], acc[t][1]);
                *(__half2*)(Ah + (r + 8) * 72 + c) = __floats2half2_rn(acc[t][2], acc[t][3]);
            }
        }
        for (int i = tid; i < 512; i += 256) {
            uint4 u = ((const uint4*)woh)[i];
            int row = i >> 3, c = (i & 7) * 8;
            *(uint4*)(Wos + row * 72 + c) = u;
        }
        __syncthreads();

        {
            float acc[4][4] = {};
            mma_block(Ah, 72, 0, Wos, 72, n0, m0, 4, acc);
            epi_store66(y, acc, m0, n0, lane);
        }
        __syncthreads();
        ln_add(xs, y, ln1g, ln1b, tid);
        __syncthreads();

        build_Ah(Ah, xs, tid);
        {
            float acc[4][4] = {};
            for (int ch = 0; ch < 2; ch++) {
                for (int i = tid; i < 1024; i += 256) {
                    int row = i >> 4, j = i & 15;
                    uint4 u = ((const uint4*)w1h)[row * 32 + ch * 16 + j];
                    *(uint4*)(W1c + row * 136 + j * 8) = u;
                }
                for (int i = tid; i < 1024; i += 256) {
                    uint4 u = ((const uint4*)w2h)[ch * 1024 + i];
                    int row = i >> 3, c = (i & 7) * 8;
                    *(uint4*)(W2c + row * 72 + c) = u;
                }
                __syncthreads();
#pragma unroll
                for (int ng = 0; ng < 2; ng++) {
                    float a1[4][4] = {};
                    mma_block(Ah, 72, 0, W1c, 136, ng * 64 + n0, m0, 4, a1);
                    int r = m0 + (lane >> 2);
                    int cb = (lane & 3) * 2;
#pragma unroll
                    for (int t = 0; t < 4; t++) {
                        int cl = ng * 64 + n0 + t * 8 + cb;
                        int cg = ch * 128 + cl;
                        float bb0 = b1[cg], bb1 = b1[cg + 1];
                        *(__half2*)(H1c + r * 136 + cl) =
                            __floats2half2_rn(gelu_f(a1[t][0] + bb0), gelu_f(a1[t][1] + bb1));
                        *(__half2*)(H1c + (r + 8) * 136 + cl) =
                            __floats2half2_rn(gelu_f(a1[t][2] + bb0), gelu_f(a1[t][3] + bb1));
                    }
                }
                __syncthreads();
                mma_block(H1c, 136, 0, W2c, 72, n0, m0, 8, acc);
                __syncthreads();
            }
            int r = m0 + (lane >> 2);
            int cb = (lane & 3) * 2;
#pragma unroll
            for (int t = 0; t < 4; t++) {
                int c = n0 + t * 8 + cb;
                float bb0 = b2[c], bb1 = b2[c + 1];
                if (r < 50)     *(float2*)(y2 + r * 66 + c)       = make_float2(acc[t][0] + bb0, acc[t][1] + bb1);
                if (r + 8 < 50) *(float2*)(y2 + (r + 8) * 66 + c) = make_float2(acc[t][2] + bb0, acc[t][3] + bb1);
            }
        }
        __syncthreads();
        ln_add(xs, y2, ln2g, ln2b, tid);
        __syncthreads();
    }

    // ---- epilogue: final LN on row lens[b]-1, write 64 floats ----
    if (w == 0) {
        int r = lens[b] - 1;
        float v0 = xs[r * 64 + lane], v1 = xs[r * 64 + 32 + lane];
        float mean = wsum(v0 + v1) * (1.0f / 64.0f);
        float d0 = v0 - mean, d1 = v1 - mean;
        float var = wsum(d0 * d0 + d1 * d1) * (1.0f / 64.0f);
        float inv = 1.0f / sqrtf(var + 1e-5f);
        out[b * D + lane]      = d0 * inv * lnfg[lane]      + lnfb[lane];
        out[b * D + 32 + lane] = d1 * inv * lnfg[lane + 32] + lnfb[lane + 32];
    }
}

// ---------------- launch -------------------------------------------
extern "C" void kernel_launch(void* const* d_in, const int* in_sizes, int n_in,
                              void* d_out, int out_size)
{
    const int*   seq  = (const int*)d_in[0];
    const int*   lens = (const int*)d_in[1];
    const int*   ei   = (const int*)d_in[2];
    const float* ew   = (const float*)d_in[3];
    const float* bert = (const float*)d_in[4];
    const float* gnn  = (const float*)d_in[5];
    const float* Wp   = (const float*)d_in[6];
    const float* bp   = (const float*)d_in[7];
    const float* pos  = (const float*)d_in[8];
    const float* wq   = (const float*)d_in[9];
    const float* wk   = (const float*)d_in[10];
    const float* wv   = (const float*)d_in[11];
    const float* wo   = (const float*)d_in[12];
    const float* w1   = (const float*)d_in[13];
    const float* b1   = (const float*)d_in[14];
    const float* w2   = (const float*)d_in[15];
    const float* b2   = (const float*)d_in[16];
    const float* ln1g = (const float*)d_in[17];
    const float* ln1b = (const float*)d_in[18];
    const float* ln2g = (const float*)d_in[19];
    const float* ln2b = (const float*)d_in[20];
    const float* lnfg = (const float*)d_in[21];
    const float* lnfb = (const float*)d_in[22];
    float* out = (float*)d_out;
    int E = in_sizes[3];

    cudaFuncSetAttribute(xformer_kernel,
                         cudaFuncAttributeMaxDynamicSharedMemorySize, SMEM_BYTES);

    __half2 *gnnh, *x1h, *x2h;
    __half *wph, *wqkvh, *woh, *w1hp, *w2hp;
    cudaGetSymbolAddress((void**)&gnnh, g_gnnh);
    cudaGetSymbolAddress((void**)&x1h, g_x1h);
    cudaGetSymbolAddress((void**)&x2h, g_x2h);
    cudaGetSymbolAddress((void**)&wph, g_wph);
    cudaGetSymbolAddress((void**)&wqkvh, g_wqkvh);
    cudaGetSymbolAddress((void**)&woh, g_woh);
    cudaGetSymbolAddress((void**)&w1hp, g_w1h);
    cudaGetSymbolAddress((void**)&w2hp, g_w2h);

    prep_kernel<<<1024, 256>>>(gnn, Wp, wq, wk, wv, wo, w1, w2);

    // CSR build
    hist_kernel<<<(E + 255) / 256, 256>>>(ei, E);
    scan1_kernel<<<(NN + 1023) / 1024, 256>>>();
    scan3_kernel<<<(NN + 255) / 256, 256>>>();
    reorder_kernel<<<(E + 255) / 256, 256>>>(ei, ew, E);

    // two GNN layers via gather-aggregate (fp16 features)
    agg_kernel<<<(NN + 7) / 8, 256>>>(gnnh, x1h);
    agg_kernel<<<(NN + 7) / 8, 256>>>(x1h, x2h);

    xformer_kernel<<<SB, 256, SMEM_BYTES>>>(seq, lens, bert, pos, bp,
        wph, wqkvh, woh, w1hp, b1, w2hp, b2,
        ln1g, ln1b, ln2g, ln2b, lnfg, lnfb, out);
}

// round 15
// speedup vs baseline: 3.7143x; 1.1620x over previous
#include <cuda_runtime.h>
#include <cuda_fp16.h>
#include <math.h>

#define NN   100001
#define D    64
#define SB   1024
#define SQ   50
#define DFF  256
#define EMAX 1048576

// ---------------- scratch (no allocations allowed) ----------------
__device__ __align__(8) __half2 g_gnnh[NN * 32];
__device__ __align__(8) __half2 g_x1h[NN * 32];
__device__ __align__(8) __half2 g_x2h[NN * 32];
// CSR build scratch
__device__ int   g_cnt[NN];
__device__ int   g_scanned[NN];
__device__ int   g_bsum[128];
__device__ int   g_rowptr[NN];
__device__ int   g_cursor[NN];
__device__ int   g_csrc[EMAX];
__device__ float g_cw[EMAX];
// fp16 packed weights (written once per launch by prep_kernel)
__device__ __align__(16) __half g_wph[4096];
__device__ __align__(16) __half g_wqkvh[2 * 64 * 192];
__device__ __align__(16) __half g_woh[2 * 4096];
__device__ __align__(16) __half g_w1h[2 * 16384];
__device__ __align__(16) __half g_w2h[2 * 16384];

// ---------------- smem byte offsets (peak 55360 -> 4 CTAs/SM) -----
#define SO_XS   0        // f32[3200]            -> 12800 (persistent)
#define SO_KM   12800    // f32[64]              -> 13056 (persistent)
#define SO_SEQ  13056    // int[64]              -> 13312 (prologue only)
#define SO_AH   13312    // half[64][72] 9216    -> 22528 (A operand / ctx)
#define SO_SF   13312    // half[2][50][52] 10400-> 23712 (scores, overlays AH+WST-head)
#define SO_CTX  13312    // half[50][72] 7200    (after SF dead)
#define SO_WST  22528    // half[64][72] 9216    -> 31744 (weight stage)
#define SO_VH   31744    // half[50][72] 7200    -> 38944
#define SO_H1C  31744    // half[64][72] 9216    -> 40960 (FFN, Vh dead)
#define SO_KH   38944    // half[50][72] 7200    -> 46144
#define SO_PH   38944    // half[2][50][72] 14400-> 53344 (over KH+QH-start, dead)
#define SO_Y    38944    // f32[50][66] 13200    -> 52144 (over PH, dead)
#define SO_W2C  40960    // half[64][72] 9216    -> 50176 (FFN)
#define SO_QH   46144    // half[64][72] 9216    -> 55360
#define SMEM_BYTES 55360

__device__ __forceinline__ float wsum(float v) {
#pragma unroll
    for (int o = 16; o > 0; o >>= 1) v += __shfl_xor_sync(0xffffffffu, v, o);
    return v;
}
__device__ __forceinline__ int wsumi(int v) {
#pragma unroll
    for (int o = 16; o > 0; o >>= 1) v += __shfl_xor_sync(0xffffffffu, v, o);
    return v;
}
__device__ __forceinline__ float wmax(float v) {
#pragma unroll
    for (int o = 16; o > 0; o >>= 1) v = fmaxf(v, __shfl_xor_sync(0xffffffffu, v, o));
    return v;
}
__device__ __forceinline__ float gelu_f(float x) {
    float inner = 0.7978845608028654f * (x + 0.044715f * x * x * x);
    return 0.5f * x * (1.0f + tanhf(inner));
}

// ---------------- mma helpers ----------------
__device__ __forceinline__ void ldsm_x4(unsigned &r0, unsigned &r1, unsigned &r2, unsigned &r3, unsigned addr) {
    asm volatile("ldmatrix.sync.aligned.m8n8.x4.shared.b16 {%0,%1,%2,%3}, [%4];"
                 : "=r"(r0), "=r"(r1), "=r"(r2), "=r"(r3) : "r"(addr));
}
__device__ __forceinline__ void ldsm_x4_t(unsigned &r0, unsigned &r1, unsigned &r2, unsigned &r3, unsigned addr) {
    asm volatile("ldmatrix.sync.aligned.m8n8.x4.trans.shared.b16 {%0,%1,%2,%3}, [%4];"
                 : "=r"(r0), "=r"(r1), "=r"(r2), "=r"(r3) : "r"(addr));
}
__device__ __forceinline__ void mma16816(float c[4], unsigned a0, unsigned a1, unsigned a2, unsigned a3,
                                         unsigned b0, unsigned b1) {
    asm volatile("mma.sync.aligned.m16n8k16.row.col.f32.f16.f16.f32 "
                 "{%0,%1,%2,%3}, {%4,%5,%6,%7}, {%8,%9}, {%0,%1,%2,%3};"
                 : "+f"(c[0]), "+f"(c[1]), "+f"(c[2]), "+f"(c[3])
                 : "r"(a0), "r"(a1), "r"(a2), "r"(a3), "r"(b0), "r"(b1));
}

// warp computes 16x32 tile. A row-major [m][k] (reads rows m0..m0+15, k0..k0+16KT-1);
// B stored [k][n] row-major in a LOCAL buffer (rows 0..16*KT-1), trans ldmatrix.
__device__ __forceinline__ void mma_block(const __half* Ah, int lda, int k0,
                                          const __half* Bh, int ldb, int n0,
                                          int m0, int KT, float acc[4][4]) {
    int lane = threadIdx.x & 31;
    unsigned abase = (unsigned)__cvta_generic_to_shared(Ah) +
                     (unsigned)(((m0 + (lane & 15)) * lda + k0 + ((lane >> 4) * 8)) * 2);
    unsigned bbase = (unsigned)__cvta_generic_to_shared(Bh);
    int brow = lane & 15;
    int bcol8 = (lane >> 4) * 8;
    for (int kt = 0; kt < KT; kt++) {
        unsigned a0, a1, a2, a3;
        ldsm_x4(a0, a1, a2, a3, abase + kt * 32);
#pragma unroll
        for (int ns = 0; ns < 2; ns++) {
            unsigned baddr = bbase + (unsigned)(((kt * 16 + brow) * ldb + n0 + ns * 16 + bcol8) * 2);
            unsigned b0, b1, b2, b3;
            ldsm_x4_t(b0, b1, b2, b3, baddr);
            mma16816(acc[ns * 2 + 0], a0, a1, a2, a3, b0, b1);
            mma16816(acc[ns * 2 + 1], a0, a1, a2, a3, b2, b3);
        }
    }
}

// scores: A = Qh [64][72] at k-cols h*32..; B = Kh [50][72] row-major (non-trans ldmatrix)
__device__ __forceinline__ void score_mma(float acc[4][4], const __half* Qh, const __half* Kh,
                                          int h, int m0, int n0, int lane) {
    unsigned abase = (unsigned)__cvta_generic_to_shared(Qh) +
                     (unsigned)(((m0 + (lane & 15)) * 72 + h * 32 + ((lane >> 4) * 8)) * 2);
    unsigned kb = (unsigned)__cvta_generic_to_shared(Kh);
    int nbase = n0 + (lane & 7) + ((lane >= 16) ? 8 : 0);
    int koff = ((lane & 15) >= 8) ? 8 : 0;
    for (int kt = 0; kt < 2; kt++) {
        unsigned a0, a1, a2, a3;
        ldsm_x4(a0, a1, a2, a3, abase + kt * 32);
#pragma unroll
        for (int ns = 0; ns < 2; ns++) {
            unsigned baddr = kb + (unsigned)(((nbase + ns * 16) * 72 + h * 32 + kt * 16 + koff) * 2);
            unsigned b0, b1, b2, b3;
            ldsm_x4(b0, b1, b2, b3, baddr);
            mma16816(acc[ns * 2 + 0], a0, a1, a2, a3, b0, b1);
            mma16816(acc[ns * 2 + 1], a0, a1, a2, a3, b2, b3);
        }
    }
}

// ---------------- prep: zero counts + convert/pack weights + gnn --
__global__ void prep_kernel(const float* __restrict__ gnn, const float* __restrict__ wp,
                            const float* __restrict__ wq, const float* __restrict__ wk,
                            const float* __restrict__ wv, const float* __restrict__ wo,
                            const float* __restrict__ w1, const float* __restrict__ w2)
{
    int i = blockIdx.x * blockDim.x + threadIdx.x;
    int st = gridDim.x * blockDim.x;
    for (int j = i; j < NN; j += st) g_cnt[j] = 0;
    for (int j = i; j < NN * 32; j += st) {
        float2 v = ((const float2*)gnn)[j];
        g_gnnh[j] = __floats2half2_rn(v.x, v.y);
    }
    for (int j = i; j < 4096; j += st) g_wph[j] = __float2half_rn(wp[j]);
    for (int j = i; j < 2 * 64 * 192; j += st) {
        int blk = j / (64 * 192), rem = j % (64 * 192);
        int k = rem / 192, n = rem % 192;
        const float* src = (n < 64) ? wq : (n < 128) ? wk : wv;
        g_wqkvh[j] = __float2half_rn(src[blk * 4096 + k * 64 + (n & 63)]);
    }
    for (int j = i; j < 2 * 4096; j += st)  g_woh[j] = __float2half_rn(wo[j]);
    for (int j = i; j < 2 * 16384; j += st) g_w1h[j] = __float2half_rn(w1[j]);
    for (int j = i; j < 2 * 16384; j += st) g_w2h[j] = __float2half_rn(w2[j]);
}

// ---------------- CSR build ----------------
__global__ void hist_kernel(const int* __restrict__ ei, int E) {
    int t = blockIdx.x * blockDim.x + threadIdx.x;
    if (t < E) atomicAdd(&g_cnt[ei[E + t]], 1);
}

__global__ void scan1_kernel() {
    __shared__ int wsums[8];
    int tid = threadIdx.x;
    int base = blockIdx.x * 1024 + tid * 4;
    int c[4]; int s = 0;
#pragma unroll
    for (int j = 0; j < 4; j++) {
        int idx = base + j;
        c[j] = (idx < NN) ? g_cnt[idx] : 0;
        s += c[j];
    }
    int lane = tid & 31, wid = tid >> 5;
    int v = s;
#pragma unroll
    for (int o = 1; o < 32; o <<= 1) { int u = __shfl_up_sync(0xffffffffu, v, o); if (lane >= o) v += u; }
    if (lane == 31) wsums[wid] = v;
    __syncthreads();
    if (wid == 0) {
        int wv = (lane < 8) ? wsums[lane] : 0;
#pragma unroll
        for (int o = 1; o < 8; o <<= 1) { int u = __shfl_up_sync(0xffffffffu, wv, o); if (lane >= o) wv += u; }
        if (lane < 8) wsums[lane] = wv;
    }
    __syncthreads();
    int excl = v - s + ((wid > 0) ? wsums[wid - 1] : 0);
    int run = excl;
#pragma unroll
    for (int j = 0; j < 4; j++) {
        int idx = base + j;
        if (idx < NN) g_scanned[idx] = run;
        run += c[j];
    }
    if (tid == 255) g_bsum[blockIdx.x] = run;
}

__global__ void scan3_kernel() {
    __shared__ int boff_s;
    int tid = threadIdx.x;
    int bucket = blockIdx.x >> 2;
    if (tid < 32) {
        int s = 0;
        for (int k = tid; k < bucket; k += 32) s += g_bsum[k];
        s = wsumi(s);
        if (tid == 0) boff_s = s;
    }
    __syncthreads();
    int idx = blockIdx.x * 256 + tid;
    if (idx < NN) {
        int v = g_scanned[idx] + boff_s;
        g_rowptr[idx] = v;
        g_cursor[idx] = v;
    }
}

__global__ void reorder_kernel(const int* __restrict__ ei, const float* __restrict__ ew, int E) {
    int t = blockIdx.x * blockDim.x + threadIdx.x;
    if (t >= E) return;
    int src = ei[t];
    int dst = ei[E + t];
    int pos = atomicAdd(&g_cursor[dst], 1);
    g_csrc[pos] = src;
    g_cw[pos] = ew[t];
}

// ---------------- aggregation (half2 in, half2 out) ---------------
__global__ void __launch_bounds__(256) agg_kernel(
    const __half2* __restrict__ xin, __half2* __restrict__ xout)
{
    int node = blockIdx.x * 8 + (threadIdx.x >> 5);
    if (node >= NN) return;
    int lane = threadIdx.x & 31;
    int beg = g_rowptr[node];
    int cnt = g_cnt[node];
    float a0 = 0.f, a1 = 0.f;
    for (int j = 0; j < cnt; j++) {
        int src = g_csrc[beg + j];
        float w = g_cw[beg + j];
        float2 f = __half22float2(xin[(size_t)src * 32 + lane]);
        a0 += w * f.x;
        a1 += w * f.y;
    }
    xout[(size_t)node * 32 + lane] = __floats2half2_rn(a0, a1);
}

// ---------------- transformer helpers ----------------
__device__ __forceinline__ void build_Ah(__half* Ah, const float* xs, int tid) {
    for (int i = tid; i < 64 * 32; i += 256) {
        int row = i >> 5, c2 = i & 31;
        __half2 hv;
        if (row < 50) {
            float2 xv = *(const float2*)(xs + row * 64 + c2 * 2);
            hv = __floats2half2_rn(xv.x, xv.y);
        } else {
            hv = __floats2half2_rn(0.f, 0.f);
        }
        *(__half2*)(Ah + row * 72 + c2 * 2) = hv;
    }
}

// fp16 epilogue into [64][72] buffer, all rows (rows >=50 are exact zeros)
__device__ __forceinline__ void epi_h16(__half* dst, float acc[4][4], int m0, int n0, int lane) {
    int r = m0 + (lane >> 2);
    int cb = (lane & 3) * 2;
#pragma unroll
    for (int t = 0; t < 4; t++) {
        int c = n0 + t * 8 + cb;
        *(__half2*)(dst + r * 72 + c)       = __floats2half2_rn(acc[t][0], acc[t][1]);
        *(__half2*)(dst + (r + 8) * 72 + c) = __floats2half2_rn(acc[t][2], acc[t][3]);
    }
}

// fp16 epilogue into [50][72] buffer, rows < 50 only
__device__ __forceinline__ void epi_h16_50(__half* dst, float acc[4][4], int m0, int n0, int lane) {
    int r = m0 + (lane >> 2);
    int cb = (lane & 3) * 2;
#pragma unroll
    for (int t = 0; t < 4; t++) {
        int c = n0 + t * 8 + cb;
        if (r < 50)     *(__half2*)(dst + r * 72 + c)       = __floats2half2_rn(acc[t][0], acc[t][1]);
        if (r + 8 < 50) *(__half2*)(dst + (r + 8) * 72 + c) = __floats2half2_rn(acc[t][2], acc[t][3]);
    }
}

__device__ __forceinline__ void epi_store66(float* dst, float acc[4][4], int m0, int n0, int lane) {
    int r = m0 + (lane >> 2);
    int cb = (lane & 3) * 2;
#pragma unroll
    for (int t = 0; t < 4; t++) {
        int c = n0 + t * 8 + cb;
        if (r < 50)     *(float2*)(dst + r * 66 + c)       = make_float2(acc[t][0], acc[t][1]);
        if (r + 8 < 50) *(float2*)(dst + (r + 8) * 66 + c) = make_float2(acc[t][2], acc[t][3]);
    }
}

__device__ __forceinline__ void ln_add(float* __restrict__ xs,
                                       const float* __restrict__ y,
                                       const float* __restrict__ g,
                                       const float* __restrict__ bta, int tid)
{
    int lane = tid & 31, w = tid >> 5;
    for (int r = w; r < 50; r += 8) {
        float v0 = xs[r * 64 + lane]      + y[r * 66 + lane];
        float v1 = xs[r * 64 + 32 + lane] + y[r * 66 + 32 + lane];
        float mean = wsum(v0 + v1) * (1.0f / 64.0f);
        float d0 = v0 - mean, d1 = v1 - mean;
        float var = wsum(d0 * d0 + d1 * d1) * (1.0f / 64.0f);
        float inv = 1.0f / sqrtf(var + 1e-5f);
        xs[r * 64 + lane]      = d0 * inv * g[lane]      + bta[lane];
        xs[r * 64 + 32 + lane] = d1 * inv * g[32 + lane] + bta[32 + lane];
    }
}

// -------- fused: proj + blend + 2 transformer blocks + final LN ---
__global__ void __launch_bounds__(256, 4) xformer_kernel(
    const int* __restrict__ seq, const int* __restrict__ lens,
    const float* __restrict__ bert, const float* __restrict__ pos,
    const float* __restrict__ bp,
    const __half* __restrict__ wph,
    const __half* __restrict__ wqkvh_all, const __half* __restrict__ woh_all,
    const __half* __restrict__ w1h_all, const float* __restrict__ b1_all,
    const __half* __restrict__ w2h_all, const float* __restrict__ b2_all,
    const float* __restrict__ ln1g_all, const float* __restrict__ ln1b_all,
    const float* __restrict__ ln2g_all, const float* __restrict__ ln2b_all,
    const float* __restrict__ lnfg, const float* __restrict__ lnfb,
    float* __restrict__ out)
{
    extern __shared__ char smraw[];
    int tid = threadIdx.x;
    int lane = tid & 31, w = tid >> 5;
    int b = blockIdx.x;

    float*  xs  = (float*)(smraw + SO_XS);
    float*  km  = (float*)(smraw + SO_KM);
    int*    seqs = (int*)(smraw + SO_SEQ);
    __half* Ah  = (__half*)(smraw + SO_AH);
    __half* Sf  = (__half*)(smraw + SO_SF);
    __half* ctx = (__half*)(smraw + SO_CTX);
    __half* Wst = (__half*)(smraw + SO_WST);
    __half* Vh  = (__half*)(smraw + SO_VH);
    __half* H1c = (__half*)(smraw + SO_H1C);
    __half* Kh  = (__half*)(smraw + SO_KH);
    __half* Ph  = (__half*)(smraw + SO_PH);
    float*  y   = (float*)(smraw + SO_Y);
    __half* W2c = (__half*)(smraw + SO_W2C);
    __half* Qh  = (__half*)(smraw + SO_QH);

    int m0 = (w & 3) * 16;
    int n0 = (w >> 2) * 32;

    // ---- prologue: seq/mask, proj of this CTA's 50 nodes, blend ----
    if (tid < 64) {
        int sv = (tid < 50) ? seq[b * SQ + tid] : 0;
        seqs[tid] = sv;
        km[tid] = (tid < 50) ? ((sv != 0) ? 0.f : 1.f) : 2.f;
    }
    __syncthreads();
    for (int i = tid; i < 512; i += 256) {
        uint4 u = ((const uint4*)wph)[i];
        int row = i >> 3, c = (i & 7) * 8;
        *(uint4*)(Wst + row * 72 + c) = u;
    }
    for (int i = tid; i < 2048; i += 256) {
        int row = i >> 5, c2 = i & 31;
        __half2 hv = __floats2half2_rn(0.f, 0.f);
        if (row < 50) {
            int idx = seqs[row];
            float2 gv = __half22float2(g_gnnh[(size_t)idx * 32 + c2]);
            float2 xa = __half22float2(g_x1h[(size_t)idx * 32 + c2]);
            float2 xb = __half22float2(g_x2h[(size_t)idx * 32 + c2]);
            hv = __floats2half2_rn((gv.x + xa.x + xb.x) * (1.0f / 3.0f),
                                   (gv.y + xa.y + xb.y) * (1.0f / 3.0f));
        }
        *(__half2*)(Ah + row * 72 + c2 * 2) = hv;
    }
    __syncthreads();
    {
        float acc[4][4] = {};
        mma_block(Ah, 72, 0, Wst, 72, n0, m0, 4, acc);
        int r = m0 + (lane >> 2);
        int cb = (lane & 3) * 2;
#pragma unroll
        for (int t = 0; t < 4; t++) {
            int c = n0 + t * 8 + cb;
            float bb0 = bp[c], bb1 = bp[c + 1];
            if (r < 50)     *(float2*)(y + r * 66 + c)       = make_float2(acc[t][0] + bb0, acc[t][1] + bb1);
            if (r + 8 < 50) *(float2*)(y + (r + 8) * 66 + c) = make_float2(acc[t][2] + bb0, acc[t][3] + bb1);
        }
    }
    __syncthreads();
    {
        int len = lens[b];
        float alpha = (len <= 10) ? 0.3f : ((len >= 50) ? 0.7f : 0.5f);
        float beta = 1.0f - alpha;
        for (int i = tid; i < 3200; i += 256) {
            int row = i >> 6, c = i & 63;
            int idx = seqs[row];
            xs[i] = alpha * bert[(size_t)idx * D + c] + beta * y[row * 66 + c] + pos[i];
        }
    }
    __syncthreads();

    // ---- two transformer blocks ----
    for (int blk = 0; blk < 2; blk++) {
        const __half* wqkvh = wqkvh_all + blk * 12288;
        const __half* woh   = woh_all   + blk * 4096;
        const __half* w1h   = w1h_all   + blk * 16384;
        const float*  b1    = b1_all    + blk * 256;
        const __half* w2h   = w2h_all   + blk * 16384;
        const float*  b2    = b2_all    + blk * 64;
        const float*  ln1g  = ln1g_all  + blk * 64;
        const float*  ln1b  = ln1b_all  + blk * 64;
        const float*  ln2g  = ln2g_all  + blk * 64;
        const float*  ln2b  = ln2b_all  + blk * 64;

        build_Ah(Ah, xs, tid);
        // Q: stage Wq third [64][72]
        for (int i = tid; i < 512; i += 256) {
            int r = i >> 3, j = i & 7;
            uint4 u = ((const uint4*)wqkvh)[r * 24 + j];
            *(uint4*)(Wst + r * 72 + j * 8) = u;
        }
        __syncthreads();
        {
            float acc[4][4] = {};
            mma_block(Ah, 72, 0, Wst, 72, n0, m0, 4, acc);
            epi_h16(Qh, acc, m0, n0, lane);   // full [64][72], rows>=50 exact zero
        }
        __syncthreads();
        // K
        for (int i = tid; i < 512; i += 256) {
            int r = i >> 3, j = i & 7;
            uint4 u = ((const uint4*)wqkvh)[r * 24 + 8 + j];
            *(uint4*)(Wst + r * 72 + j * 8) = u;
        }
        __syncthreads();
        {
            float acc[4][4] = {};
            mma_block(Ah, 72, 0, Wst, 72, n0, m0, 4, acc);
            epi_h16_50(Kh, acc, m0, n0, lane);
        }
        __syncthreads();
        // V
        for (int i = tid; i < 512; i += 256) {
            int r = i >> 3, j = i & 7;
            uint4 u = ((const uint4*)wqkvh)[r * 24 + 16 + j];
            *(uint4*)(Wst + r * 72 + j * 8) = u;
        }
        __syncthreads();
        {
            float acc[4][4] = {};
            mma_block(Ah, 72, 0, Wst, 72, n0, m0, 4, acc);
            epi_h16_50(Vh, acc, m0, n0, lane);
        }
        __syncthreads();

        // scores both heads -> Sf fp16 [2][50][52]
#pragma unroll
        for (int h = 0; h < 2; h++) {
            float acc[4][4] = {};
            score_mma(acc, Qh, Kh, h, m0, n0, lane);
            int r = m0 + (lane >> 2);
            int cb = (lane & 3) * 2;
            __half* S = Sf + h * 2600;
#pragma unroll
            for (int t = 0; t < 4; t++) {
                int c = n0 + t * 8 + cb;
                if (r < 50) {
                    if (c < 50)     S[r * 52 + c]     = __float2half_rn(acc[t][0]);
                    if (c + 1 < 50) S[r * 52 + c + 1] = __float2half_rn(acc[t][1]);
                }
                if (r + 8 < 50) {
                    if (c < 50)     S[(r + 8) * 52 + c]     = __float2half_rn(acc[t][2]);
                    if (c + 1 < 50) S[(r + 8) * 52 + c + 1] = __float2half_rn(acc[t][3]);
                }
            }
        }
        __syncthreads();

        // softmax -> Ph fp16 [2][50][72] (cols 50-63 exact zeros via -INF)
        {
            const float scale = 0.17677669529663687f; // 1/sqrt(32)
            for (int idx = w; idx < 100; idx += 8) {
                int h = (idx >= 50) ? 1 : 0;
                int r = idx - h * 50;
                __half* prow = Ph + h * 3600 + r * 72;
                const __half* Srow = Sf + h * 2600 + r * 52;
                float f0 = km[lane], f1 = km[lane + 32];
                float raw0 = __half2float(Srow[lane]);
                float raw1 = __half2float(Srow[(lane + 32 < 50) ? lane + 32 : 0]);
                float s0 = (f0 == 0.f) ? raw0 * scale : -1e9f;
                float s1 = (f1 == 0.f) ? raw1 * scale : ((f1 == 1.f) ? -1e9f : -INFINITY);
                float m = wmax(fmaxf(s0, s1));
                float e0 = expf(s0 - m);
                float e1 = expf(s1 - m);
                float inv = 1.0f / wsum(e0 + e1);
                prow[lane]      = __float2half_rn(e0 * inv);
                prow[lane + 32] = __float2half_rn(e1 * inv);
            }
        }
        __syncthreads();

        // ctx = P @ V per head -> ctx [50][72] (guarded); stage Wo
        {
            int h = w >> 2, mm = (w & 3) * 16;
            float acc[4][4] = {};
            mma_block(Ph + h * 3600, 72, 0, Vh, 72, h * 32, mm, 4, acc);
            int r = mm + (lane >> 2);
            int cb = (lane & 3) * 2;
#pragma unroll
            for (int t = 0; t < 4; t++) {
                int c = h * 32 + t * 8 + cb;
                if (r < 50)     *(__half2*)(ctx + r * 72 + c)       = __floats2half2_rn(acc[t][0], acc[t][1]);
                if (r + 8 < 50) *(__half2*)(ctx + (r + 8) * 72 + c) = __floats2half2_rn(acc[t][2], acc[t][3]);
            }
        }
        for (int i = tid; i < 512; i += 256) {
            uint4 u = ((const uint4*)woh)[i];
            int row = i >> 3, c = (i & 7) * 8;
            *(uint4*)(Wst + row * 72 + c) = u;
        }
        __syncthreads();

        // O = ctx @ Wo -> y ; LN1
        {
            float acc[4][4] = {};
            mma_block(ctx, 72, 0, Wst, 72, n0, m0, 4, acc);
            epi_store66(y, acc, m0, n0, lane);
        }
        __syncthreads();
        ln_add(xs, y, ln1g, ln1b, tid);
        __syncthreads();

        // FFN: 4 chunks of 64 (N for FFN1, K for FFN2)
        build_Ah(Ah, xs, tid);
        {
            float acc[4][4] = {};
            for (int ch = 0; ch < 4; ch++) {
                for (int i = tid; i < 512; i += 256) {
                    int r = i >> 3, j = i & 7;
                    uint4 u = ((const uint4*)w1h)[r * 32 + ch * 8 + j];
                    *(uint4*)(Wst + r * 72 + j * 8) = u;
                }
                for (int i = tid; i < 512; i += 256) {
                    int r = i >> 3, c = (i & 7) * 8;
                    uint4 u = ((const uint4*)w2h)[ch * 512 + i];
                    *(uint4*)(W2c + r * 72 + c) = u;
                }
                __syncthreads();
                {
                    float a1[4][4] = {};
                    mma_block(Ah, 72, 0, Wst, 72, n0, m0, 4, a1);
                    int r = m0 + (lane >> 2);
                    int cb = (lane & 3) * 2;
#pragma unroll
                    for (int t = 0; t < 4; t++) {
                        int cl = n0 + t * 8 + cb;
                        int cg = ch * 64 + cl;
                        float bb0 = b1[cg], bb1 = b1[cg + 1];
                        *(__half2*)(H1c + r * 72 + cl) =
                            __floats2half2_rn(gelu_f(a1[t][0] + bb0), gelu_f(a1[t][1] + bb1));
                        *(__half2*)(H1c + (r + 8) * 72 + cl) =
                            __floats2half2_rn(gelu_f(a1[t][2] + bb0), gelu_f(a1[t][3] + bb1));
                    }
                }
                __syncthreads();
                mma_block(H1c, 72, 0, W2c, 72, n0, m0, 4, acc);
                __syncthreads();
            }
            int r = m0 + (lane >> 2);
            int cb = (lane & 3) * 2;
#pragma unroll
            for (int t = 0; t < 4; t++) {
                int c = n0 + t * 8 + cb;
                float bb0 = b2[c], bb1 = b2[c + 1];
                if (r < 50)     *(float2*)(y + r * 66 + c)       = make_float2(acc[t][0] + bb0, acc[t][1] + bb1);
                if (r + 8 < 50) *(float2*)(y + (r + 8) * 66 + c) = make_float2(acc[t][2] + bb0, acc[t][3] + bb1);
            }
        }
        __syncthreads();
        ln_add(xs, y, ln2g, ln2b, tid);
        __syncthreads();
    }

    // ---- epilogue: final LN on row lens[b]-1, write 64 floats ----
    if (w == 0) {
        int r = lens[b] - 1;
        float v0 = xs[r * 64 + lane], v1 = xs[r * 64 + 32 + lane];
        float mean = wsum(v0 + v1) * (1.0f / 64.0f);
        float d0 = v0 - mean, d1 = v1 - mean;
        float var = wsum(d0 * d0 + d1 * d1) * (1.0f / 64.0f);
        float inv = 1.0f / sqrtf(var + 1e-5f);
        out[b * D + lane]      = d0 * inv * lnfg[lane]      + lnfb[lane];
        out[b * D + 32 + lane] = d1 * inv * lnfg[lane + 32] + lnfb[lane + 32];
    }
}

// ---------------- launch -------------------------------------------
extern "C" void kernel_launch(void* const* d_in, const int* in_sizes, int n_in,
                              void* d_out, int out_size)
{
    const int*   seq  = (const int*)d_in[0];
    const int*   lens = (const int*)d_in[1];
    const int*   ei   = (const int*)d_in[2];
    const float* ew   = (const float*)d_in[3];
    const float* bert = (const float*)d_in[4];
    const float* gnn  = (const float*)d_in[5];
    const float* Wp   = (const float*)d_in[6];
    const float* bp   = (const float*)d_in[7];
    const float* pos  = (const float*)d_in[8];
    const float* wq   = (const float*)d_in[9];
    const float* wk   = (const float*)d_in[10];
    const float* wv   = (const float*)d_in[11];
    const float* wo   = (const float*)d_in[12];
    const float* w1   = (const float*)d_in[13];
    const float* b1   = (const float*)d_in[14];
    const float* w2   = (const float*)d_in[15];
    const float* b2   = (const float*)d_in[16];
    const float* ln1g = (const float*)d_in[17];
    const float* ln1b = (const float*)d_in[18];
    const float* ln2g = (const float*)d_in[19];
    const float* ln2b = (const float*)d_in[20];
    const float* lnfg = (const float*)d_in[21];
    const float* lnfb = (const float*)d_in[22];
    float* out = (float*)d_out;
    int E = in_sizes[3];

    cudaFuncSetAttribute(xformer_kernel,
                         cudaFuncAttributeMaxDynamicSharedMemorySize, SMEM_BYTES);

    __half2 *gnnh, *x1h, *x2h;
    __half *wph, *wqkvh, *woh, *w1hp, *w2hp;
    cudaGetSymbolAddress((void**)&gnnh, g_gnnh);
    cudaGetSymbolAddress((void**)&x1h, g_x1h);
    cudaGetSymbolAddress((void**)&x2h, g_x2h);
    cudaGetSymbolAddress((void**)&wph, g_wph);
    cudaGetSymbolAddress((void**)&wqkvh, g_wqkvh);
    cudaGetSymbolAddress((void**)&woh, g_woh);
    cudaGetSymbolAddress((void**)&w1hp, g_w1h);
    cudaGetSymbolAddress((void**)&w2hp, g_w2h);

    prep_kernel<<<1024, 256>>>(gnn, Wp, wq, wk, wv, wo, w1, w2);

    // CSR build
    hist_kernel<<<(E + 255) / 256, 256>>>(ei, E);
    scan1_kernel<<<(NN + 1023) / 1024, 256>>>();
    scan3_kernel<<<(NN + 255) / 256, 256>>>();
    reorder_kernel<<<(E + 255) / 256, 256>>>(ei, ew, E);

    // two GNN layers via gather-aggregate (fp16 features)
    agg_kernel<<<(NN + 7) / 8, 256>>>(gnnh, x1h);
    agg_kernel<<<(NN + 7) / 8, 256>>>(x1h, x2h);

    xformer_kernel<<<SB, 256, SMEM_BYTES>>>(seq, lens, bert, pos, bp,
        wph, wqkvh, woh, w1hp, b1, w2hp, b2,
        ln1g, ln1b, ln2g, ln2b, lnfg, lnfb, out);
}

// round 16
// speedup vs baseline: 3.9357x; 1.0596x over previous
#include <cuda_runtime.h>
#include <cuda_fp16.h>
#include <math.h>

#define NN   100001
#define D    64
#define SB   1024
#define SQ   50
#define DFF  256
#define EMAX 1048576

// ---------------- scratch (no allocations allowed) ----------------
__device__ __align__(8) __half2 g_gnnh[NN * 32];
__device__ __align__(8) __half2 g_x1h[NN * 32];
__device__ __align__(8) __half2 g_x2h[NN * 32];
// CSR build scratch
__device__ int   g_cnt[NN];
__device__ int   g_scanned[NN];
__device__ int   g_bsum[128];
__device__ int   g_rowptr[NN];
__device__ int   g_cursor[NN];
__device__ int   g_csrc[EMAX];
__device__ float g_cw[EMAX];
// fp16 packed weights (written once per launch by prep_kernel)
__device__ __align__(16) __half g_wph[4096];
__device__ __align__(16) __half g_wqkvh[2 * 64 * 192];
__device__ __align__(16) __half g_woh[2 * 4096];
__device__ __align__(16) __half g_w1h[2 * 16384];
__device__ __align__(16) __half g_w2h[2 * 16384];

// ---------------- smem byte offsets (peak 50176, occ 4) -----------
#define SO_XS   0        // f32[3200]        -> 12800 (persistent)
#define SO_KM   12800    // f32[64]          -> 13056 (persistent)
#define SO_SEQ  13056    // int[64]          -> 13312
#define SO_AH   13312    // half[64][72]     -> 22528 (A operand / ctx out)
#define SO_WST  22528    // half[64][72]     -> 31744 (weight stage)
#define SO_KH   31744    // half[64][72]     -> 40960 (K, zero-padded rows)
#define SO_VH   40960    // half[64][72]     -> 50176 (V, zero-padded rows)
#define SO_Y    31744    // f32[50][66] 13200-> 44944 (over KH+VH-head; post-attention)
#define SO_W2C  31744    // half[64][72]     -> 40960 (FFN; over dead Y/KH)
#define SO_H1C  40960    // half[64][72]     -> 50176 (FFN; over dead VH)
#define SMEM_BYTES 50176

__device__ __forceinline__ float wsum(float v) {
#pragma unroll
    for (int o = 16; o > 0; o >>= 1) v += __shfl_xor_sync(0xffffffffu, v, o);
    return v;
}
__device__ __forceinline__ int wsumi(int v) {
#pragma unroll
    for (int o = 16; o > 0; o >>= 1) v += __shfl_xor_sync(0xffffffffu, v, o);
    return v;
}
__device__ __forceinline__ float gelu_f(float x) {
    float inner = 0.7978845608028654f * (x + 0.044715f * x * x * x);
    return 0.5f * x * (1.0f + tanhf(inner));
}
__device__ __forceinline__ unsigned h2pack(float a, float b) {
    __half2 h = __floats2half2_rn(a, b);
    return *(unsigned*)&h;
}

// ---------------- mma helpers ----------------
__device__ __forceinline__ void ldsm_x4(unsigned &r0, unsigned &r1, unsigned &r2, unsigned &r3, unsigned addr) {
    asm volatile("ldmatrix.sync.aligned.m8n8.x4.shared.b16 {%0,%1,%2,%3}, [%4];"
                 : "=r"(r0), "=r"(r1), "=r"(r2), "=r"(r3) : "r"(addr));
}
__device__ __forceinline__ void ldsm_x4_t(unsigned &r0, unsigned &r1, unsigned &r2, unsigned &r3, unsigned addr) {
    asm volatile("ldmatrix.sync.aligned.m8n8.x4.trans.shared.b16 {%0,%1,%2,%3}, [%4];"
                 : "=r"(r0), "=r"(r1), "=r"(r2), "=r"(r3) : "r"(addr));
}
__device__ __forceinline__ void mma16816(float c[4], unsigned a0, unsigned a1, unsigned a2, unsigned a3,
                                         unsigned b0, unsigned b1) {
    asm volatile("mma.sync.aligned.m16n8k16.row.col.f32.f16.f16.f32 "
                 "{%0,%1,%2,%3}, {%4,%5,%6,%7}, {%8,%9}, {%0,%1,%2,%3};"
                 : "+f"(c[0]), "+f"(c[1]), "+f"(c[2]), "+f"(c[3])
                 : "r"(a0), "r"(a1), "r"(a2), "r"(a3), "r"(b0), "r"(b1));
}

// warp computes 16x32 tile. A row-major [m][k]; B [k][n] row-major local buffer.
__device__ __forceinline__ void mma_block(const __half* Ah, int lda, int k0,
                                          const __half* Bh, int ldb, int n0,
                                          int m0, int KT, float acc[4][4]) {
    int lane = threadIdx.x & 31;
    unsigned abase = (unsigned)__cvta_generic_to_shared(Ah) +
                     (unsigned)(((m0 + (lane & 15)) * lda + k0 + ((lane >> 4) * 8)) * 2);
    unsigned bbase = (unsigned)__cvta_generic_to_shared(Bh);
    int brow = lane & 15;
    int bcol8 = (lane >> 4) * 8;
    for (int kt = 0; kt < KT; kt++) {
        unsigned a0, a1, a2, a3;
        ldsm_x4(a0, a1, a2, a3, abase + kt * 32);
#pragma unroll
        for (int ns = 0; ns < 2; ns++) {
            unsigned baddr = bbase + (unsigned)(((kt * 16 + brow) * ldb + n0 + ns * 16 + bcol8) * 2);
            unsigned b0, b1, b2, b3;
            ldsm_x4_t(b0, b1, b2, b3, baddr);
            mma16816(acc[ns * 2 + 0], a0, a1, a2, a3, b0, b1);
            mma16816(acc[ns * 2 + 1], a0, a1, a2, a3, b2, b3);
        }
    }
}

// ---------------- prep ----------------
__global__ void prep_kernel(const float* __restrict__ gnn, const float* __restrict__ wp,
                            const float* __restrict__ wq, const float* __restrict__ wk,
                            const float* __restrict__ wv, const float* __restrict__ wo,
                            const float* __restrict__ w1, const float* __restrict__ w2)
{
    int i = blockIdx.x * blockDim.x + threadIdx.x;
    int st = gridDim.x * blockDim.x;
    for (int j = i; j < NN; j += st) g_cnt[j] = 0;
    for (int j = i; j < NN * 32; j += st) {
        float2 v = ((const float2*)gnn)[j];
        g_gnnh[j] = __floats2half2_rn(v.x, v.y);
    }
    for (int j = i; j < 4096; j += st) g_wph[j] = __float2half_rn(wp[j]);
    for (int j = i; j < 2 * 64 * 192; j += st) {
        int blk = j / (64 * 192), rem = j % (64 * 192);
        int k = rem / 192, n = rem % 192;
        const float* src = (n < 64) ? wq : (n < 128) ? wk : wv;
        g_wqkvh[j] = __float2half_rn(src[blk * 4096 + k * 64 + (n & 63)]);
    }
    for (int j = i; j < 2 * 4096; j += st)  g_woh[j] = __float2half_rn(wo[j]);
    for (int j = i; j < 2 * 16384; j += st) g_w1h[j] = __float2half_rn(w1[j]);
    for (int j = i; j < 2 * 16384; j += st) g_w2h[j] = __float2half_rn(w2[j]);
}

// ---------------- CSR build ----------------
__global__ void hist_kernel(const int* __restrict__ ei, int E) {
    int t = blockIdx.x * blockDim.x + threadIdx.x;
    if (t < E) atomicAdd(&g_cnt[ei[E + t]], 1);
}

__global__ void scan1_kernel() {
    __shared__ int wsums[8];
    int tid = threadIdx.x;
    int base = blockIdx.x * 1024 + tid * 4;
    int c[4]; int s = 0;
#pragma unroll
    for (int j = 0; j < 4; j++) {
        int idx = base + j;
        c[j] = (idx < NN) ? g_cnt[idx] : 0;
        s += c[j];
    }
    int lane = tid & 31, wid = tid >> 5;
    int v = s;
#pragma unroll
    for (int o = 1; o < 32; o <<= 1) { int u = __shfl_up_sync(0xffffffffu, v, o); if (lane >= o) v += u; }
    if (lane == 31) wsums[wid] = v;
    __syncthreads();
    if (wid == 0) {
        int wv = (lane < 8) ? wsums[lane] : 0;
#pragma unroll
        for (int o = 1; o < 8; o <<= 1) { int u = __shfl_up_sync(0xffffffffu, wv, o); if (lane >= o) wv += u; }
        if (lane < 8) wsums[lane] = wv;
    }
    __syncthreads();
    int excl = v - s + ((wid > 0) ? wsums[wid - 1] : 0);
    int run = excl;
#pragma unroll
    for (int j = 0; j < 4; j++) {
        int idx = base + j;
        if (idx < NN) g_scanned[idx] = run;
        run += c[j];
    }
    if (tid == 255) g_bsum[blockIdx.x] = run;
}

__global__ void scan3_kernel() {
    __shared__ int boff_s;
    int tid = threadIdx.x;
    int bucket = blockIdx.x >> 2;
    if (tid < 32) {
        int s = 0;
        for (int k = tid; k < bucket; k += 32) s += g_bsum[k];
        s = wsumi(s);
        if (tid == 0) boff_s = s;
    }
    __syncthreads();
    int idx = blockIdx.x * 256 + tid;
    if (idx < NN) {
        int v = g_scanned[idx] + boff_s;
        g_rowptr[idx] = v;
        g_cursor[idx] = v;
    }
}

__global__ void reorder_kernel(const int* __restrict__ ei, const float* __restrict__ ew, int E) {
    int t = blockIdx.x * blockDim.x + threadIdx.x;
    if (t >= E) return;
    int src = ei[t];
    int dst = ei[E + t];
    int pos = atomicAdd(&g_cursor[dst], 1);
    g_csrc[pos] = src;
    g_cw[pos] = ew[t];
}

// ---------------- aggregation (half2, unroll-4 MLP) ---------------
__global__ void __launch_bounds__(256) agg_kernel(
    const __half2* __restrict__ xin, __half2* __restrict__ xout)
{
    int node = blockIdx.x * 8 + (threadIdx.x >> 5);
    if (node >= NN) return;
    int lane = threadIdx.x & 31;
    int beg = g_rowptr[node];
    int cnt = g_cnt[node];
    float a0 = 0.f, a1 = 0.f;
    int j = 0;
    for (; j + 4 <= cnt; j += 4) {
        int s0 = g_csrc[beg + j],     s1 = g_csrc[beg + j + 1];
        int s2 = g_csrc[beg + j + 2], s3 = g_csrc[beg + j + 3];
        float w0 = g_cw[beg + j],     w1 = g_cw[beg + j + 1];
        float w2 = g_cw[beg + j + 2], w3 = g_cw[beg + j + 3];
        float2 f0 = __half22float2(xin[(size_t)s0 * 32 + lane]);
        float2 f1 = __half22float2(xin[(size_t)s1 * 32 + lane]);
        float2 f2 = __half22float2(xin[(size_t)s2 * 32 + lane]);
        float2 f3 = __half22float2(xin[(size_t)s3 * 32 + lane]);
        a0 += w0 * f0.x + w1 * f1.x + w2 * f2.x + w3 * f3.x;
        a1 += w0 * f0.y + w1 * f1.y + w2 * f2.y + w3 * f3.y;
    }
    for (; j < cnt; j++) {
        int src = g_csrc[beg + j];
        float w = g_cw[beg + j];
        float2 f = __half22float2(xin[(size_t)src * 32 + lane]);
        a0 += w * f.x;
        a1 += w * f.y;
    }
    xout[(size_t)node * 32 + lane] = __floats2half2_rn(a0, a1);
}

// ---------------- transformer helpers ----------------
__device__ __forceinline__ void build_Ah(__half* Ah, const float* xs, int tid) {
    for (int i = tid; i < 64 * 32; i += 256) {
        int row = i >> 5, c2 = i & 31;
        __half2 hv;
        if (row < 50) {
            float2 xv = *(const float2*)(xs + row * 64 + c2 * 2);
            hv = __floats2half2_rn(xv.x, xv.y);
        } else {
            hv = __floats2half2_rn(0.f, 0.f);
        }
        *(__half2*)(Ah + row * 72 + c2 * 2) = hv;
    }
}

// fp16 epilogue into [64][72], all rows (rows >=50 = exact zeros from zero A rows)
__device__ __forceinline__ void epi_h16(__half* dst, float acc[4][4], int m0, int n0, int lane) {
    int r = m0 + (lane >> 2);
    int cb = (lane & 3) * 2;
#pragma unroll
    for (int t = 0; t < 4; t++) {
        int c = n0 + t * 8 + cb;
        *(__half2*)(dst + r * 72 + c)       = __floats2half2_rn(acc[t][0], acc[t][1]);
        *(__half2*)(dst + (r + 8) * 72 + c) = __floats2half2_rn(acc[t][2], acc[t][3]);
    }
}

__device__ __forceinline__ void epi_store66(float* dst, float acc[4][4], int m0, int n0, int lane) {
    int r = m0 + (lane >> 2);
    int cb = (lane & 3) * 2;
#pragma unroll
    for (int t = 0; t < 4; t++) {
        int c = n0 + t * 8 + cb;
        if (r < 50)     *(float2*)(dst + r * 66 + c)       = make_float2(acc[t][0], acc[t][1]);
        if (r + 8 < 50) *(float2*)(dst + (r + 8) * 66 + c) = make_float2(acc[t][2], acc[t][3]);
    }
}

__device__ __forceinline__ void ln_add(float* __restrict__ xs,
                                       const float* __restrict__ y,
                                       const float* __restrict__ g,
                                       const float* __restrict__ bta, int tid)
{
    int lane = tid & 31, w = tid >> 5;
    for (int r = w; r < 50; r += 8) {
        float v0 = xs[r * 64 + lane]      + y[r * 66 + lane];
        float v1 = xs[r * 64 + 32 + lane] + y[r * 66 + 32 + lane];
        float mean = wsum(v0 + v1) * (1.0f / 64.0f);
        float d0 = v0 - mean, d1 = v1 - mean;
        float var = wsum(d0 * d0 + d1 * d1) * (1.0f / 64.0f);
        float inv = 1.0f / sqrtf(var + 1e-5f);
        xs[r * 64 + lane]      = d0 * inv * g[lane]      + bta[lane];
        xs[r * 64 + 32 + lane] = d1 * inv * g[32 + lane] + bta[32 + lane];
    }
}

// -------- fused: proj + blend + 2 transformer blocks + final LN ---
__global__ void __launch_bounds__(256, 4) xformer_kernel(
    const int* __restrict__ seq, const int* __restrict__ lens,
    const float* __restrict__ bert, const float* __restrict__ pos,
    const float* __restrict__ bp,
    const __half* __restrict__ wph,
    const __half* __restrict__ wqkvh_all, const __half* __restrict__ woh_all,
    const __half* __restrict__ w1h_all, const float* __restrict__ b1_all,
    const __half* __restrict__ w2h_all, const float* __restrict__ b2_all,
    const float* __restrict__ ln1g_all, const float* __restrict__ ln1b_all,
    const float* __restrict__ ln2g_all, const float* __restrict__ ln2b_all,
    const float* __restrict__ lnfg, const float* __restrict__ lnfb,
    float* __restrict__ out)
{
    extern __shared__ char smraw[];
    int tid = threadIdx.x;
    int lane = tid & 31, w = tid >> 5;
    int b = blockIdx.x;

    float*  xs   = (float*)(smraw + SO_XS);
    float*  km   = (float*)(smraw + SO_KM);
    int*    seqs = (int*)(smraw + SO_SEQ);
    __half* Ah   = (__half*)(smraw + SO_AH);
    __half* Wst  = (__half*)(smraw + SO_WST);
    __half* Kh   = (__half*)(smraw + SO_KH);
    __half* Vh   = (__half*)(smraw + SO_VH);
    float*  y    = (float*)(smraw + SO_Y);
    __half* W2c  = (__half*)(smraw + SO_W2C);
    __half* H1c  = (__half*)(smraw + SO_H1C);

    int m0 = (w & 3) * 16;
    int n0 = (w >> 2) * 32;
    int h  = w >> 2;          // head owned by this warp (== n0/32)

    // ---- prologue ----
    if (tid < 64) {
        int sv = (tid < 50) ? seq[b * SQ + tid] : 0;
        seqs[tid] = sv;
        km[tid] = (tid < 50) ? ((sv != 0) ? 0.f : 1.f) : 2.f;
    }
    __syncthreads();
    for (int i = tid; i < 512; i += 256) {
        uint4 u = ((const uint4*)wph)[i];
        int row = i >> 3, c = (i & 7) * 8;
        *(uint4*)(Wst + row * 72 + c) = u;
    }
    for (int i = tid; i < 2048; i += 256) {
        int row = i >> 5, c2 = i & 31;
        __half2 hv = __floats2half2_rn(0.f, 0.f);
        if (row < 50) {
            int idx = seqs[row];
            float2 gv = __half22float2(g_gnnh[(size_t)idx * 32 + c2]);
            float2 xa = __half22float2(g_x1h[(size_t)idx * 32 + c2]);
            float2 xb = __half22float2(g_x2h[(size_t)idx * 32 + c2]);
            hv = __floats2half2_rn((gv.x + xa.x + xb.x) * (1.0f / 3.0f),
                                   (gv.y + xa.y + xb.y) * (1.0f / 3.0f));
        }
        *(__half2*)(Ah + row * 72 + c2 * 2) = hv;
    }
    __syncthreads();
    {
        float acc[4][4] = {};
        mma_block(Ah, 72, 0, Wst, 72, n0, m0, 4, acc);
        int r = m0 + (lane >> 2);
        int cb = (lane & 3) * 2;
#pragma unroll
        for (int t = 0; t < 4; t++) {
            int c = n0 + t * 8 + cb;
            float bb0 = bp[c], bb1 = bp[c + 1];
            if (r < 50)     *(float2*)(y + r * 66 + c)       = make_float2(acc[t][0] + bb0, acc[t][1] + bb1);
            if (r + 8 < 50) *(float2*)(y + (r + 8) * 66 + c) = make_float2(acc[t][2] + bb0, acc[t][3] + bb1);
        }
    }
    __syncthreads();
    {
        int len = lens[b];
        float alpha = (len <= 10) ? 0.3f : ((len >= 50) ? 0.7f : 0.5f);
        float beta = 1.0f - alpha;
        for (int i = tid; i < 3200; i += 256) {
            int row = i >> 6, c = i & 63;
            int idx = seqs[row];
            xs[i] = alpha * bert[(size_t)idx * D + c] + beta * y[row * 66 + c] + pos[i];
        }
    }
    __syncthreads();

    // ---- two transformer blocks ----
    for (int blk = 0; blk < 2; blk++) {
        const __half* wqkvh = wqkvh_all + blk * 12288;
        const __half* woh   = woh_all   + blk * 4096;
        const __half* w1h   = w1h_all   + blk * 16384;
        const float*  b1    = b1_all    + blk * 256;
        const __half* w2h   = w2h_all   + blk * 16384;
        const float*  b2    = b2_all    + blk * 64;
        const float*  ln1g  = ln1g_all  + blk * 64;
        const float*  ln1b  = ln1b_all  + blk * 64;
        const float*  ln2g  = ln2g_all  + blk * 64;
        const float*  ln2b  = ln2b_all  + blk * 64;

        // (a) build A + stage Wq
        build_Ah(Ah, xs, tid);
        for (int i = tid; i < 512; i += 256) {
            int r = i >> 3, j = i & 7;
            uint4 u = ((const uint4*)wqkvh)[r * 24 + j];
            *(uint4*)(Wst + r * 72 + j * 8) = u;
        }
        __syncthreads();

        // (b) Q-mma -> REGISTERS (repack C-frags as score A-frags)
        unsigned qa[2][4];
        {
            float q[4][4] = {};
            mma_block(Ah, 72, 0, Wst, 72, n0, m0, 4, q);
#pragma unroll
            for (int kt = 0; kt < 2; kt++) {
                qa[kt][0] = h2pack(q[2 * kt][0],     q[2 * kt][1]);
                qa[kt][1] = h2pack(q[2 * kt][2],     q[2 * kt][3]);
                qa[kt][2] = h2pack(q[2 * kt + 1][0], q[2 * kt + 1][1]);
                qa[kt][3] = h2pack(q[2 * kt + 1][2], q[2 * kt + 1][3]);
            }
        }
        __syncthreads();

        // (c/d) K
        for (int i = tid; i < 512; i += 256) {
            int r = i >> 3, j = i & 7;
            uint4 u = ((const uint4*)wqkvh)[r * 24 + 8 + j];
            *(uint4*)(Wst + r * 72 + j * 8) = u;
        }
        __syncthreads();
        {
            float acc[4][4] = {};
            mma_block(Ah, 72, 0, Wst, 72, n0, m0, 4, acc);
            epi_h16(Kh, acc, m0, n0, lane);   // rows 50-63 exact zeros
        }
        __syncthreads();
        // (e/f) V
        for (int i = tid; i < 512; i += 256) {
            int r = i >> 3, j = i & 7;
            uint4 u = ((const uint4*)wqkvh)[r * 24 + 16 + j];
            *(uint4*)(Wst + r * 72 + j * 8) = u;
        }
        __syncthreads();
        {
            float acc[4][4] = {};
            mma_block(Ah, 72, 0, Wst, 72, n0, m0, 4, acc);
            epi_h16(Vh, acc, m0, n0, lane);   // rows 50-63 exact zeros
        }
        __syncthreads();

        // (g) scores + softmax + ctx ALL IN REGISTERS; warp = (m0, head h)
        {
            unsigned kb = (unsigned)__cvta_generic_to_shared(Kh);
            int nrow = (lane & 7) + ((lane >= 16) ? 8 : 0);
            int koff = ((lane & 15) >= 8) ? 8 : 0;
            float s[8][4];
#pragma unroll
            for (int i = 0; i < 8; i++) { s[i][0] = s[i][1] = s[i][2] = s[i][3] = 0.f; }
#pragma unroll
            for (int ns = 0; ns < 4; ns++) {
#pragma unroll
                for (int kt = 0; kt < 2; kt++) {
                    unsigned b0, b1, b2, b3;
                    ldsm_x4(b0, b1, b2, b3,
                        kb + (unsigned)(((ns * 16 + nrow) * 72 + h * 32 + kt * 16 + koff) * 2));
                    mma16816(s[ns * 2 + 0], qa[kt][0], qa[kt][1], qa[kt][2], qa[kt][3], b0, b1);
                    mma16816(s[ns * 2 + 1], qa[kt][0], qa[kt][1], qa[kt][2], qa[kt][3], b2, b3);
                }
            }
            // softmax (quad-reduction: 4 threads lane%4=0..3 cover a row's 64 cols)
            const float scale = 0.17677669529663687f; // 1/sqrt(32)
            float mx0 = -INFINITY, mx1 = -INFINITY;
#pragma unroll
            for (int i = 0; i < 8; i++) {
                int colb = (i >> 1) * 16 + (i & 1) * 8 + (lane & 3) * 2;
#pragma unroll
                for (int j = 0; j < 4; j++) {
                    int col = colb + (j & 1);
                    float f = km[col];
                    float v = (f == 0.f) ? s[i][j] * scale : ((f == 1.f) ? -1e9f : -INFINITY);
                    s[i][j] = v;
                    if (j < 2) mx0 = fmaxf(mx0, v); else mx1 = fmaxf(mx1, v);
                }
            }
#pragma unroll
            for (int o = 1; o <= 2; o <<= 1) {
                mx0 = fmaxf(mx0, __shfl_xor_sync(0xffffffffu, mx0, o));
                mx1 = fmaxf(mx1, __shfl_xor_sync(0xffffffffu, mx1, o));
            }
            float sm0 = 0.f, sm1 = 0.f;
#pragma unroll
            for (int i = 0; i < 8; i++) {
                float e0 = expf(s[i][0] - mx0), e1 = expf(s[i][1] - mx0);
                float e2 = expf(s[i][2] - mx1), e3 = expf(s[i][3] - mx1);
                s[i][0] = e0; s[i][1] = e1; s[i][2] = e2; s[i][3] = e3;
                sm0 += e0 + e1; sm1 += e2 + e3;
            }
#pragma unroll
            for (int o = 1; o <= 2; o <<= 1) {
                sm0 += __shfl_xor_sync(0xffffffffu, sm0, o);
                sm1 += __shfl_xor_sync(0xffffffffu, sm1, o);
            }
            float inv0 = 1.0f / sm0, inv1 = 1.0f / sm1;
            unsigned pa[4][4];
#pragma unroll
            for (int kt = 0; kt < 4; kt++) {
                pa[kt][0] = h2pack(s[2 * kt][0] * inv0,     s[2 * kt][1] * inv0);
                pa[kt][1] = h2pack(s[2 * kt][2] * inv1,     s[2 * kt][3] * inv1);
                pa[kt][2] = h2pack(s[2 * kt + 1][0] * inv0, s[2 * kt + 1][1] * inv0);
                pa[kt][3] = h2pack(s[2 * kt + 1][2] * inv1, s[2 * kt + 1][3] * inv1);
            }
            // ctx = P @ V : rows m0..m0+15, cols h*32..h*32+31 -> Ah region
            {
                unsigned vb = (unsigned)__cvta_generic_to_shared(Vh);
                int brow = lane & 15;
                int bcol8 = (lane >> 4) * 8;
                float acc[4][4] = {};
#pragma unroll
                for (int kt = 0; kt < 4; kt++) {
#pragma unroll
                    for (int ns = 0; ns < 2; ns++) {
                        unsigned b0, b1, b2, b3;
                        ldsm_x4_t(b0, b1, b2, b3,
                            vb + (unsigned)(((kt * 16 + brow) * 72 + h * 32 + ns * 16 + bcol8) * 2));
                        mma16816(acc[ns * 2 + 0], pa[kt][0], pa[kt][1], pa[kt][2], pa[kt][3], b0, b1);
                        mma16816(acc[ns * 2 + 1], pa[kt][0], pa[kt][1], pa[kt][2], pa[kt][3], b2, b3);
                    }
                }
                epi_h16(Ah, acc, m0, h * 32, lane);  // rows 50-63 finite, discarded later
            }
        }
        // stage Wo in same phase (Wst free since V-mma sync)
        for (int i = tid; i < 512; i += 256) {
            uint4 u = ((const uint4*)woh)[i];
            int row = i >> 3, c = (i & 7) * 8;
            *(uint4*)(Wst + row * 72 + c) = u;
        }
        __syncthreads();

        // (h) O = ctx @ Wo -> y ; (i) LN1
        {
            float acc[4][4] = {};
            mma_block(Ah, 72, 0, Wst, 72, n0, m0, 4, acc);
            epi_store66(y, acc, m0, n0, lane);
        }
        __syncthreads();
        ln_add(xs, y, ln1g, ln1b, tid);
        __syncthreads();

        // FFN: 4 chunks of 64
        {
            float acc[4][4] = {};
            for (int ch = 0; ch < 4; ch++) {
                if (ch == 0) build_Ah(Ah, xs, tid);
                for (int i = tid; i < 512; i += 256) {
                    int r = i >> 3, j = i & 7;
                    uint4 u = ((const uint4*)w1h)[r * 32 + ch * 8 + j];
                    *(uint4*)(Wst + r * 72 + j * 8) = u;
                }
                for (int i = tid; i < 512; i += 256) {
                    int r = i >> 3, c = (i & 7) * 8;
                    uint4 u = ((const uint4*)w2h)[ch * 512 + i];
                    *(uint4*)(W2c + r * 72 + c) = u;
                }
                __syncthreads();
                {
                    float a1[4][4] = {};
                    mma_block(Ah, 72, 0, Wst, 72, n0, m0, 4, a1);
                    int r = m0 + (lane >> 2);
                    int cb = (lane & 3) * 2;
#pragma unroll
                    for (int t = 0; t < 4; t++) {
                        int cl = n0 + t * 8 + cb;
                        int cg = ch * 64 + cl;
                        float bb0 = b1[cg], bb1 = b1[cg + 1];
                        *(__half2*)(H1c + r * 72 + cl) =
                            __floats2half2_rn(gelu_f(a1[t][0] + bb0), gelu_f(a1[t][1] + bb1));
                        *(__half2*)(H1c + (r + 8) * 72 + cl) =
                            __floats2half2_rn(gelu_f(a1[t][2] + bb0), gelu_f(a1[t][3] + bb1));
                    }
                }
                __syncthreads();
                mma_block(H1c, 72, 0, W2c, 72, n0, m0, 4, acc);
                __syncthreads();
            }
            int r = m0 + (lane >> 2);
            int cb = (lane & 3) * 2;
#pragma unroll
            for (int t = 0; t < 4; t++) {
                int c = n0 + t * 8 + cb;
                float bb0 = b2[c], bb1 = b2[c + 1];
                if (r < 50)     *(float2*)(y + r * 66 + c)       = make_float2(acc[t][0] + bb0, acc[t][1] + bb1);
                if (r + 8 < 50) *(float2*)(y + (r + 8) * 66 + c) = make_float2(acc[t][2] + bb0, acc[t][3] + bb1);
            }
        }
        __syncthreads();
        ln_add(xs, y, ln2g, ln2b, tid);
        __syncthreads();
    }

    // ---- epilogue: final LN on row lens[b]-1 ----
    if (w == 0) {
        int r = lens[b] - 1;
        float v0 = xs[r * 64 + lane], v1 = xs[r * 64 + 32 + lane];
        float mean = wsum(v0 + v1) * (1.0f / 64.0f);
        float d0 = v0 - mean, d1 = v1 - mean;
        float var = wsum(d0 * d0 + d1 * d1) * (1.0f / 64.0f);
        float inv = 1.0f / sqrtf(var + 1e-5f);
        out[b * D + lane]      = d0 * inv * lnfg[lane]      + lnfb[lane];
        out[b * D + 32 + lane] = d1 * inv * lnfg[lane + 32] + lnfb[lane + 32];
    }
}

// ---------------- launch -------------------------------------------
extern "C" void kernel_launch(void* const* d_in, const int* in_sizes, int n_in,
                              void* d_out, int out_size)
{
    const int*   seq  = (const int*)d_in[0];
    const int*   lens = (const int*)d_in[1];
    const int*   ei   = (const int*)d_in[2];
    const float* ew   = (const float*)d_in[3];
    const float* bert = (const float*)d_in[4];
    const float* gnn  = (const float*)d_in[5];
    const float* Wp   = (const float*)d_in[6];
    const float* bp   = (const float*)d_in[7];
    const float* pos  = (const float*)d_in[8];
    const float* wq   = (const float*)d_in[9];
    const float* wk   = (const float*)d_in[10];
    const float* wv   = (const float*)d_in[11];
    const float* wo   = (const float*)d_in[12];
    const float* w1   = (const float*)d_in[13];
    const float* b1   = (const float*)d_in[14];
    const float* w2   = (const float*)d_in[15];
    const float* b2   = (const float*)d_in[16];
    const float* ln1g = (const float*)d_in[17];
    const float* ln1b = (const float*)d_in[18];
    const float* ln2g = (const float*)d_in[19];
    const float* ln2b = (const float*)d_in[20];
    const float* lnfg = (const float*)d_in[21];
    const float* lnfb = (const float*)d_in[22];
    float* out = (float*)d_out;
    int E = in_sizes[3];

    cudaFuncSetAttribute(xformer_kernel,
                         cudaFuncAttributeMaxDynamicSharedMemorySize, SMEM_BYTES);

    __half2 *gnnh, *x1h, *x2h;
    __half *wph, *wqkvh, *woh, *w1hp, *w2hp;
    cudaGetSymbolAddress((void**)&gnnh, g_gnnh);
    cudaGetSymbolAddress((void**)&x1h, g_x1h);
    cudaGetSymbolAddress((void**)&x2h, g_x2h);
    cudaGetSymbolAddress((void**)&wph, g_wph);
    cudaGetSymbolAddress((void**)&wqkvh, g_wqkvh);
    cudaGetSymbolAddress((void**)&woh, g_woh);
    cudaGetSymbolAddress((void**)&w1hp, g_w1h);
    cudaGetSymbolAddress((void**)&w2hp, g_w2h);

    prep_kernel<<<1024, 256>>>(gnn, Wp, wq, wk, wv, wo, w1, w2);

    hist_kernel<<<(E + 255) / 256, 256>>>(ei, E);
    scan1_kernel<<<(NN + 1023) / 1024, 256>>>();
    scan3_kernel<<<(NN + 255) / 256, 256>>>();
    reorder_kernel<<<(E + 255) / 256, 256>>>(ei, ew, E);

    agg_kernel<<<(NN + 7) / 8, 256>>>(gnnh, x1h);
    agg_kernel<<<(NN + 7) / 8, 256>>>(x1h, x2h);

    xformer_kernel<<<SB, 256, SMEM_BYTES>>>(seq, lens, bert, pos, bp,
        wph, wqkvh, woh, w1hp, b1, w2hp, b2,
        ln1g, ln1b, ln2g, ln2b, lnfg, lnfb, out);
}

// round 17
// speedup vs baseline: 3.9474x; 1.0030x over previous
#include <cuda_runtime.h>
#include <cuda_fp16.h>
#include <math.h>

#define NN   100001
#define D    64
#define SB   1024
#define SQ   50
#define DFF  256
#define EMAX 1048576

// ---------------- scratch (no allocations allowed) ----------------
__device__ __align__(8) __half2 g_gnnh[NN * 32];
__device__ __align__(8) __half2 g_x1h[NN * 32];
__device__ __align__(8) __half2 g_x2h[NN * 32];
// CSR build scratch
__device__ int   g_cnt[NN];
__device__ int   g_scanned[NN];
__device__ int   g_bsum[128];
__device__ int   g_rowptr[NN];
__device__ int   g_cursor[NN];
__device__ int   g_csrc[EMAX];
__device__ float g_cw[EMAX];
// fp16 packed weights (written once per launch by prep_kernel)
__device__ __align__(16) __half g_wph[4096];
__device__ __align__(16) __half g_wqkvh[2 * 64 * 192];
__device__ __align__(16) __half g_woh[2 * 4096];
__device__ __align__(16) __half g_w1h[2 * 16384];
__device__ __align__(16) __half g_w2h[2 * 16384];

// ---------------- smem byte offsets (peak 50176, occ 4) -----------
#define SO_XS   0        // f32[3200]        -> 12800 (persistent)
#define SO_KM   12800    // f32[64]          -> 13056 (persistent)
#define SO_SEQ  13056    // int[64]          -> 13312
#define SO_AH   13312    // half[64][72]     -> 22528 (A operand)
#define SO_WST  22528    // half[64][72]     -> 31744 (weight stage)
#define SO_KH   31744    // half[64][72]     -> 40960 (K out, zero-pad rows)
#define SO_VH   40960    // half[64][72]     -> 50176 (Wk stage, then V out)
#define SO_Y    31744    // f32[50][66] 13200-> 44944 (post-attention / post-FFN)
#define SO_W2C  31744    // half[64][72]     -> 40960 (FFN W2 chunk; y dead)
#define SMEM_BYTES 50176

__device__ __forceinline__ float wsum(float v) {
#pragma unroll
    for (int o = 16; o > 0; o >>= 1) v += __shfl_xor_sync(0xffffffffu, v, o);
    return v;
}
__device__ __forceinline__ int wsumi(int v) {
#pragma unroll
    for (int o = 16; o > 0; o >>= 1) v += __shfl_xor_sync(0xffffffffu, v, o);
    return v;
}
__device__ __forceinline__ float gelu_f(float x) {
    float inner = 0.7978845608028654f * (x + 0.044715f * x * x * x);
    return 0.5f * x * (1.0f + tanhf(inner));
}
__device__ __forceinline__ unsigned h2pack(float a, float b) {
    __half2 h = __floats2half2_rn(a, b);
    return *(unsigned*)&h;
}

// ---------------- mma helpers ----------------
__device__ __forceinline__ void ldsm_x4(unsigned &r0, unsigned &r1, unsigned &r2, unsigned &r3, unsigned addr) {
    asm volatile("ldmatrix.sync.aligned.m8n8.x4.shared.b16 {%0,%1,%2,%3}, [%4];"
                 : "=r"(r0), "=r"(r1), "=r"(r2), "=r"(r3) : "r"(addr));
}
__device__ __forceinline__ void ldsm_x4_t(unsigned &r0, unsigned &r1, unsigned &r2, unsigned &r3, unsigned addr) {
    asm volatile("ldmatrix.sync.aligned.m8n8.x4.trans.shared.b16 {%0,%1,%2,%3}, [%4];"
                 : "=r"(r0), "=r"(r1), "=r"(r2), "=r"(r3) : "r"(addr));
}
__device__ __forceinline__ void mma16816(float c[4], unsigned a0, unsigned a1, unsigned a2, unsigned a3,
                                         unsigned b0, unsigned b1) {
    asm volatile("mma.sync.aligned.m16n8k16.row.col.f32.f16.f16.f32 "
                 "{%0,%1,%2,%3}, {%4,%5,%6,%7}, {%8,%9}, {%0,%1,%2,%3};"
                 : "+f"(c[0]), "+f"(c[1]), "+f"(c[2]), "+f"(c[3])
                 : "r"(a0), "r"(a1), "r"(a2), "r"(a3), "r"(b0), "r"(b1));
}

// warp computes 16x32 tile. A row-major [m][k]; B [k][n] row-major local buffer.
__device__ __forceinline__ void mma_block(const __half* Ah, int lda, int k0,
                                          const __half* Bh, int ldb, int n0,
                                          int m0, int KT, float acc[4][4]) {
    int lane = threadIdx.x & 31;
    unsigned abase = (unsigned)__cvta_generic_to_shared(Ah) +
                     (unsigned)(((m0 + (lane & 15)) * lda + k0 + ((lane >> 4) * 8)) * 2);
    unsigned bbase = (unsigned)__cvta_generic_to_shared(Bh);
    int brow = lane & 15;
    int bcol8 = (lane >> 4) * 8;
    for (int kt = 0; kt < KT; kt++) {
        unsigned a0, a1, a2, a3;
        ldsm_x4(a0, a1, a2, a3, abase + kt * 32);
#pragma unroll
        for (int ns = 0; ns < 2; ns++) {
            unsigned baddr = bbase + (unsigned)(((kt * 16 + brow) * ldb + n0 + ns * 16 + bcol8) * 2);
            unsigned b0, b1, b2, b3;
            ldsm_x4_t(b0, b1, b2, b3, baddr);
            mma16816(acc[ns * 2 + 0], a0, a1, a2, a3, b0, b1);
            mma16816(acc[ns * 2 + 1], a0, a1, a2, a3, b2, b3);
        }
    }
}

// ---------------- prep ----------------
__global__ void prep_kernel(const float* __restrict__ gnn, const float* __restrict__ wp,
                            const float* __restrict__ wq, const float* __restrict__ wk,
                            const float* __restrict__ wv, const float* __restrict__ wo,
                            const float* __restrict__ w1, const float* __restrict__ w2)
{
    int i = blockIdx.x * blockDim.x + threadIdx.x;
    int st = gridDim.x * blockDim.x;
    for (int j = i; j < NN; j += st) g_cnt[j] = 0;
    for (int j = i; j < NN * 32; j += st) {
        float2 v = ((const float2*)gnn)[j];
        g_gnnh[j] = __floats2half2_rn(v.x, v.y);
    }
    for (int j = i; j < 4096; j += st) g_wph[j] = __float2half_rn(wp[j]);
    for (int j = i; j < 2 * 64 * 192; j += st) {
        int blk = j / (64 * 192), rem = j % (64 * 192);
        int k = rem / 192, n = rem % 192;
        const float* src = (n < 64) ? wq : (n < 128) ? wk : wv;
        g_wqkvh[j] = __float2half_rn(src[blk * 4096 + k * 64 + (n & 63)]);
    }
    for (int j = i; j < 2 * 4096; j += st)  g_woh[j] = __float2half_rn(wo[j]);
    for (int j = i; j < 2 * 16384; j += st) g_w1h[j] = __float2half_rn(w1[j]);
    for (int j = i; j < 2 * 16384; j += st) g_w2h[j] = __float2half_rn(w2[j]);
}

// ---------------- CSR build ----------------
__global__ void hist_kernel(const int* __restrict__ ei, int E) {
    int t = blockIdx.x * blockDim.x + threadIdx.x;
    if (t < E) atomicAdd(&g_cnt[ei[E + t]], 1);
}

__global__ void scan1_kernel() {
    __shared__ int wsums[8];
    int tid = threadIdx.x;
    int base = blockIdx.x * 1024 + tid * 4;
    int c[4]; int s = 0;
#pragma unroll
    for (int j = 0; j < 4; j++) {
        int idx = base + j;
        c[j] = (idx < NN) ? g_cnt[idx] : 0;
        s += c[j];
    }
    int lane = tid & 31, wid = tid >> 5;
    int v = s;
#pragma unroll
    for (int o = 1; o < 32; o <<= 1) { int u = __shfl_up_sync(0xffffffffu, v, o); if (lane >= o) v += u; }
    if (lane == 31) wsums[wid] = v;
    __syncthreads();
    if (wid == 0) {
        int wv = (lane < 8) ? wsums[lane] : 0;
#pragma unroll
        for (int o = 1; o < 8; o <<= 1) { int u = __shfl_up_sync(0xffffffffu, wv, o); if (lane >= o) wv += u; }
        if (lane < 8) wsums[lane] = wv;
    }
    __syncthreads();
    int excl = v - s + ((wid > 0) ? wsums[wid - 1] : 0);
    int run = excl;
#pragma unroll
    for (int j = 0; j < 4; j++) {
        int idx = base + j;
        if (idx < NN) g_scanned[idx] = run;
        run += c[j];
    }
    if (tid == 255) g_bsum[blockIdx.x] = run;
}

__global__ void scan3_kernel() {
    __shared__ int boff_s;
    int tid = threadIdx.x;
    int bucket = blockIdx.x >> 2;
    if (tid < 32) {
        int s = 0;
        for (int k = tid; k < bucket; k += 32) s += g_bsum[k];
        s = wsumi(s);
        if (tid == 0) boff_s = s;
    }
    __syncthreads();
    int idx = blockIdx.x * 256 + tid;
    if (idx < NN) {
        int v = g_scanned[idx] + boff_s;
        g_rowptr[idx] = v;
        g_cursor[idx] = v;
    }
}

__global__ void reorder_kernel(const int* __restrict__ ei, const float* __restrict__ ew, int E) {
    int t = blockIdx.x * blockDim.x + threadIdx.x;
    if (t >= E) return;
    int src = ei[t];
    int dst = ei[E + t];
    int pos = atomicAdd(&g_cursor[dst], 1);
    g_csrc[pos] = src;
    g_cw[pos] = ew[t];
}

// ---------------- aggregation (half2, unroll-4 MLP) ---------------
__global__ void __launch_bounds__(256) agg_kernel(
    const __half2* __restrict__ xin, __half2* __restrict__ xout)
{
    int node = blockIdx.x * 8 + (threadIdx.x >> 5);
    if (node >= NN) return;
    int lane = threadIdx.x & 31;
    int beg = g_rowptr[node];
    int cnt = g_cnt[node];
    float a0 = 0.f, a1 = 0.f;
    int j = 0;
    for (; j + 4 <= cnt; j += 4) {
        int s0 = g_csrc[beg + j],     s1 = g_csrc[beg + j + 1];
        int s2 = g_csrc[beg + j + 2], s3 = g_csrc[beg + j + 3];
        float w0 = g_cw[beg + j],     w1 = g_cw[beg + j + 1];
        float w2 = g_cw[beg + j + 2], w3 = g_cw[beg + j + 3];
        float2 f0 = __half22float2(xin[(size_t)s0 * 32 + lane]);
        float2 f1 = __half22float2(xin[(size_t)s1 * 32 + lane]);
        float2 f2 = __half22float2(xin[(size_t)s2 * 32 + lane]);
        float2 f3 = __half22float2(xin[(size_t)s3 * 32 + lane]);
        a0 += w0 * f0.x + w1 * f1.x + w2 * f2.x + w3 * f3.x;
        a1 += w0 * f0.y + w1 * f1.y + w2 * f2.y + w3 * f3.y;
    }
    for (; j < cnt; j++) {
        int src = g_csrc[beg + j];
        float w = g_cw[beg + j];
        float2 f = __half22float2(xin[(size_t)src * 32 + lane]);
        a0 += w * f.x;
        a1 += w * f.y;
    }
    xout[(size_t)node * 32 + lane] = __floats2half2_rn(a0, a1);
}

// ---------------- transformer helpers ----------------
__device__ __forceinline__ void build_Ah(__half* Ah, const float* xs, int tid) {
    for (int i = tid; i < 64 * 32; i += 256) {
        int row = i >> 5, c2 = i & 31;
        __half2 hv;
        if (row < 50) {
            float2 xv = *(const float2*)(xs + row * 64 + c2 * 2);
            hv = __floats2half2_rn(xv.x, xv.y);
        } else {
            hv = __floats2half2_rn(0.f, 0.f);
        }
        *(__half2*)(Ah + row * 72 + c2 * 2) = hv;
    }
}

// fp16 epilogue into [64][72], all rows (rows >=50 = exact zeros from zero A rows)
__device__ __forceinline__ void epi_h16(__half* dst, float acc[4][4], int m0, int n0, int lane) {
    int r = m0 + (lane >> 2);
    int cb = (lane & 3) * 2;
#pragma unroll
    for (int t = 0; t < 4; t++) {
        int c = n0 + t * 8 + cb;
        *(__half2*)(dst + r * 72 + c)       = __floats2half2_rn(acc[t][0], acc[t][1]);
        *(__half2*)(dst + (r + 8) * 72 + c) = __floats2half2_rn(acc[t][2], acc[t][3]);
    }
}

__device__ __forceinline__ void ln_add(float* __restrict__ xs,
                                       const float* __restrict__ y,
                                       const float* __restrict__ g,
                                       const float* __restrict__ bta, int tid)
{
    int lane = tid & 31, w = tid >> 5;
    for (int r = w; r < 50; r += 8) {
        float v0 = xs[r * 64 + lane]      + y[r * 66 + lane];
        float v1 = xs[r * 64 + 32 + lane] + y[r * 66 + 32 + lane];
        float mean = wsum(v0 + v1) * (1.0f / 64.0f);
        float d0 = v0 - mean, d1 = v1 - mean;
        float var = wsum(d0 * d0 + d1 * d1) * (1.0f / 64.0f);
        float inv = 1.0f / sqrtf(var + 1e-5f);
        xs[r * 64 + lane]      = d0 * inv * g[lane]      + bta[lane];
        xs[r * 64 + 32 + lane] = d1 * inv * g[32 + lane] + bta[32 + lane];
    }
}

// -------- fused: proj + blend + 2 transformer blocks + final LN ---
__global__ void __launch_bounds__(256, 4) xformer_kernel(
    const int* __restrict__ seq, const int* __restrict__ lens,
    const float* __restrict__ bert, const float* __restrict__ pos,
    const float* __restrict__ bp,
    const __half* __restrict__ wph,
    const __half* __restrict__ wqkvh_all, const __half* __restrict__ woh_all,
    const __half* __restrict__ w1h_all, const float* __restrict__ b1_all,
    const __half* __restrict__ w2h_all, const float* __restrict__ b2_all,
    const float* __restrict__ ln1g_all, const float* __restrict__ ln1b_all,
    const float* __restrict__ ln2g_all, const float* __restrict__ ln2b_all,
    const float* __restrict__ lnfg, const float* __restrict__ lnfb,
    float* __restrict__ out)
{
    extern __shared__ char smraw[];
    int tid = threadIdx.x;
    int lane = tid & 31, w = tid >> 5;
    int b = blockIdx.x;

    float*  xs   = (float*)(smraw + SO_XS);
    float*  km   = (float*)(smraw + SO_KM);
    int*    seqs = (int*)(smraw + SO_SEQ);
    __half* Ah   = (__half*)(smraw + SO_AH);
    __half* Wst  = (__half*)(smraw + SO_WST);
    __half* Kh   = (__half*)(smraw + SO_KH);
    __half* Vh   = (__half*)(smraw + SO_VH);
    float*  y    = (float*)(smraw + SO_Y);
    __half* W2c  = (__half*)(smraw + SO_W2C);

    int m0 = (w & 3) * 16;
    int n0 = (w >> 2) * 32;
    int h  = w >> 2;

    // ---- prologue: seq/mask; blend -> Ah; Wp -> Wst; proj -> xs ----
    if (tid < 64) {
        int sv = (tid < 50) ? seq[b * SQ + tid] : 0;
        seqs[tid] = sv;
        km[tid] = (tid < 50) ? ((sv != 0) ? 0.f : 1.f) : 2.f;
    }
    __syncthreads();
    for (int i = tid; i < 512; i += 256) {
        uint4 u = ((const uint4*)wph)[i];
        int row = i >> 3, c = (i & 7) * 8;
        *(uint4*)(Wst + row * 72 + c) = u;
    }
    for (int i = tid; i < 2048; i += 256) {
        int row = i >> 5, c2 = i & 31;
        __half2 hv = __floats2half2_rn(0.f, 0.f);
        if (row < 50) {
            int idx = seqs[row];
            float2 gv = __half22float2(g_gnnh[(size_t)idx * 32 + c2]);
            float2 xa = __half22float2(g_x1h[(size_t)idx * 32 + c2]);
            float2 xb = __half22float2(g_x2h[(size_t)idx * 32 + c2]);
            hv = __floats2half2_rn((gv.x + xa.x + xb.x) * (1.0f / 3.0f),
                                   (gv.y + xa.y + xb.y) * (1.0f / 3.0f));
        }
        *(__half2*)(Ah + row * 72 + c2 * 2) = hv;
    }
    __syncthreads();
    {
        float acc[4][4] = {};
        mma_block(Ah, 72, 0, Wst, 72, n0, m0, 4, acc);
        int len = lens[b];
        float alpha = (len <= 10) ? 0.3f : ((len >= 50) ? 0.7f : 0.5f);
        float beta = 1.0f - alpha;
        int r = m0 + (lane >> 2);
        int cb = (lane & 3) * 2;
        int i0 = (r < 50) ? seqs[r] : 0;
        int i1 = (r + 8 < 50) ? seqs[r + 8] : 0;
#pragma unroll
        for (int t = 0; t < 4; t++) {
            int c = n0 + t * 8 + cb;
            if (r < 50) {
                xs[r * 64 + c]     = alpha * bert[(size_t)i0 * D + c]     + beta * (acc[t][0] + bp[c])     + pos[r * 64 + c];
                xs[r * 64 + c + 1] = alpha * bert[(size_t)i0 * D + c + 1] + beta * (acc[t][1] + bp[c + 1]) + pos[r * 64 + c + 1];
            }
            if (r + 8 < 50) {
                xs[(r + 8) * 64 + c]     = alpha * bert[(size_t)i1 * D + c]     + beta * (acc[t][2] + bp[c])     + pos[(r + 8) * 64 + c];
                xs[(r + 8) * 64 + c + 1] = alpha * bert[(size_t)i1 * D + c + 1] + beta * (acc[t][3] + bp[c + 1]) + pos[(r + 8) * 64 + c + 1];
            }
        }
    }
    __syncthreads();

    // ---- two transformer blocks ----
    for (int blk = 0; blk < 2; blk++) {
        const __half* wqkvh = wqkvh_all + blk * 12288;
        const __half* woh   = woh_all   + blk * 4096;
        const __half* w1h   = w1h_all   + blk * 16384;
        const float*  b1    = b1_all    + blk * 256;
        const __half* w2h   = w2h_all   + blk * 16384;
        const float*  b2    = b2_all    + blk * 64;
        const float*  ln1g  = ln1g_all  + blk * 64;
        const float*  ln1b  = ln1b_all  + blk * 64;
        const float*  ln2g  = ln2g_all  + blk * 64;
        const float*  ln2b  = ln2b_all  + blk * 64;

        // (1) build A; stage Wq->Wst, Wk->Vh(slot)
        build_Ah(Ah, xs, tid);
        for (int i = tid; i < 512; i += 256) {
            int r = i >> 3, j = i & 7;
            uint4 uq = ((const uint4*)wqkvh)[r * 24 + j];
            uint4 uk = ((const uint4*)wqkvh)[r * 24 + 8 + j];
            *(uint4*)(Wst + r * 72 + j * 8) = uq;
            *(uint4*)(Vh  + r * 72 + j * 8) = uk;
        }
        __syncthreads();

        // (2) Q-mma -> regs; K-mma -> Kh
        unsigned qa[2][4];
        {
            float q[4][4] = {};
            mma_block(Ah, 72, 0, Wst, 72, n0, m0, 4, q);
#pragma unroll
            for (int kt = 0; kt < 2; kt++) {
                qa[kt][0] = h2pack(q[2 * kt][0],     q[2 * kt][1]);
                qa[kt][1] = h2pack(q[2 * kt][2],     q[2 * kt][3]);
                qa[kt][2] = h2pack(q[2 * kt + 1][0], q[2 * kt + 1][1]);
                qa[kt][3] = h2pack(q[2 * kt + 1][2], q[2 * kt + 1][3]);
            }
        }
        {
            float acc[4][4] = {};
            mma_block(Ah, 72, 0, Vh, 72, n0, m0, 4, acc);
            epi_h16(Kh, acc, m0, n0, lane);   // rows 50-63 exact zeros
        }
        __syncthreads();

        // (3) stage Wv -> Wst
        for (int i = tid; i < 512; i += 256) {
            int r = i >> 3, j = i & 7;
            uint4 u = ((const uint4*)wqkvh)[r * 24 + 16 + j];
            *(uint4*)(Wst + r * 72 + j * 8) = u;
        }
        __syncthreads();
        // (4) V-mma -> Vh
        {
            float acc[4][4] = {};
            mma_block(Ah, 72, 0, Wst, 72, n0, m0, 4, acc);
            epi_h16(Vh, acc, m0, n0, lane);   // rows 50-63 exact zeros
        }
        __syncthreads();

        // (5) scores + softmax + ctx in REGISTERS; stage Wo -> Wst
        unsigned ka[2][4];
        {
            unsigned kb = (unsigned)__cvta_generic_to_shared(Kh);
            int nrow = (lane & 7) + ((lane >= 16) ? 8 : 0);
            int koff = ((lane & 15) >= 8) ? 8 : 0;
            float s[8][4];
#pragma unroll
            for (int i = 0; i < 8; i++) { s[i][0] = s[i][1] = s[i][2] = s[i][3] = 0.f; }
#pragma unroll
            for (int ns = 0; ns < 4; ns++) {
#pragma unroll
                for (int kt = 0; kt < 2; kt++) {
                    unsigned b0, b1, b2, b3;
                    ldsm_x4(b0, b1, b2, b3,
                        kb + (unsigned)(((ns * 16 + nrow) * 72 + h * 32 + kt * 16 + koff) * 2));
                    mma16816(s[ns * 2 + 0], qa[kt][0], qa[kt][1], qa[kt][2], qa[kt][3], b0, b1);
                    mma16816(s[ns * 2 + 1], qa[kt][0], qa[kt][1], qa[kt][2], qa[kt][3], b2, b3);
                }
            }
            const float scale = 0.17677669529663687f; // 1/sqrt(32)
            float mx0 = -INFINITY, mx1 = -INFINITY;
#pragma unroll
            for (int i = 0; i < 8; i++) {
                int colb = (i >> 1) * 16 + (i & 1) * 8 + (lane & 3) * 2;
#pragma unroll
                for (int j = 0; j < 4; j++) {
                    int col = colb + (j & 1);
                    float f = km[col];
                    float v = (f == 0.f) ? s[i][j] * scale : ((f == 1.f) ? -1e9f : -INFINITY);
                    s[i][j] = v;
                    if (j < 2) mx0 = fmaxf(mx0, v); else mx1 = fmaxf(mx1, v);
                }
            }
#pragma unroll
            for (int o = 1; o <= 2; o <<= 1) {
                mx0 = fmaxf(mx0, __shfl_xor_sync(0xffffffffu, mx0, o));
                mx1 = fmaxf(mx1, __shfl_xor_sync(0xffffffffu, mx1, o));
            }
            float sm0 = 0.f, sm1 = 0.f;
#pragma unroll
            for (int i = 0; i < 8; i++) {
                float e0 = expf(s[i][0] - mx0), e1 = expf(s[i][1] - mx0);
                float e2 = expf(s[i][2] - mx1), e3 = expf(s[i][3] - mx1);
                s[i][0] = e0; s[i][1] = e1; s[i][2] = e2; s[i][3] = e3;
                sm0 += e0 + e1; sm1 += e2 + e3;
            }
#pragma unroll
            for (int o = 1; o <= 2; o <<= 1) {
                sm0 += __shfl_xor_sync(0xffffffffu, sm0, o);
                sm1 += __shfl_xor_sync(0xffffffffu, sm1, o);
            }
            float inv0 = 1.0f / sm0, inv1 = 1.0f / sm1;
            unsigned pa[4][4];
#pragma unroll
            for (int kt = 0; kt < 4; kt++) {
                pa[kt][0] = h2pack(s[2 * kt][0] * inv0,     s[2 * kt][1] * inv0);
                pa[kt][1] = h2pack(s[2 * kt][2] * inv1,     s[2 * kt][3] * inv1);
                pa[kt][2] = h2pack(s[2 * kt + 1][0] * inv0, s[2 * kt + 1][1] * inv0);
                pa[kt][3] = h2pack(s[2 * kt + 1][2] * inv1, s[2 * kt + 1][3] * inv1);
            }
            // ctx = P @ V -> registers, then repack as A-frags (k = head dims)
            unsigned vb = (unsigned)__cvta_generic_to_shared(Vh);
            int brow = lane & 15;
            int bcol8 = (lane >> 4) * 8;
            float cacc[4][4] = {};
#pragma unroll
            for (int kt = 0; kt < 4; kt++) {
#pragma unroll
                for (int ns = 0; ns < 2; ns++) {
                    unsigned b0, b1, b2, b3;
                    ldsm_x4_t(b0, b1, b2, b3,
                        vb + (unsigned)(((kt * 16 + brow) * 72 + h * 32 + ns * 16 + bcol8) * 2));
                    mma16816(cacc[ns * 2 + 0], pa[kt][0], pa[kt][1], pa[kt][2], pa[kt][3], b0, b1);
                    mma16816(cacc[ns * 2 + 1], pa[kt][0], pa[kt][1], pa[kt][2], pa[kt][3], b2, b3);
                }
            }
#pragma unroll
            for (int kt = 0; kt < 2; kt++) {
                ka[kt][0] = h2pack(cacc[2 * kt][0],     cacc[2 * kt][1]);
                ka[kt][1] = h2pack(cacc[2 * kt][2],     cacc[2 * kt][3]);
                ka[kt][2] = h2pack(cacc[2 * kt + 1][0], cacc[2 * kt + 1][1]);
                ka[kt][3] = h2pack(cacc[2 * kt + 1][2], cacc[2 * kt + 1][3]);
            }
        }
        for (int i = tid; i < 512; i += 256) {
            uint4 u = ((const uint4*)woh)[i];
            int row = i >> 3, c = (i & 7) * 8;
            *(uint4*)(Wst + row * 72 + c) = u;
        }
        __syncthreads();

        // (6) O partial: each warp 16x64 over its k = h*32 slice; pair-reduce via y
        {
            unsigned wb = (unsigned)__cvta_generic_to_shared(Wst);
            int brow = lane & 15;
            int bcol8 = (lane >> 4) * 8;
            float oacc[8][4];
#pragma unroll
            for (int i = 0; i < 8; i++) { oacc[i][0] = oacc[i][1] = oacc[i][2] = oacc[i][3] = 0.f; }
#pragma unroll
            for (int kt = 0; kt < 2; kt++) {
#pragma unroll
                for (int ns = 0; ns < 4; ns++) {
                    unsigned b0, b1, b2, b3;
                    ldsm_x4_t(b0, b1, b2, b3,
                        wb + (unsigned)(((h * 32 + kt * 16 + brow) * 72 + ns * 16 + bcol8) * 2));
                    mma16816(oacc[ns * 2 + 0], ka[kt][0], ka[kt][1], ka[kt][2], ka[kt][3], b0, b1);
                    mma16816(oacc[ns * 2 + 1], ka[kt][0], ka[kt][1], ka[kt][2], ka[kt][3], b2, b3);
                }
            }
            int r = m0 + (lane >> 2);
            int cb = (lane & 3) * 2;
            if (h == 1) {
#pragma unroll
                for (int t = 0; t < 8; t++) {
                    int c = (t >> 1) * 16 + (t & 1) * 8 + cb;
                    if (r < 50)     *(float2*)(y + r * 66 + c)       = make_float2(oacc[t][0], oacc[t][1]);
                    if (r + 8 < 50) *(float2*)(y + (r + 8) * 66 + c) = make_float2(oacc[t][2], oacc[t][3]);
                }
            }
            __syncthreads();
            if (h == 0) {
#pragma unroll
                for (int t = 0; t < 8; t++) {
                    int c = (t >> 1) * 16 + (t & 1) * 8 + cb;
                    if (r < 50) {
                        y[r * 66 + c]     += oacc[t][0];
                        y[r * 66 + c + 1] += oacc[t][1];
                    }
                    if (r + 8 < 50) {
                        y[(r + 8) * 66 + c]     += oacc[t][2];
                        y[(r + 8) * 66 + c + 1] += oacc[t][3];
                    }
                }
            }
        }
        __syncthreads();
        ln_add(xs, y, ln1g, ln1b, tid);
        __syncthreads();

        // (7) FFN: 4 chunks, H1 stays in registers, FFN2 partial accumulation
        {
            float acc[8][4];
#pragma unroll
            for (int i = 0; i < 8; i++) { acc[i][0] = acc[i][1] = acc[i][2] = acc[i][3] = 0.f; }
            int cb = (lane & 3) * 2;
            int brow = lane & 15;
            int bcol8 = (lane >> 4) * 8;
            unsigned w2b = (unsigned)__cvta_generic_to_shared(W2c);
            for (int ch = 0; ch < 4; ch++) {
                if (ch == 0) build_Ah(Ah, xs, tid);
                for (int i = tid; i < 512; i += 256) {
                    int r = i >> 3, j = i & 7;
                    uint4 u1 = ((const uint4*)w1h)[r * 32 + ch * 8 + j];
                    uint4 u2 = ((const uint4*)w2h)[ch * 512 + i];
                    *(uint4*)(Wst + r * 72 + j * 8) = u1;
                    *(uint4*)(W2c + r * 72 + j * 8) = u2;
                }
                __syncthreads();
                float a1[4][4] = {};
                mma_block(Ah, 72, 0, Wst, 72, n0, m0, 4, a1);
                unsigned ha[2][4];
#pragma unroll
                for (int kt = 0; kt < 2; kt++) {
                    int c0 = ch * 64 + n0 + kt * 16 + cb;
                    float b0a = b1[c0],     b0b = b1[c0 + 1];
                    float b8a = b1[c0 + 8], b8b = b1[c0 + 9];
                    ha[kt][0] = h2pack(gelu_f(a1[2 * kt][0] + b0a),     gelu_f(a1[2 * kt][1] + b0b));
                    ha[kt][1] = h2pack(gelu_f(a1[2 * kt][2] + b0a),     gelu_f(a1[2 * kt][3] + b0b));
                    ha[kt][2] = h2pack(gelu_f(a1[2 * kt + 1][0] + b8a), gelu_f(a1[2 * kt + 1][1] + b8b));
                    ha[kt][3] = h2pack(gelu_f(a1[2 * kt + 1][2] + b8a), gelu_f(a1[2 * kt + 1][3] + b8b));
                }
                // FFN2 partial: A k-local = this warp's 32 H1 cols -> W2 rows n0+klocal
#pragma unroll
                for (int kt = 0; kt < 2; kt++) {
#pragma unroll
                    for (int ns = 0; ns < 4; ns++) {
                        unsigned b0, b1r, b2r, b3;
                        ldsm_x4_t(b0, b1r, b2r, b3,
                            w2b + (unsigned)(((n0 + kt * 16 + brow) * 72 + ns * 16 + bcol8) * 2));
                        mma16816(acc[ns * 2 + 0], ha[kt][0], ha[kt][1], ha[kt][2], ha[kt][3], b0, b1r);
                        mma16816(acc[ns * 2 + 1], ha[kt][0], ha[kt][1], ha[kt][2], ha[kt][3], b2r, b3);
                    }
                }
                __syncthreads();
            }
            // pair-reduce into y (w>=4 writes, w<4 adds + b2)
            int r = m0 + (lane >> 2);
            if (w >= 4) {
#pragma unroll
                for (int t = 0; t < 8; t++) {
                    int c = (t >> 1) * 16 + (t & 1) * 8 + cb;
                    if (r < 50)     *(float2*)(y + r * 66 + c)       = make_float2(acc[t][0], acc[t][1]);
                    if (r + 8 < 50) *(float2*)(y + (r + 8) * 66 + c) = make_float2(acc[t][2], acc[t][3]);
                }
            }
            __syncthreads();
            if (w < 4) {
#pragma unroll
                for (int t = 0; t < 8; t++) {
                    int c = (t >> 1) * 16 + (t & 1) * 8 + cb;
                    if (r < 50) {
                        y[r * 66 + c]     += acc[t][0] + b2[c];
                        y[r * 66 + c + 1] += acc[t][1] + b2[c + 1];
                    }
                    if (r + 8 < 50) {
                        y[(r + 8) * 66 + c]     += acc[t][2] + b2[c];
                        y[(r + 8) * 66 + c + 1] += acc[t][3] + b2[c + 1];
                    }
                }
            }
        }
        __syncthreads();
        ln_add(xs, y, ln2g, ln2b, tid);
        __syncthreads();
    }

    // ---- epilogue: final LN on row lens[b]-1 ----
    if (w == 0) {
        int r = lens[b] - 1;
        float v0 = xs[r * 64 + lane], v1 = xs[r * 64 + 32 + lane];
        float mean = wsum(v0 + v1) * (1.0f / 64.0f);
        float d0 = v0 - mean, d1 = v1 - mean;
        float var = wsum(d0 * d0 + d1 * d1) * (1.0f / 64.0f);
        float inv = 1.0f / sqrtf(var + 1e-5f);
        out[b * D + lane]      = d0 * inv * lnfg[lane]      + lnfb[lane];
        out[b * D + 32 + lane] = d1 * inv * lnfg[lane + 32] + lnfb[lane + 32];
    }
}

// ---------------- launch -------------------------------------------
extern "C" void kernel_launch(void* const* d_in, const int* in_sizes, int n_in,
                              void* d_out, int out_size)
{
    const int*   seq  = (const int*)d_in[0];
    const int*   lens = (const int*)d_in[1];
    const int*   ei   = (const int*)d_in[2];
    const float* ew   = (const float*)d_in[3];
    const float* bert = (const float*)d_in[4];
    const float* gnn  = (const float*)d_in[5];
    const float* Wp   = (const float*)d_in[6];
    const float* bp   = (const float*)d_in[7];
    const float* pos  = (const float*)d_in[8];
    const float* wq   = (const float*)d_in[9];
    const float* wk   = (const float*)d_in[10];
    const float* wv   = (const float*)d_in[11];
    const float* wo   = (const float*)d_in[12];
    const float* w1   = (const float*)d_in[13];
    const float* b1   = (const float*)d_in[14];
    const float* w2   = (const float*)d_in[15];
    const float* b2   = (const float*)d_in[16];
    const float* ln1g = (const float*)d_in[17];
    const float* ln1b = (const float*)d_in[18];
    const float* ln2g = (const float*)d_in[19];
    const float* ln2b = (const float*)d_in[20];
    const float* lnfg = (const float*)d_in[21];
    const float* lnfb = (const float*)d_in[22];
    float* out = (float*)d_out;
    int E = in_sizes[3];

    cudaFuncSetAttribute(xformer_kernel,
                         cudaFuncAttributeMaxDynamicSharedMemorySize, SMEM_BYTES);

    __half2 *gnnh, *x1h, *x2h;
    __half *wph, *wqkvh, *woh, *w1hp, *w2hp;
    cudaGetSymbolAddress((void**)&gnnh, g_gnnh);
    cudaGetSymbolAddress((void**)&x1h, g_x1h);
    cudaGetSymbolAddress((void**)&x2h, g_x2h);
    cudaGetSymbolAddress((void**)&wph, g_wph);
    cudaGetSymbolAddress((void**)&wqkvh, g_wqkvh);
    cudaGetSymbolAddress((void**)&woh, g_woh);
    cudaGetSymbolAddress((void**)&w1hp, g_w1h);
    cudaGetSymbolAddress((void**)&w2hp, g_w2h);

    prep_kernel<<<1024, 256>>>(gnn, Wp, wq, wk, wv, wo, w1, w2);

    hist_kernel<<<(E + 255) / 256, 256>>>(ei, E);
    scan1_kernel<<<(NN + 1023) / 1024, 256>>>();
    scan3_kernel<<<(NN + 255) / 256, 256>>>();
    reorder_kernel<<<(E + 255) / 256, 256>>>(ei, ew, E);

    agg_kernel<<<(NN + 7) / 8, 256>>>(gnnh, x1h);
    agg_kernel<<<(NN + 7) / 8, 256>>>(x1h, x2h);

    xformer_kernel<<<SB, 256, SMEM_BYTES>>>(seq, lens, bert, pos, bp,
        wph, wqkvh, woh, w1hp, b1, w2hp, b2,
        ln1g, ln1b, ln2g, ln2b, lnfg, lnfb, out);
}